// round 1
// baseline (speedup 1.0000x reference)
#include <cuda_runtime.h>

#define NSEQ   1605
#define DIMF   1024
#define NH     16
#define DH     64
#define HWLEN  1600
#define PREFIX 5
#define NPAD   1664   // 26 * 64

// ---- scratch (device globals; zero-initialized at module load) ----
__device__ float g_q[(size_t)NH * NPAD * DH];
__device__ float g_k[(size_t)NH * NPAD * DH];
__device__ float g_v[(size_t)NH * NPAD * DH];
__device__ float g_attn[(size_t)NSEQ * DIMF];

// ============================================================
// GEMM 1:  qkv = x @ W_qkv^T   (M=1605, N=3072, K=1024, NT)
// Epilogue scatters into g_q/g_k/g_v with layout [h][n][d],
// folding the 1/sqrt(64) scale into q.
// ============================================================
__global__ __launch_bounds__(256) void gemm_qkv_kernel(
    const float* __restrict__ A,   // x [1605,1024]
    const float* __restrict__ B)   // W_qkv [3072,1024]
{
    __shared__ __align__(16) float As[16][68];
    __shared__ __align__(16) float Bs[16][68];

    const int bm = blockIdx.y * 64;
    const int bn = blockIdx.x * 64;
    const int tid = threadIdx.x;
    const int ty = tid >> 4, tx = tid & 15;
    const int lr = tid >> 2, lk = (tid & 3) << 2;

    float acc[4][4];
#pragma unroll
    for (int i = 0; i < 4; i++)
#pragma unroll
        for (int j = 0; j < 4; j++) acc[i][j] = 0.0f;

    for (int k0 = 0; k0 < 1024; k0 += 16) {
        float4 av = make_float4(0.f, 0.f, 0.f, 0.f);
        if (bm + lr < NSEQ)
            av = *(const float4*)(A + (size_t)(bm + lr) * 1024 + k0 + lk);
        As[lk + 0][lr] = av.x; As[lk + 1][lr] = av.y;
        As[lk + 2][lr] = av.z; As[lk + 3][lr] = av.w;

        float4 bv = *(const float4*)(B + (size_t)(bn + lr) * 1024 + k0 + lk);
        Bs[lk + 0][lr] = bv.x; Bs[lk + 1][lr] = bv.y;
        Bs[lk + 2][lr] = bv.z; Bs[lk + 3][lr] = bv.w;

        __syncthreads();
#pragma unroll
        for (int k = 0; k < 16; ++k) {
            float4 a4 = *(const float4*)&As[k][ty * 4];
            float4 b4 = *(const float4*)&Bs[k][tx * 4];
            float a[4] = {a4.x, a4.y, a4.z, a4.w};
            float b[4] = {b4.x, b4.y, b4.z, b4.w};
#pragma unroll
            for (int i = 0; i < 4; i++)
#pragma unroll
                for (int j = 0; j < 4; j++) acc[i][j] += a[i] * b[j];
        }
        __syncthreads();
    }

    // scatter epilogue. Whole 64-col tile lies inside one (s,h) pair.
    const int j0 = bn;                // 64-aligned
    const int s  = j0 >> 10;
    const int h  = (j0 & 1023) >> 6;
#pragma unroll
    for (int i = 0; i < 4; i++) {
        const int n = bm + ty * 4 + i;
        if (n >= NSEQ) continue;
#pragma unroll
        for (int j = 0; j < 4; j++) {
            const int d = tx * 4 + j;  // 0..63 within the head
            const size_t off = ((size_t)h * NPAD + n) * DH + d;
            float v = acc[i][j];
            if (s == 0)      g_q[off] = v * 0.125f;
            else if (s == 1) g_k[off] = v;
            else             g_v[off] = v;
        }
    }
}

// ============================================================
// RoPE on q and k, rows PREFIX..NSEQ-1.
// One thread per (p, h, d<32) pair, updates both halves of q and k.
// ============================================================
__global__ void rope_kernel(const float* __restrict__ rope)
{
    int idx = blockIdx.x * blockDim.x + threadIdx.x;
    if (idx >= HWLEN * NH * 32) return;
    const int d = idx & 31;
    const int h = (idx >> 5) & 15;
    const int p = idx >> 9;
    const int n = PREFIX + p;

    const float s0 = rope[p * 64 + d];
    const float s1 = rope[p * 64 + d + 32];
    const float c0 = rope[HWLEN * 64 + p * 64 + d];
    const float c1 = rope[HWLEN * 64 + p * 64 + d + 32];

    const size_t base = ((size_t)h * NPAD + n) * DH;

    float q0 = g_q[base + d], q1 = g_q[base + d + 32];
    g_q[base + d]      = q0 * c0 - q1 * s0;
    g_q[base + d + 32] = q1 * c1 + q0 * s1;

    float k0 = g_k[base + d], k1 = g_k[base + d + 32];
    g_k[base + d]      = k0 * c0 - k1 * s0;
    g_k[base + d + 32] = k1 * c1 + k0 * s1;
}

// ============================================================
// Flash-style attention. grid = (26 q-blocks, 16 heads), 256 thr.
// Q-tile 64x64 in smem, K/V-tiles 32x64, online softmax fp32.
// q is pre-scaled by 1/8.
// ============================================================
__global__ __launch_bounds__(256) void attn_kernel()
{
    __shared__ __align__(16) float Qs[64][64];
    __shared__ float Ks[32][65];
    __shared__ float Vs[32][65];
    __shared__ float Ps[64][33];
    __shared__ float m_s[64], l_s[64], alpha_s[64];

    const int h  = blockIdx.y;
    const int qb = blockIdx.x * 64;
    const int tid = threadIdx.x;

    const float* __restrict__ Qg = g_q + (size_t)h * NPAD * DH;
    const float* __restrict__ Kg = g_k + (size_t)h * NPAD * DH;
    const float* __restrict__ Vg = g_v + (size_t)h * NPAD * DH;

    // load Q tile (rows beyond NSEQ are zero in the padded array)
    for (int i = tid; i < 64 * 16; i += 256) {
        const int r = i >> 4, c4 = (i & 15) * 4;
        *(float4*)&Qs[r][c4] = *(const float4*)(Qg + (size_t)(qb + r) * DH + c4);
    }
    if (tid < 64) { m_s[tid] = -1e38f; l_s[tid] = 0.0f; }

    float o[4][4];
#pragma unroll
    for (int i = 0; i < 4; i++)
#pragma unroll
        for (int j = 0; j < 4; j++) o[i][j] = 0.0f;

    const int srow = (tid >> 4) * 4;   // S phase: 4 rows
    const int scol = (tid & 15) * 2;   // S phase: 2 cols
    const int trow = tid >> 2;         // softmax: 1 row / 4 lanes
    const int part = tid & 3;
    const int orow = (tid >> 4) * 4;   // O phase: 4 rows
    const int ocol = (tid & 15) * 4;   // O phase: 4 cols

    __syncthreads();

    const int nkt = (NSEQ + 31) / 32;  // 51
    for (int kt = 0; kt < nkt; ++kt) {
        const int key0 = kt * 32;

        // load K,V tiles (32x64 each)
        for (int i = tid; i < 32 * 16; i += 256) {
            const int r = i >> 4, c4 = (i & 15) * 4;
            float4 kv = *(const float4*)(Kg + (size_t)(key0 + r) * DH + c4);
            Ks[r][c4 + 0] = kv.x; Ks[r][c4 + 1] = kv.y;
            Ks[r][c4 + 2] = kv.z; Ks[r][c4 + 3] = kv.w;
            float4 vv = *(const float4*)(Vg + (size_t)(key0 + r) * DH + c4);
            Vs[r][c4 + 0] = vv.x; Vs[r][c4 + 1] = vv.y;
            Vs[r][c4 + 2] = vv.z; Vs[r][c4 + 3] = vv.w;
        }
        __syncthreads();

        // S = Q K^T  (each thread 4x2)
        float sacc[4][2];
#pragma unroll
        for (int i = 0; i < 4; i++) { sacc[i][0] = 0.f; sacc[i][1] = 0.f; }
#pragma unroll 8
        for (int d = 0; d < 64; ++d) {
            float k0v = Ks[scol + 0][d];
            float k1v = Ks[scol + 1][d];
#pragma unroll
            for (int i = 0; i < 4; i++) {
                float qv = Qs[srow + i][d];
                sacc[i][0] += qv * k0v;
                sacc[i][1] += qv * k1v;
            }
        }
#pragma unroll
        for (int i = 0; i < 4; i++)
#pragma unroll
            for (int c = 0; c < 2; c++) {
                float v = sacc[i][c];
                if (key0 + scol + c >= NSEQ) v = -1e30f;
                Ps[srow + i][scol + c] = v;
            }
        __syncthreads();

        // online softmax: 4 lanes per row, 8 cols each
        {
            float mp = -1e38f;
#pragma unroll
            for (int c = 0; c < 8; c++)
                mp = fmaxf(mp, Ps[trow][part * 8 + c]);
            mp = fmaxf(mp, __shfl_xor_sync(0xffffffffu, mp, 1));
            mp = fmaxf(mp, __shfl_xor_sync(0xffffffffu, mp, 2));
            const float mold = m_s[trow];
            const float mnew = fmaxf(mold, mp);
            const float a = __expf(mold - mnew);
            float lsum = 0.0f;
#pragma unroll
            for (int c = 0; c < 8; c++) {
                float p = __expf(Ps[trow][part * 8 + c] - mnew);
                Ps[trow][part * 8 + c] = p;
                lsum += p;
            }
            lsum += __shfl_xor_sync(0xffffffffu, lsum, 1);
            lsum += __shfl_xor_sync(0xffffffffu, lsum, 2);
            if (part == 0) {
                m_s[trow] = mnew;
                l_s[trow] = l_s[trow] * a + lsum;
                alpha_s[trow] = a;
            }
        }
        __syncthreads();

        // O = O*alpha + P V   (each thread 4x4)
#pragma unroll
        for (int i = 0; i < 4; i++) {
            const float a = alpha_s[orow + i];
#pragma unroll
            for (int j = 0; j < 4; j++) o[i][j] *= a;
        }
#pragma unroll 8
        for (int k = 0; k < 32; ++k) {
            float vv[4];
#pragma unroll
            for (int j = 0; j < 4; j++) vv[j] = Vs[k][ocol + j];
#pragma unroll
            for (int i = 0; i < 4; i++) {
                const float p = Ps[orow + i][k];
#pragma unroll
                for (int j = 0; j < 4; j++) o[i][j] += p * vv[j];
            }
        }
        __syncthreads();
    }

    // normalize + store
#pragma unroll
    for (int i = 0; i < 4; i++) {
        const int n = qb + orow + i;
        if (n >= NSEQ) continue;
        const float inv = 1.0f / l_s[orow + i];
#pragma unroll
        for (int j = 0; j < 4; j++)
            g_attn[(size_t)n * DIMF + h * DH + ocol + j] = o[i][j] * inv;
    }
}

// ============================================================
// GEMM 2:  out = attn_out @ W_proj^T + b  (M=1605, N=1024, K=1024)
// ============================================================
__global__ __launch_bounds__(256) void gemm_proj_kernel(
    const float* __restrict__ B,     // W_proj [1024,1024]
    const float* __restrict__ bias,  // [1024]
    float* __restrict__ C)           // out [1605,1024]
{
    __shared__ __align__(16) float As[16][68];
    __shared__ __align__(16) float Bs[16][68];

    const int bm = blockIdx.y * 64;
    const int bn = blockIdx.x * 64;
    const int tid = threadIdx.x;
    const int ty = tid >> 4, tx = tid & 15;
    const int lr = tid >> 2, lk = (tid & 3) << 2;
    const float* __restrict__ A = g_attn;

    float acc[4][4];
#pragma unroll
    for (int i = 0; i < 4; i++)
#pragma unroll
        for (int j = 0; j < 4; j++) acc[i][j] = 0.0f;

    for (int k0 = 0; k0 < 1024; k0 += 16) {
        float4 av = make_float4(0.f, 0.f, 0.f, 0.f);
        if (bm + lr < NSEQ)
            av = *(const float4*)(A + (size_t)(bm + lr) * 1024 + k0 + lk);
        As[lk + 0][lr] = av.x; As[lk + 1][lr] = av.y;
        As[lk + 2][lr] = av.z; As[lk + 3][lr] = av.w;

        float4 bv = *(const float4*)(B + (size_t)(bn + lr) * 1024 + k0 + lk);
        Bs[lk + 0][lr] = bv.x; Bs[lk + 1][lr] = bv.y;
        Bs[lk + 2][lr] = bv.z; Bs[lk + 3][lr] = bv.w;

        __syncthreads();
#pragma unroll
        for (int k = 0; k < 16; ++k) {
            float4 a4 = *(const float4*)&As[k][ty * 4];
            float4 b4 = *(const float4*)&Bs[k][tx * 4];
            float a[4] = {a4.x, a4.y, a4.z, a4.w};
            float b[4] = {b4.x, b4.y, b4.z, b4.w};
#pragma unroll
            for (int i = 0; i < 4; i++)
#pragma unroll
                for (int j = 0; j < 4; j++) acc[i][j] += a[i] * b[j];
        }
        __syncthreads();
    }

#pragma unroll
    for (int i = 0; i < 4; i++) {
        const int n = bm + ty * 4 + i;
        if (n >= NSEQ) continue;
#pragma unroll
        for (int j = 0; j < 4; j++) {
            const int col = bn + tx * 4 + j;
            C[(size_t)n * 1024 + col] = acc[i][j] + bias[col];
        }
    }
}

// ============================================================
extern "C" void kernel_launch(void* const* d_in, const int* in_sizes, int n_in,
                              void* d_out, int out_size)
{
    (void)in_sizes; (void)n_in; (void)out_size;
    const float* x     = (const float*)d_in[0];
    const float* rope  = (const float*)d_in[1];
    const float* Wqkv  = (const float*)d_in[2];
    const float* Wproj = (const float*)d_in[3];
    const float* bproj = (const float*)d_in[4];
    float* out = (float*)d_out;

    gemm_qkv_kernel<<<dim3(48, 26), 256>>>(x, Wqkv);
    rope_kernel<<<(HWLEN * NH * 32 + 255) / 256, 256>>>(rope);
    attn_kernel<<<dim3(26, NH), 256>>>();
    gemm_proj_kernel<<<dim3(16, 26), 256>>>(Wproj, bproj, out);
}

// round 3
// speedup vs baseline: 1.0972x; 1.0972x over previous
#include <cuda_runtime.h>
#include <cstdint>

#define NSEQ   1605
#define DIMF   1024
#define NH     16
#define DH     64
#define HWLEN  1600
#define PREFIX 5
#define NPAD   1664   // 26 * 64

// ---- scratch (device globals; zero-initialized at module load) ----
__device__ float g_q[(size_t)NH * NPAD * DH];
__device__ float g_k[(size_t)NH * NPAD * DH];
__device__ float g_v[(size_t)NH * NPAD * DH];
__device__ float g_attn[(size_t)NSEQ * DIMF];

// ============================================================
// mma.sync tf32 helpers (portable sm_80+ path; tcgen05 is not
// assemblable at the harness's compute_103 family target)
// ============================================================
__device__ __forceinline__ uint32_t f2tf32(float a) {
    uint32_t u; asm("cvt.rna.tf32.f32 %0, %1;" : "=r"(u) : "f"(a));
    return u;
}

#define MMA_TF32(d, a0, a1, a2, a3, b0, b1) \
    asm volatile("mma.sync.aligned.m16n8k8.row.col.f32.tf32.tf32.f32 " \
        "{%0,%1,%2,%3}, {%4,%5,%6,%7}, {%8,%9}, {%0,%1,%2,%3};" \
        : "+f"((d)[0]), "+f"((d)[1]), "+f"((d)[2]), "+f"((d)[3]) \
        : "r"(a0), "r"(a1), "r"(a2), "r"(a3), "r"(b0), "r"(b1))

// smem tile geometry: [128 rows][16 k] stored with row stride 20 floats
// (banks: (r*20+c)&31 conflict-free for the fragment access pattern;
//  r*20 floats = r*80 bytes keeps float4 alignment for stores)
#define TSTRIDE 20
#define TILE_FLOATS (128 * TSTRIDE)   // 2560

// ============================================================
// 3xTF32 mma.sync mainloop:
//   acc[4][4][4] += A[bm:bm+128, 0:1024] @ B[bn:bn+128, 0:1024]^T
// A rows >= aRows read as zero. smem: 4 tiles (A hi/lo, B hi/lo).
// ============================================================
__device__ __forceinline__ void gemm3x_mma(
    const float* __restrict__ A, const float* __restrict__ B,
    int bm, int bn, int aRows, float* smem, float acc[4][4][4])
{
    float* As_h = smem;
    float* As_l = smem + TILE_FLOATS;
    float* Bs_h = smem + 2 * TILE_FLOATS;
    float* Bs_l = smem + 3 * TILE_FLOATS;

    const int tid = threadIdx.x;
    const int wid = tid >> 5, lane = tid & 31;
    const int warp_m = wid & 1;          // 2 -> 64 rows each
    const int warp_n = wid >> 1;         // 4 -> 32 cols each
    const int grp = lane >> 2, tig = lane & 3;

    // prefetch registers: per thread 2 float4 of A, 2 of B
    float4 pa[2], pb[2];

    const int r0 = tid >> 2;             // +64 per t
    const int f0 = (tid & 3) * 4;

#define LOAD_TILE(k0) do { \
    _Pragma("unroll") \
    for (int t = 0; t < 2; ++t) { \
        const int r = r0 + t * 64; \
        pa[t] = make_float4(0.f, 0.f, 0.f, 0.f); \
        if (bm + r < aRows) \
            pa[t] = *(const float4*)(A + (size_t)(bm + r) * 1024 + (k0) + f0); \
        pb[t] = *(const float4*)(B + (size_t)(bn + r) * 1024 + (k0) + f0); \
    } } while (0)

#define STORE_TILE() do { \
    _Pragma("unroll") \
    for (int t = 0; t < 2; ++t) { \
        const int r = r0 + t * 64; \
        float4 hi, lo; \
        hi.x = __uint_as_float(f2tf32(pa[t].x)); lo.x = __uint_as_float(f2tf32(pa[t].x - hi.x)); \
        hi.y = __uint_as_float(f2tf32(pa[t].y)); lo.y = __uint_as_float(f2tf32(pa[t].y - hi.y)); \
        hi.z = __uint_as_float(f2tf32(pa[t].z)); lo.z = __uint_as_float(f2tf32(pa[t].z - hi.z)); \
        hi.w = __uint_as_float(f2tf32(pa[t].w)); lo.w = __uint_as_float(f2tf32(pa[t].w - hi.w)); \
        *(float4*)(As_h + r * TSTRIDE + f0) = hi; \
        *(float4*)(As_l + r * TSTRIDE + f0) = lo; \
        hi.x = __uint_as_float(f2tf32(pb[t].x)); lo.x = __uint_as_float(f2tf32(pb[t].x - hi.x)); \
        hi.y = __uint_as_float(f2tf32(pb[t].y)); lo.y = __uint_as_float(f2tf32(pb[t].y - hi.y)); \
        hi.z = __uint_as_float(f2tf32(pb[t].z)); lo.z = __uint_as_float(f2tf32(pb[t].z - hi.z)); \
        hi.w = __uint_as_float(f2tf32(pb[t].w)); lo.w = __uint_as_float(f2tf32(pb[t].w - hi.w)); \
        *(float4*)(Bs_h + r * TSTRIDE + f0) = hi; \
        *(float4*)(Bs_l + r * TSTRIDE + f0) = lo; \
    } } while (0)

    LOAD_TILE(0);
    STORE_TILE();
    __syncthreads();

    for (int c = 0; c < 64; ++c) {
        if (c < 63) LOAD_TILE((c + 1) * 16);

#pragma unroll
        for (int ks = 0; ks < 2; ++ks) {
            const int kc = ks * 8 + tig;
            uint32_t ah[4][4], al[4][4], bh[4][2], bl[4][2];
#pragma unroll
            for (int mt = 0; mt < 4; ++mt) {
                const int ra = (warp_m * 64 + mt * 16 + grp) * TSTRIDE;
                ah[mt][0] = __float_as_uint(As_h[ra + kc]);
                ah[mt][1] = __float_as_uint(As_h[ra + 8 * TSTRIDE + kc]);
                ah[mt][2] = __float_as_uint(As_h[ra + kc + 4]);
                ah[mt][3] = __float_as_uint(As_h[ra + 8 * TSTRIDE + kc + 4]);
                al[mt][0] = __float_as_uint(As_l[ra + kc]);
                al[mt][1] = __float_as_uint(As_l[ra + 8 * TSTRIDE + kc]);
                al[mt][2] = __float_as_uint(As_l[ra + kc + 4]);
                al[mt][3] = __float_as_uint(As_l[ra + 8 * TSTRIDE + kc + 4]);
            }
#pragma unroll
            for (int nt = 0; nt < 4; ++nt) {
                const int rb = (warp_n * 32 + nt * 8 + grp) * TSTRIDE + ks * 8 + tig;
                bh[nt][0] = __float_as_uint(Bs_h[rb]);
                bh[nt][1] = __float_as_uint(Bs_h[rb + 4]);
                bl[nt][0] = __float_as_uint(Bs_l[rb]);
                bl[nt][1] = __float_as_uint(Bs_l[rb + 4]);
            }
#pragma unroll
            for (int mt = 0; mt < 4; ++mt)
#pragma unroll
                for (int nt = 0; nt < 4; ++nt) {
                    MMA_TF32(acc[mt][nt], ah[mt][0], ah[mt][1], ah[mt][2], ah[mt][3],
                             bh[nt][0], bh[nt][1]);
                    MMA_TF32(acc[mt][nt], ah[mt][0], ah[mt][1], ah[mt][2], ah[mt][3],
                             bl[nt][0], bl[nt][1]);
                    MMA_TF32(acc[mt][nt], al[mt][0], al[mt][1], al[mt][2], al[mt][3],
                             bh[nt][0], bh[nt][1]);
                }
        }
        __syncthreads();
        if (c < 63) {
            STORE_TILE();
            __syncthreads();
        }
    }
#undef LOAD_TILE
#undef STORE_TILE
}

// ============================================================
// qkv GEMM: x @ W_qkv^T, scatter into g_q/g_k/g_v [h][n][d], q scaled 1/8
// grid (24, 13): bn = bx*128, bm = by*128
// ============================================================
__global__ __launch_bounds__(256) void gemm_qkv_tc(
    const float* __restrict__ A, const float* __restrict__ B)
{
    __shared__ __align__(16) float smem[4 * TILE_FLOATS];
    const int bm = blockIdx.y * 128;
    const int bn = blockIdx.x * 128;

    float acc[4][4][4];
#pragma unroll
    for (int a = 0; a < 4; a++)
#pragma unroll
        for (int b = 0; b < 4; b++)
#pragma unroll
            for (int cc = 0; cc < 4; cc++) acc[a][b][cc] = 0.0f;

    gemm3x_mma(A, B, bm, bn, NSEQ, smem, acc);

    const int tid = threadIdx.x;
    const int wid = tid >> 5, lane = tid & 31;
    const int warp_m = wid & 1, warp_n = wid >> 1;
    const int grp = lane >> 2, tig = lane & 3;

    const int s = bn >> 10;                   // 0=q,1=k,2=v
    float* __restrict__ dst = (s == 0) ? g_q : (s == 1) ? g_k : g_v;
    const float scale = (s == 0) ? 0.125f : 1.0f;

#pragma unroll
    for (int mt = 0; mt < 4; ++mt)
#pragma unroll
        for (int half = 0; half < 2; ++half) {
            const int row = bm + warp_m * 64 + mt * 16 + grp + half * 8;
            if (row >= NSEQ) continue;
#pragma unroll
            for (int nt = 0; nt < 4; ++nt) {
                const int col = bn + warp_n * 32 + nt * 8 + tig * 2;
                const int h = (col & 1023) >> 6;
                const int d = col & 63;
                float2 v;
                v.x = acc[mt][nt][half * 2 + 0] * scale;
                v.y = acc[mt][nt][half * 2 + 1] * scale;
                *(float2*)&dst[((size_t)h * NPAD + row) * DH + d] = v;
            }
        }
}

// ============================================================
// proj GEMM: g_attn @ W_proj^T + bias -> out.  grid (8, 13)
// ============================================================
__global__ __launch_bounds__(256) void gemm_proj_tc(
    const float* __restrict__ B, const float* __restrict__ bias,
    float* __restrict__ C)
{
    __shared__ __align__(16) float smem[4 * TILE_FLOATS];
    const int bm = blockIdx.y * 128;
    const int bn = blockIdx.x * 128;

    float acc[4][4][4];
#pragma unroll
    for (int a = 0; a < 4; a++)
#pragma unroll
        for (int b = 0; b < 4; b++)
#pragma unroll
            for (int cc = 0; cc < 4; cc++) acc[a][b][cc] = 0.0f;

    gemm3x_mma(g_attn, B, bm, bn, NSEQ, smem, acc);

    const int tid = threadIdx.x;
    const int wid = tid >> 5, lane = tid & 31;
    const int warp_m = wid & 1, warp_n = wid >> 1;
    const int grp = lane >> 2, tig = lane & 3;

#pragma unroll
    for (int mt = 0; mt < 4; ++mt)
#pragma unroll
        for (int half = 0; half < 2; ++half) {
            const int row = bm + warp_m * 64 + mt * 16 + grp + half * 8;
            if (row >= NSEQ) continue;
#pragma unroll
            for (int nt = 0; nt < 4; ++nt) {
                const int col = bn + warp_n * 32 + nt * 8 + tig * 2;
                float2 v;
                v.x = acc[mt][nt][half * 2 + 0] + bias[col];
                v.y = acc[mt][nt][half * 2 + 1] + bias[col + 1];
                *(float2*)&C[(size_t)row * 1024 + col] = v;
            }
        }
}

// ============================================================
// RoPE on q and k, rows PREFIX..NSEQ-1
// ============================================================
__global__ void rope_kernel(const float* __restrict__ rope)
{
    int idx = blockIdx.x * blockDim.x + threadIdx.x;
    if (idx >= HWLEN * NH * 32) return;
    const int d = idx & 31;
    const int h = (idx >> 5) & 15;
    const int p = idx >> 9;
    const int n = PREFIX + p;

    const float s0 = rope[p * 64 + d];
    const float s1 = rope[p * 64 + d + 32];
    const float c0 = rope[HWLEN * 64 + p * 64 + d];
    const float c1 = rope[HWLEN * 64 + p * 64 + d + 32];

    const size_t base = ((size_t)h * NPAD + n) * DH;

    float q0 = g_q[base + d], q1 = g_q[base + d + 32];
    g_q[base + d]      = q0 * c0 - q1 * s0;
    g_q[base + d + 32] = q1 * c1 + q0 * s1;

    float k0 = g_k[base + d], k1 = g_k[base + d + 32];
    g_k[base + d]      = k0 * c0 - k1 * s0;
    g_k[base + d + 32] = k1 * c1 + k0 * s1;
}

// ============================================================
// Flash-style attention (round-1 SIMT version)
// ============================================================
__global__ __launch_bounds__(256) void attn_kernel()
{
    __shared__ __align__(16) float Qs[64][64];
    __shared__ float Ks[32][65];
    __shared__ float Vs[32][65];
    __shared__ float Ps[64][33];
    __shared__ float m_s[64], l_s[64], alpha_s[64];

    const int h  = blockIdx.y;
    const int qb = blockIdx.x * 64;
    const int tid = threadIdx.x;

    const float* __restrict__ Qg = g_q + (size_t)h * NPAD * DH;
    const float* __restrict__ Kg = g_k + (size_t)h * NPAD * DH;
    const float* __restrict__ Vg = g_v + (size_t)h * NPAD * DH;

    for (int i = tid; i < 64 * 16; i += 256) {
        const int r = i >> 4, c4 = (i & 15) * 4;
        *(float4*)&Qs[r][c4] = *(const float4*)(Qg + (size_t)(qb + r) * DH + c4);
    }
    if (tid < 64) { m_s[tid] = -1e38f; l_s[tid] = 0.0f; }

    float o[4][4];
#pragma unroll
    for (int i = 0; i < 4; i++)
#pragma unroll
        for (int j = 0; j < 4; j++) o[i][j] = 0.0f;

    const int srow = (tid >> 4) * 4;
    const int scol = (tid & 15) * 2;
    const int trow = tid >> 2;
    const int part = tid & 3;
    const int orow = (tid >> 4) * 4;
    const int ocol = (tid & 15) * 4;

    __syncthreads();

    const int nkt = (NSEQ + 31) / 32;
    for (int kt = 0; kt < nkt; ++kt) {
        const int key0 = kt * 32;

        for (int i = tid; i < 32 * 16; i += 256) {
            const int r = i >> 4, c4 = (i & 15) * 4;
            float4 kv = *(const float4*)(Kg + (size_t)(key0 + r) * DH + c4);
            Ks[r][c4 + 0] = kv.x; Ks[r][c4 + 1] = kv.y;
            Ks[r][c4 + 2] = kv.z; Ks[r][c4 + 3] = kv.w;
            float4 vv = *(const float4*)(Vg + (size_t)(key0 + r) * DH + c4);
            Vs[r][c4 + 0] = vv.x; Vs[r][c4 + 1] = vv.y;
            Vs[r][c4 + 2] = vv.z; Vs[r][c4 + 3] = vv.w;
        }
        __syncthreads();

        float sacc[4][2];
#pragma unroll
        for (int i = 0; i < 4; i++) { sacc[i][0] = 0.f; sacc[i][1] = 0.f; }
#pragma unroll 8
        for (int d = 0; d < 64; ++d) {
            float k0v = Ks[scol + 0][d];
            float k1v = Ks[scol + 1][d];
#pragma unroll
            for (int i = 0; i < 4; i++) {
                float qv = Qs[srow + i][d];
                sacc[i][0] += qv * k0v;
                sacc[i][1] += qv * k1v;
            }
        }
#pragma unroll
        for (int i = 0; i < 4; i++)
#pragma unroll
            for (int c = 0; c < 2; c++) {
                float v = sacc[i][c];
                if (key0 + scol + c >= NSEQ) v = -1e30f;
                Ps[srow + i][scol + c] = v;
            }
        __syncthreads();

        {
            float mp = -1e38f;
#pragma unroll
            for (int c = 0; c < 8; c++)
                mp = fmaxf(mp, Ps[trow][part * 8 + c]);
            mp = fmaxf(mp, __shfl_xor_sync(0xffffffffu, mp, 1));
            mp = fmaxf(mp, __shfl_xor_sync(0xffffffffu, mp, 2));
            const float mold = m_s[trow];
            const float mnew = fmaxf(mold, mp);
            const float a = __expf(mold - mnew);
            float lsum = 0.0f;
#pragma unroll
            for (int c = 0; c < 8; c++) {
                float p = __expf(Ps[trow][part * 8 + c] - mnew);
                Ps[trow][part * 8 + c] = p;
                lsum += p;
            }
            lsum += __shfl_xor_sync(0xffffffffu, lsum, 1);
            lsum += __shfl_xor_sync(0xffffffffu, lsum, 2);
            if (part == 0) {
                m_s[trow] = mnew;
                l_s[trow] = l_s[trow] * a + lsum;
                alpha_s[trow] = a;
            }
        }
        __syncthreads();

#pragma unroll
        for (int i = 0; i < 4; i++) {
            const float a = alpha_s[orow + i];
#pragma unroll
            for (int j = 0; j < 4; j++) o[i][j] *= a;
        }
#pragma unroll 8
        for (int k = 0; k < 32; ++k) {
            float vv[4];
#pragma unroll
            for (int j = 0; j < 4; j++) vv[j] = Vs[k][ocol + j];
#pragma unroll
            for (int i = 0; i < 4; i++) {
                const float p = Ps[orow + i][k];
#pragma unroll
                for (int j = 0; j < 4; j++) o[i][j] += p * vv[j];
            }
        }
        __syncthreads();
    }

#pragma unroll
    for (int i = 0; i < 4; i++) {
        const int n = qb + orow + i;
        if (n >= NSEQ) continue;
        const float inv = 1.0f / l_s[orow + i];
#pragma unroll
        for (int j = 0; j < 4; j++)
            g_attn[(size_t)n * DIMF + h * DH + ocol + j] = o[i][j] * inv;
    }
}

// ============================================================
extern "C" void kernel_launch(void* const* d_in, const int* in_sizes, int n_in,
                              void* d_out, int out_size)
{
    (void)in_sizes; (void)n_in; (void)out_size;
    const float* x     = (const float*)d_in[0];
    const float* rope  = (const float*)d_in[1];
    const float* Wqkv  = (const float*)d_in[2];
    const float* Wproj = (const float*)d_in[3];
    const float* bproj = (const float*)d_in[4];
    float* out = (float*)d_out;

    gemm_qkv_tc<<<dim3(24, 13), 256>>>(x, Wqkv);
    rope_kernel<<<(HWLEN * NH * 32 + 255) / 256, 256>>>(rope);
    attn_kernel<<<dim3(26, NH), 256>>>();
    gemm_proj_tc<<<dim3(8, 13), 256>>>(Wproj, bproj, out);
}

// round 4
// speedup vs baseline: 1.4221x; 1.2961x over previous
#include <cuda_runtime.h>
#include <cstdint>

#define NSEQ   1605
#define DIMF   1024
#define NH     16
#define DH     64
#define HWLEN  1600
#define PREFIX 5
#define NPAD   1664   // 26 * 64

// ---- scratch (device globals; zero-initialized at module load) ----
__device__ float g_q[(size_t)NH * NPAD * DH];
__device__ float g_k[(size_t)NH * NPAD * DH];
__device__ float g_v[(size_t)NH * NPAD * DH];
__device__ float g_attn[(size_t)NSEQ * DIMF];

// ============================================================
// mma.sync tf32 helpers (sm_80+ portable; tcgen05 not assemblable
// at the harness's compute_103 family target)
// ============================================================
__device__ __forceinline__ uint32_t f2tf32(float a) {
    uint32_t u; asm("cvt.rna.tf32.f32 %0, %1;" : "=r"(u) : "f"(a));
    return u;
}

#define MMA_TF32(d, a0, a1, a2, a3, b0, b1) \
    asm volatile("mma.sync.aligned.m16n8k8.row.col.f32.tf32.tf32.f32 " \
        "{%0,%1,%2,%3}, {%4,%5,%6,%7}, {%8,%9}, {%0,%1,%2,%3};" \
        : "+f"((d)[0]), "+f"((d)[1]), "+f"((d)[2]), "+f"((d)[3]) \
        : "r"(a0), "r"(a1), "r"(a2), "r"(a3), "r"(b0), "r"(b1))

__device__ __forceinline__ void split4(const float4 v, float4& hi, float4& lo) {
    hi.x = __uint_as_float(f2tf32(v.x)); lo.x = __uint_as_float(f2tf32(v.x - hi.x));
    hi.y = __uint_as_float(f2tf32(v.y)); lo.y = __uint_as_float(f2tf32(v.y - hi.y));
    hi.z = __uint_as_float(f2tf32(v.z)); lo.z = __uint_as_float(f2tf32(v.z - hi.z));
    hi.w = __uint_as_float(f2tf32(v.w)); lo.w = __uint_as_float(f2tf32(v.w - hi.w));
}
__device__ __forceinline__ void hi4(const float4 v, float4& hi) {
    hi.x = __uint_as_float(f2tf32(v.x));
    hi.y = __uint_as_float(f2tf32(v.y));
    hi.z = __uint_as_float(f2tf32(v.z));
    hi.w = __uint_as_float(f2tf32(v.w));
}

// ============================================================
// Double-buffered GEMM mainloop (templated pass count).
// acc[4][4][4] += A[bm:+128, 0:1024] @ B[bn:+128, 0:1024]^T
// PASSES==3: 3xTF32 (fp32-grade); PASSES==1: plain tf32.
// ============================================================
#define GST 20
#define GTILE (128 * GST)          // 2560 floats per tile

template<int PASSES>
__device__ __forceinline__ void gemm_db(
    const float* __restrict__ A, const float* __restrict__ B,
    int bm, int bn, int aRows, float* __restrict__ smem,
    float acc[4][4][4])
{
    constexpr int NB = (PASSES == 3) ? 4 : 2;     // tiles per buffer
    constexpr int BOFF_B = (PASSES == 3) ? 2 : 1; // Bh tile index

    const int tid = threadIdx.x;
    const int wid = tid >> 5, lane = tid & 31;
    const int warp_m = wid & 1, warp_n = wid >> 1;
    const int grp = lane >> 2, tig = lane & 3;
    const int r0 = tid >> 2;
    const int f0 = (tid & 3) * 4;

    float4 pa[2], pb[2];

#define G_LOAD(k0) do { \
    _Pragma("unroll") \
    for (int t = 0; t < 2; ++t) { \
        const int r = r0 + t * 64; \
        pa[t] = make_float4(0.f, 0.f, 0.f, 0.f); \
        if (bm + r < aRows) \
            pa[t] = *(const float4*)(A + (size_t)(bm + r) * 1024 + (k0) + f0); \
        pb[t] = *(const float4*)(B + (size_t)(bn + r) * 1024 + (k0) + f0); \
    } } while (0)

#define G_STORE(bufp) do { \
    float* Ah_ = (bufp); \
    float* Bh_ = (bufp) + BOFF_B * GTILE; \
    _Pragma("unroll") \
    for (int t = 0; t < 2; ++t) { \
        const int r = r0 + t * 64; \
        float4 hi, lo; \
        if (PASSES == 3) { \
            split4(pa[t], hi, lo); \
            *(float4*)(Ah_ + r * GST + f0) = hi; \
            *(float4*)(Ah_ + GTILE + r * GST + f0) = lo; \
            split4(pb[t], hi, lo); \
            *(float4*)(Bh_ + r * GST + f0) = hi; \
            *(float4*)(Bh_ + GTILE + r * GST + f0) = lo; \
        } else { \
            hi4(pa[t], hi); *(float4*)(Ah_ + r * GST + f0) = hi; \
            hi4(pb[t], hi); *(float4*)(Bh_ + r * GST + f0) = hi; \
        } \
    } } while (0)

    G_LOAD(0);
    G_STORE(smem);
    __syncthreads();

    for (int c = 0; c < 64; ++c) {
        float* cur = smem + (c & 1) * (NB * GTILE);
        if (c < 63) G_LOAD((c + 1) * 16);

        float* Ah = cur;
        float* Al = cur + GTILE;
        float* Bh = cur + BOFF_B * GTILE;
        float* Bl = cur + 3 * GTILE;

#pragma unroll
        for (int ks = 0; ks < 2; ++ks) {
            const int kc = ks * 8 + tig;
            uint32_t ah[4][4], al[4][4], bh[4][2], bl[4][2];
#pragma unroll
            for (int mt = 0; mt < 4; ++mt) {
                const int ra = (warp_m * 64 + mt * 16 + grp) * GST;
                ah[mt][0] = __float_as_uint(Ah[ra + kc]);
                ah[mt][1] = __float_as_uint(Ah[ra + 8 * GST + kc]);
                ah[mt][2] = __float_as_uint(Ah[ra + kc + 4]);
                ah[mt][3] = __float_as_uint(Ah[ra + 8 * GST + kc + 4]);
                if (PASSES == 3) {
                    al[mt][0] = __float_as_uint(Al[ra + kc]);
                    al[mt][1] = __float_as_uint(Al[ra + 8 * GST + kc]);
                    al[mt][2] = __float_as_uint(Al[ra + kc + 4]);
                    al[mt][3] = __float_as_uint(Al[ra + 8 * GST + kc + 4]);
                }
            }
#pragma unroll
            for (int nt = 0; nt < 4; ++nt) {
                const int rb = (warp_n * 32 + nt * 8 + grp) * GST + ks * 8 + tig;
                bh[nt][0] = __float_as_uint(Bh[rb]);
                bh[nt][1] = __float_as_uint(Bh[rb + 4]);
                if (PASSES == 3) {
                    bl[nt][0] = __float_as_uint(Bl[rb]);
                    bl[nt][1] = __float_as_uint(Bl[rb + 4]);
                }
            }
#pragma unroll
            for (int mt = 0; mt < 4; ++mt)
#pragma unroll
                for (int nt = 0; nt < 4; ++nt) {
                    MMA_TF32(acc[mt][nt], ah[mt][0], ah[mt][1], ah[mt][2], ah[mt][3],
                             bh[nt][0], bh[nt][1]);
                    if (PASSES == 3) {
                        MMA_TF32(acc[mt][nt], ah[mt][0], ah[mt][1], ah[mt][2], ah[mt][3],
                                 bl[nt][0], bl[nt][1]);
                        MMA_TF32(acc[mt][nt], al[mt][0], al[mt][1], al[mt][2], al[mt][3],
                                 bh[nt][0], bh[nt][1]);
                    }
                }
        }
        if (c < 63) G_STORE(smem + ((c + 1) & 1) * (NB * GTILE));
        __syncthreads();
    }
#undef G_LOAD
#undef G_STORE
}

#define GSMEM3 (2 * 4 * GTILE * 4)   // 81920 B
#define GSMEM1 (2 * 2 * GTILE * 4)   // 40960 B

extern __shared__ float dynsm[];

// ---- qkv (q,k columns): 3xTF32, scatter with 1/8 scale on q ----
__global__ __launch_bounds__(256, 1) void gemm_qk_kern(
    const float* __restrict__ A, const float* __restrict__ B)
{
    const int bm = blockIdx.y * 128;
    const int bn = blockIdx.x * 128;          // 0..2047 (q,k region)
    float acc[4][4][4];
#pragma unroll
    for (int a = 0; a < 4; a++)
#pragma unroll
        for (int b = 0; b < 4; b++)
#pragma unroll
            for (int cc = 0; cc < 4; cc++) acc[a][b][cc] = 0.0f;

    gemm_db<3>(A, B, bm, bn, NSEQ, dynsm, acc);

    const int tid = threadIdx.x;
    const int wid = tid >> 5, lane = tid & 31;
    const int warp_m = wid & 1, warp_n = wid >> 1;
    const int grp = lane >> 2, tig = lane & 3;

    const int s = bn >> 10;                   // 0=q, 1=k
    float* __restrict__ dst = (s == 0) ? g_q : g_k;
    const float scale = (s == 0) ? 0.125f : 1.0f;

#pragma unroll
    for (int mt = 0; mt < 4; ++mt)
#pragma unroll
        for (int half = 0; half < 2; ++half) {
            const int row = bm + warp_m * 64 + mt * 16 + grp + half * 8;
            if (row >= NSEQ) continue;
#pragma unroll
            for (int nt = 0; nt < 4; ++nt) {
                const int col = bn + warp_n * 32 + nt * 8 + tig * 2;
                const int h = (col & 1023) >> 6;
                const int d = col & 63;
                float2 v;
                v.x = acc[mt][nt][half * 2 + 0] * scale;
                v.y = acc[mt][nt][half * 2 + 1] * scale;
                *(float2*)&dst[((size_t)h * NPAD + row) * DH + d] = v;
            }
        }
}

// ---- qkv (v columns): 1xTF32 ----
__global__ __launch_bounds__(256, 2) void gemm_v_kern(
    const float* __restrict__ A, const float* __restrict__ B)
{
    const int bm = blockIdx.y * 128;
    const int bn = 2048 + blockIdx.x * 128;   // v region
    float acc[4][4][4];
#pragma unroll
    for (int a = 0; a < 4; a++)
#pragma unroll
        for (int b = 0; b < 4; b++)
#pragma unroll
            for (int cc = 0; cc < 4; cc++) acc[a][b][cc] = 0.0f;

    gemm_db<1>(A, B, bm, bn, NSEQ, dynsm, acc);

    const int tid = threadIdx.x;
    const int wid = tid >> 5, lane = tid & 31;
    const int warp_m = wid & 1, warp_n = wid >> 1;
    const int grp = lane >> 2, tig = lane & 3;

#pragma unroll
    for (int mt = 0; mt < 4; ++mt)
#pragma unroll
        for (int half = 0; half < 2; ++half) {
            const int row = bm + warp_m * 64 + mt * 16 + grp + half * 8;
            if (row >= NSEQ) continue;
#pragma unroll
            for (int nt = 0; nt < 4; ++nt) {
                const int col = bn + warp_n * 32 + nt * 8 + tig * 2;
                const int h = (col & 1023) >> 6;
                const int d = col & 63;
                float2 v;
                v.x = acc[mt][nt][half * 2 + 0];
                v.y = acc[mt][nt][half * 2 + 1];
                *(float2*)&g_v[((size_t)h * NPAD + row) * DH + d] = v;
            }
        }
}

// ---- proj: 1xTF32 + bias ----
__global__ __launch_bounds__(256, 2) void gemm_proj_kern(
    const float* __restrict__ B, const float* __restrict__ bias,
    float* __restrict__ C)
{
    const int bm = blockIdx.y * 128;
    const int bn = blockIdx.x * 128;
    float acc[4][4][4];
#pragma unroll
    for (int a = 0; a < 4; a++)
#pragma unroll
        for (int b = 0; b < 4; b++)
#pragma unroll
            for (int cc = 0; cc < 4; cc++) acc[a][b][cc] = 0.0f;

    gemm_db<1>(g_attn, B, bm, bn, NSEQ, dynsm, acc);

    const int tid = threadIdx.x;
    const int wid = tid >> 5, lane = tid & 31;
    const int warp_m = wid & 1, warp_n = wid >> 1;
    const int grp = lane >> 2, tig = lane & 3;

#pragma unroll
    for (int mt = 0; mt < 4; ++mt)
#pragma unroll
        for (int half = 0; half < 2; ++half) {
            const int row = bm + warp_m * 64 + mt * 16 + grp + half * 8;
            if (row >= NSEQ) continue;
#pragma unroll
            for (int nt = 0; nt < 4; ++nt) {
                const int col = bn + warp_n * 32 + nt * 8 + tig * 2;
                float2 v;
                v.x = acc[mt][nt][half * 2 + 0] + bias[col];
                v.y = acc[mt][nt][half * 2 + 1] + bias[col + 1];
                *(float2*)&C[(size_t)row * 1024 + col] = v;
            }
        }
}

// ============================================================
// RoPE on q and k, rows PREFIX..NSEQ-1
// ============================================================
__global__ void rope_kernel(const float* __restrict__ rope)
{
    int idx = blockIdx.x * blockDim.x + threadIdx.x;
    if (idx >= HWLEN * NH * 32) return;
    const int d = idx & 31;
    const int h = (idx >> 5) & 15;
    const int p = idx >> 9;
    const int n = PREFIX + p;

    const float s0 = rope[p * 64 + d];
    const float s1 = rope[p * 64 + d + 32];
    const float c0 = rope[HWLEN * 64 + p * 64 + d];
    const float c1 = rope[HWLEN * 64 + p * 64 + d + 32];

    const size_t base = ((size_t)h * NPAD + n) * DH;

    float q0 = g_q[base + d], q1 = g_q[base + d + 32];
    g_q[base + d]      = q0 * c0 - q1 * s0;
    g_q[base + d + 32] = q1 * c1 + q0 * s1;

    float k0 = g_k[base + d], k1 = g_k[base + d + 32];
    g_k[base + d]      = k0 * c0 - k1 * s0;
    g_k[base + d + 32] = k1 * c1 + k0 * s1;
}

// ============================================================
// Flash attention on mma.sync:
//   S (128x64) = 3xTF32,  softmax fp32 SIMT,  O += P V via 2x (V split)
// grid (13, 16), 256 threads, ~172 KB dynamic smem, 1 CTA/SM.
// ============================================================
#define AST 68
#define O_QH 0
#define O_QL 8704
#define O_KH 17408
#define O_KL 21760
#define O_VH 26112
#define O_VL 30464
#define O_PS 34816
#define O_M  43520
#define O_L  43648
#define O_AL 43776
#define ATTN_SMEM_BYTES (43904 * 4)

__global__ __launch_bounds__(256, 1) void attn_mma_kernel()
{
    float* Qh = dynsm + O_QH;  float* Ql = dynsm + O_QL;
    float* Kh = dynsm + O_KH;  float* Kl = dynsm + O_KL;
    float* Vh = dynsm + O_VH;  float* Vl = dynsm + O_VL;
    float* Ps = dynsm + O_PS;
    float* m_s = dynsm + O_M;  float* l_s = dynsm + O_L;  float* al_s = dynsm + O_AL;

    const int h  = blockIdx.y;
    const int qb = blockIdx.x * 128;
    const int tid = threadIdx.x;
    const int wid = tid >> 5, lane = tid & 31;
    const int warp_m = wid & 3, warp_n = wid >> 2;
    const int grp = lane >> 2, tig = lane & 3;

    const float* __restrict__ Qg = g_q + (size_t)h * NPAD * DH;
    const float* __restrict__ Kg = g_k + (size_t)h * NPAD * DH;
    const float* __restrict__ Vg = g_v + (size_t)h * NPAD * DH;

    // load Q tile 128x64 (padded rows are zero), split hi/lo
    for (int i = tid; i < 128 * 16; i += 256) {
        const int r = i >> 4, c4 = (i & 15) * 4;
        float4 v = *(const float4*)(Qg + (size_t)(qb + r) * DH + c4);
        float4 hi, lo; split4(v, hi, lo);
        *(float4*)(Qh + r * AST + c4) = hi;
        *(float4*)(Ql + r * AST + c4) = lo;
    }
    if (tid < 128) { m_s[tid] = -1e38f; l_s[tid] = 0.0f; }

    float o[2][4][4];
#pragma unroll
    for (int mt = 0; mt < 2; mt++)
#pragma unroll
        for (int nt = 0; nt < 4; nt++)
#pragma unroll
            for (int i = 0; i < 4; i++) o[mt][nt][i] = 0.0f;

    __syncthreads();

    for (int kt = 0; kt < 26; ++kt) {
        const int key0 = kt * 64;

        // K tile: split into Kh/Kl [key][d]; stage raw V into Ps [key][d]
        for (int i = tid; i < 64 * 16; i += 256) {
            const int r = i >> 4, c4 = (i & 15) * 4;
            float4 kv = *(const float4*)(Kg + (size_t)(key0 + r) * DH + c4);
            float4 hi, lo; split4(kv, hi, lo);
            *(float4*)(Kh + r * AST + c4) = hi;
            *(float4*)(Kl + r * AST + c4) = lo;
            float4 vv = *(const float4*)(Vg + (size_t)(key0 + r) * DH + c4);
            *(float4*)(Ps + r * AST + c4) = vv;
        }
        __syncthreads();

        // transpose V: Ps[key][d] -> Vh/Vl[d][key ^ swz]  (swizzled, conflict-free)
        {
            const int d = tid & 63, kq = tid >> 6;
            const int sw = (d >> 3) & 3;
#pragma unroll
            for (int j = 0; j < 16; ++j) {
                const int key = kq * 16 + j;
                const float v = Ps[key * AST + d];
                const float hi = __uint_as_float(f2tf32(v));
                const float lo = __uint_as_float(f2tf32(v - hi));
                Vh[d * AST + (key ^ sw)] = hi;
                Vl[d * AST + (key ^ sw)] = lo;
            }
        }
        __syncthreads();

        // S = Q K^T (3xTF32), accumulate in regs
        float sacc[2][4][4];
#pragma unroll
        for (int mt = 0; mt < 2; mt++)
#pragma unroll
            for (int nt = 0; nt < 4; nt++)
#pragma unroll
                for (int i = 0; i < 4; i++) sacc[mt][nt][i] = 0.0f;

#pragma unroll
        for (int ks = 0; ks < 8; ++ks) {
            const int k0 = ks * 8;
            uint32_t ah[2][4], al[2][4], bh[4][2], bl[4][2];
#pragma unroll
            for (int mt = 0; mt < 2; ++mt) {
                const int rm = warp_m * 32 + mt * 16;
                ah[mt][0] = __float_as_uint(Qh[(rm + grp) * AST + k0 + tig]);
                ah[mt][1] = __float_as_uint(Qh[(rm + grp + 8) * AST + k0 + tig]);
                ah[mt][2] = __float_as_uint(Qh[(rm + grp) * AST + k0 + tig + 4]);
                ah[mt][3] = __float_as_uint(Qh[(rm + grp + 8) * AST + k0 + tig + 4]);
                al[mt][0] = __float_as_uint(Ql[(rm + grp) * AST + k0 + tig]);
                al[mt][1] = __float_as_uint(Ql[(rm + grp + 8) * AST + k0 + tig]);
                al[mt][2] = __float_as_uint(Ql[(rm + grp) * AST + k0 + tig + 4]);
                al[mt][3] = __float_as_uint(Ql[(rm + grp + 8) * AST + k0 + tig + 4]);
            }
#pragma unroll
            for (int nt = 0; nt < 4; ++nt) {
                const int rn = warp_n * 32 + nt * 8 + grp;
                bh[nt][0] = __float_as_uint(Kh[rn * AST + k0 + tig]);
                bh[nt][1] = __float_as_uint(Kh[rn * AST + k0 + tig + 4]);
                bl[nt][0] = __float_as_uint(Kl[rn * AST + k0 + tig]);
                bl[nt][1] = __float_as_uint(Kl[rn * AST + k0 + tig + 4]);
            }
#pragma unroll
            for (int mt = 0; mt < 2; ++mt)
#pragma unroll
                for (int nt = 0; nt < 4; ++nt) {
                    MMA_TF32(sacc[mt][nt], ah[mt][0], ah[mt][1], ah[mt][2], ah[mt][3],
                             bh[nt][0], bh[nt][1]);
                    MMA_TF32(sacc[mt][nt], ah[mt][0], ah[mt][1], ah[mt][2], ah[mt][3],
                             bl[nt][0], bl[nt][1]);
                    MMA_TF32(sacc[mt][nt], al[mt][0], al[mt][1], al[mt][2], al[mt][3],
                             bh[nt][0], bh[nt][1]);
                }
        }

        // write S into Ps
#pragma unroll
        for (int mt = 0; mt < 2; ++mt) {
            const int r1 = warp_m * 32 + mt * 16 + grp;
#pragma unroll
            for (int nt = 0; nt < 4; ++nt) {
                const int col = warp_n * 32 + nt * 8 + tig * 2;
                *(float2*)(Ps + r1 * AST + col) =
                    make_float2(sacc[mt][nt][0], sacc[mt][nt][1]);
                *(float2*)(Ps + (r1 + 8) * AST + col) =
                    make_float2(sacc[mt][nt][2], sacc[mt][nt][3]);
            }
        }
        __syncthreads();

        // online softmax: 2 threads per row
        {
            const int row = tid >> 1, half = tid & 1;
            float* prow = Ps + row * AST + half * 32;
            const int kbase = key0 + half * 32;
            float mx = -1e30f;
#pragma unroll
            for (int c = 0; c < 32; ++c) {
                float v = prow[c];
                if (kbase + c >= NSEQ) { v = -1e30f; prow[c] = v; }
                mx = fmaxf(mx, v);
            }
            mx = fmaxf(mx, __shfl_xor_sync(0xffffffffu, mx, 1));
            const float mold = m_s[row];
            const float mnew = fmaxf(mold, mx);
            const float a = __expf(mold - mnew);
            float ssum = 0.0f;
#pragma unroll
            for (int c = 0; c < 32; ++c) {
                const float p = __expf(prow[c] - mnew);
                prow[c] = p;
                ssum += p;
            }
            ssum += __shfl_xor_sync(0xffffffffu, ssum, 1);
            if (half == 0) {
                m_s[row] = mnew;
                l_s[row] = l_s[row] * a + ssum;
                al_s[row] = a;
            }
        }
        __syncthreads();

        // rescale O by alpha, then O += P V (2 passes, V split)
#pragma unroll
        for (int mt = 0; mt < 2; ++mt) {
            const int r1 = warp_m * 32 + mt * 16 + grp;
            const float a1 = al_s[r1];
            const float a2 = al_s[r1 + 8];
#pragma unroll
            for (int nt = 0; nt < 4; ++nt) {
                o[mt][nt][0] *= a1; o[mt][nt][1] *= a1;
                o[mt][nt][2] *= a2; o[mt][nt][3] *= a2;
            }
        }
#pragma unroll
        for (int ks = 0; ks < 8; ++ks) {
            const int k0 = ks * 8;
            uint32_t pa_[2][4], bh[4][2], bl[4][2];
#pragma unroll
            for (int mt = 0; mt < 2; ++mt) {
                const int rm = warp_m * 32 + mt * 16;
                pa_[mt][0] = f2tf32(Ps[(rm + grp) * AST + k0 + tig]);
                pa_[mt][1] = f2tf32(Ps[(rm + grp + 8) * AST + k0 + tig]);
                pa_[mt][2] = f2tf32(Ps[(rm + grp) * AST + k0 + tig + 4]);
                pa_[mt][3] = f2tf32(Ps[(rm + grp + 8) * AST + k0 + tig + 4]);
            }
#pragma unroll
            for (int nt = 0; nt < 4; ++nt) {
                const int rn = warp_n * 32 + nt * 8 + grp;     // d index
                const int sw = (rn >> 3) & 3;
                bh[nt][0] = __float_as_uint(Vh[rn * AST + ((k0 + tig) ^ sw)]);
                bh[nt][1] = __float_as_uint(Vh[rn * AST + ((k0 + tig + 4) ^ sw)]);
                bl[nt][0] = __float_as_uint(Vl[rn * AST + ((k0 + tig) ^ sw)]);
                bl[nt][1] = __float_as_uint(Vl[rn * AST + ((k0 + tig + 4) ^ sw)]);
            }
#pragma unroll
            for (int mt = 0; mt < 2; ++mt)
#pragma unroll
                for (int nt = 0; nt < 4; ++nt) {
                    MMA_TF32(o[mt][nt], pa_[mt][0], pa_[mt][1], pa_[mt][2], pa_[mt][3],
                             bh[nt][0], bh[nt][1]);
                    MMA_TF32(o[mt][nt], pa_[mt][0], pa_[mt][1], pa_[mt][2], pa_[mt][3],
                             bl[nt][0], bl[nt][1]);
                }
        }
        __syncthreads();
    }

    // epilogue: normalize by l, write g_attn[n][h*64 + d]
#pragma unroll
    for (int mt = 0; mt < 2; ++mt) {
        const int r1 = warp_m * 32 + mt * 16 + grp;
        const int n1 = qb + r1, n2 = n1 + 8;
        const float inv1 = 1.0f / l_s[r1];
        const float inv2 = 1.0f / l_s[r1 + 8];
#pragma unroll
        for (int nt = 0; nt < 4; ++nt) {
            const int col = warp_n * 32 + nt * 8 + tig * 2;
            if (n1 < NSEQ)
                *(float2*)&g_attn[(size_t)n1 * DIMF + h * DH + col] =
                    make_float2(o[mt][nt][0] * inv1, o[mt][nt][1] * inv1);
            if (n2 < NSEQ)
                *(float2*)&g_attn[(size_t)n2 * DIMF + h * DH + col] =
                    make_float2(o[mt][nt][2] * inv2, o[mt][nt][3] * inv2);
        }
    }
}

// ============================================================
extern "C" void kernel_launch(void* const* d_in, const int* in_sizes, int n_in,
                              void* d_out, int out_size)
{
    (void)in_sizes; (void)n_in; (void)out_size;
    const float* x     = (const float*)d_in[0];
    const float* rope  = (const float*)d_in[1];
    const float* Wqkv  = (const float*)d_in[2];
    const float* Wproj = (const float*)d_in[3];
    const float* bproj = (const float*)d_in[4];
    float* out = (float*)d_out;

    static int configured = 0;
    if (!configured) {
        cudaFuncSetAttribute(gemm_qk_kern,   cudaFuncAttributeMaxDynamicSharedMemorySize, GSMEM3);
        cudaFuncSetAttribute(gemm_v_kern,    cudaFuncAttributeMaxDynamicSharedMemorySize, GSMEM1);
        cudaFuncSetAttribute(gemm_proj_kern, cudaFuncAttributeMaxDynamicSharedMemorySize, GSMEM1);
        cudaFuncSetAttribute(attn_mma_kernel, cudaFuncAttributeMaxDynamicSharedMemorySize, ATTN_SMEM_BYTES);
        configured = 1;
    }

    gemm_qk_kern<<<dim3(16, 13), 256, GSMEM3>>>(x, Wqkv);
    gemm_v_kern<<<dim3(8, 13), 256, GSMEM1>>>(x, Wqkv);
    rope_kernel<<<(HWLEN * NH * 32 + 255) / 256, 256>>>(rope);
    attn_mma_kernel<<<dim3(13, NH), 256, ATTN_SMEM_BYTES>>>();
    gemm_proj_kern<<<dim3(8, 13), 256, GSMEM1>>>(Wproj, bproj, out);
}

// round 5
// speedup vs baseline: 1.6656x; 1.1712x over previous
#include <cuda_runtime.h>
#include <cstdint>

#define NSEQ   1605
#define DIMF   1024
#define NH     16
#define DH     64
#define HWLEN  1600
#define PREFIX 5
#define NPAD   1664   // 26 * 64

// ---- scratch (device globals; zero-initialized at module load) ----
__device__ float g_q[(size_t)NH * NPAD * DH];
__device__ float g_k[(size_t)NH * NPAD * DH];
__device__ float g_v[(size_t)NH * NPAD * DH];
__device__ float g_attn[(size_t)NSEQ * DIMF];

// ============================================================
// mma.sync tf32 helpers (sm_80+ portable; tcgen05 not assemblable
// at the harness's compute_103 family target)
// ============================================================
__device__ __forceinline__ uint32_t f2tf32(float a) {
    uint32_t u; asm("cvt.rna.tf32.f32 %0, %1;" : "=r"(u) : "f"(a));
    return u;
}

#define MMA_TF32(d, a0, a1, a2, a3, b0, b1) \
    asm volatile("mma.sync.aligned.m16n8k8.row.col.f32.tf32.tf32.f32 " \
        "{%0,%1,%2,%3}, {%4,%5,%6,%7}, {%8,%9}, {%0,%1,%2,%3};" \
        : "+f"((d)[0]), "+f"((d)[1]), "+f"((d)[2]), "+f"((d)[3]) \
        : "r"(a0), "r"(a1), "r"(a2), "r"(a3), "r"(b0), "r"(b1))

__device__ __forceinline__ void split4(const float4 v, float4& hi, float4& lo) {
    hi.x = __uint_as_float(f2tf32(v.x)); lo.x = __uint_as_float(f2tf32(v.x - hi.x));
    hi.y = __uint_as_float(f2tf32(v.y)); lo.y = __uint_as_float(f2tf32(v.y - hi.y));
    hi.z = __uint_as_float(f2tf32(v.z)); lo.z = __uint_as_float(f2tf32(v.z - hi.z));
    hi.w = __uint_as_float(f2tf32(v.w)); lo.w = __uint_as_float(f2tf32(v.w - hi.w));
}
__device__ __forceinline__ void hi4(const float4 v, float4& hi) {
    hi.x = __uint_as_float(f2tf32(v.x));
    hi.y = __uint_as_float(f2tf32(v.y));
    hi.z = __uint_as_float(f2tf32(v.z));
    hi.w = __uint_as_float(f2tf32(v.w));
}

// ============================================================
// Double-buffered GEMM mainloop (templated pass count).
// ============================================================
#define GST 20
#define GTILE (128 * GST)

template<int PASSES>
__device__ __forceinline__ void gemm_db(
    const float* __restrict__ A, const float* __restrict__ B,
    int bm, int bn, int aRows, float* __restrict__ smem,
    float acc[4][4][4])
{
    constexpr int NB = (PASSES == 3) ? 4 : 2;
    constexpr int BOFF_B = (PASSES == 3) ? 2 : 1;

    const int tid = threadIdx.x;
    const int wid = tid >> 5, lane = tid & 31;
    const int warp_m = wid & 1, warp_n = wid >> 1;
    const int grp = lane >> 2, tig = lane & 3;
    const int r0 = tid >> 2;
    const int f0 = (tid & 3) * 4;

    float4 pa[2], pb[2];

#define G_LOAD(k0) do { \
    _Pragma("unroll") \
    for (int t = 0; t < 2; ++t) { \
        const int r = r0 + t * 64; \
        pa[t] = make_float4(0.f, 0.f, 0.f, 0.f); \
        if (bm + r < aRows) \
            pa[t] = *(const float4*)(A + (size_t)(bm + r) * 1024 + (k0) + f0); \
        pb[t] = *(const float4*)(B + (size_t)(bn + r) * 1024 + (k0) + f0); \
    } } while (0)

#define G_STORE(bufp) do { \
    float* Ah_ = (bufp); \
    float* Bh_ = (bufp) + BOFF_B * GTILE; \
    _Pragma("unroll") \
    for (int t = 0; t < 2; ++t) { \
        const int r = r0 + t * 64; \
        float4 hi, lo; \
        if (PASSES == 3) { \
            split4(pa[t], hi, lo); \
            *(float4*)(Ah_ + r * GST + f0) = hi; \
            *(float4*)(Ah_ + GTILE + r * GST + f0) = lo; \
            split4(pb[t], hi, lo); \
            *(float4*)(Bh_ + r * GST + f0) = hi; \
            *(float4*)(Bh_ + GTILE + r * GST + f0) = lo; \
        } else { \
            hi4(pa[t], hi); *(float4*)(Ah_ + r * GST + f0) = hi; \
            hi4(pb[t], hi); *(float4*)(Bh_ + r * GST + f0) = hi; \
        } \
    } } while (0)

    G_LOAD(0);
    G_STORE(smem);
    __syncthreads();

    for (int c = 0; c < 64; ++c) {
        float* cur = smem + (c & 1) * (NB * GTILE);
        if (c < 63) G_LOAD((c + 1) * 16);

        float* Ah = cur;
        float* Al = cur + GTILE;
        float* Bh = cur + BOFF_B * GTILE;
        float* Bl = cur + 3 * GTILE;

#pragma unroll
        for (int ks = 0; ks < 2; ++ks) {
            const int kc = ks * 8 + tig;
            uint32_t ah[4][4], al[4][4], bh[4][2], bl[4][2];
#pragma unroll
            for (int mt = 0; mt < 4; ++mt) {
                const int ra = (warp_m * 64 + mt * 16 + grp) * GST;
                ah[mt][0] = __float_as_uint(Ah[ra + kc]);
                ah[mt][1] = __float_as_uint(Ah[ra + 8 * GST + kc]);
                ah[mt][2] = __float_as_uint(Ah[ra + kc + 4]);
                ah[mt][3] = __float_as_uint(Ah[ra + 8 * GST + kc + 4]);
                if (PASSES == 3) {
                    al[mt][0] = __float_as_uint(Al[ra + kc]);
                    al[mt][1] = __float_as_uint(Al[ra + 8 * GST + kc]);
                    al[mt][2] = __float_as_uint(Al[ra + kc + 4]);
                    al[mt][3] = __float_as_uint(Al[ra + 8 * GST + kc + 4]);
                }
            }
#pragma unroll
            for (int nt = 0; nt < 4; ++nt) {
                const int rb = (warp_n * 32 + nt * 8 + grp) * GST + ks * 8 + tig;
                bh[nt][0] = __float_as_uint(Bh[rb]);
                bh[nt][1] = __float_as_uint(Bh[rb + 4]);
                if (PASSES == 3) {
                    bl[nt][0] = __float_as_uint(Bl[rb]);
                    bl[nt][1] = __float_as_uint(Bl[rb + 4]);
                }
            }
#pragma unroll
            for (int mt = 0; mt < 4; ++mt)
#pragma unroll
                for (int nt = 0; nt < 4; ++nt) {
                    MMA_TF32(acc[mt][nt], ah[mt][0], ah[mt][1], ah[mt][2], ah[mt][3],
                             bh[nt][0], bh[nt][1]);
                    if (PASSES == 3) {
                        MMA_TF32(acc[mt][nt], ah[mt][0], ah[mt][1], ah[mt][2], ah[mt][3],
                                 bl[nt][0], bl[nt][1]);
                        MMA_TF32(acc[mt][nt], al[mt][0], al[mt][1], al[mt][2], al[mt][3],
                                 bh[nt][0], bh[nt][1]);
                    }
                }
        }
        if (c < 63) G_STORE(smem + ((c + 1) & 1) * (NB * GTILE));
        __syncthreads();
    }
#undef G_LOAD
#undef G_STORE
}

#define GSMEM3 (2 * 4 * GTILE * 4)
#define GSMEM1 (2 * 2 * GTILE * 4)

extern __shared__ float dynsm[];

// ---- qkv (q,k columns): 3xTF32 ----
__global__ __launch_bounds__(256, 1) void gemm_qk_kern(
    const float* __restrict__ A, const float* __restrict__ B)
{
    const int bm = blockIdx.y * 128;
    const int bn = blockIdx.x * 128;
    float acc[4][4][4];
#pragma unroll
    for (int a = 0; a < 4; a++)
#pragma unroll
        for (int b = 0; b < 4; b++)
#pragma unroll
            for (int cc = 0; cc < 4; cc++) acc[a][b][cc] = 0.0f;

    gemm_db<3>(A, B, bm, bn, NSEQ, dynsm, acc);

    const int tid = threadIdx.x;
    const int wid = tid >> 5, lane = tid & 31;
    const int warp_m = wid & 1, warp_n = wid >> 1;
    const int grp = lane >> 2, tig = lane & 3;

    const int s = bn >> 10;
    float* __restrict__ dst = (s == 0) ? g_q : g_k;
    const float scale = (s == 0) ? 0.125f : 1.0f;

#pragma unroll
    for (int mt = 0; mt < 4; ++mt)
#pragma unroll
        for (int half = 0; half < 2; ++half) {
            const int row = bm + warp_m * 64 + mt * 16 + grp + half * 8;
            if (row >= NSEQ) continue;
#pragma unroll
            for (int nt = 0; nt < 4; ++nt) {
                const int col = bn + warp_n * 32 + nt * 8 + tig * 2;
                const int h = (col & 1023) >> 6;
                const int d = col & 63;
                float2 v;
                v.x = acc[mt][nt][half * 2 + 0] * scale;
                v.y = acc[mt][nt][half * 2 + 1] * scale;
                *(float2*)&dst[((size_t)h * NPAD + row) * DH + d] = v;
            }
        }
}

// ---- qkv (v columns): 1xTF32 ----
__global__ __launch_bounds__(256, 2) void gemm_v_kern(
    const float* __restrict__ A, const float* __restrict__ B)
{
    const int bm = blockIdx.y * 128;
    const int bn = 2048 + blockIdx.x * 128;
    float acc[4][4][4];
#pragma unroll
    for (int a = 0; a < 4; a++)
#pragma unroll
        for (int b = 0; b < 4; b++)
#pragma unroll
            for (int cc = 0; cc < 4; cc++) acc[a][b][cc] = 0.0f;

    gemm_db<1>(A, B, bm, bn, NSEQ, dynsm, acc);

    const int tid = threadIdx.x;
    const int wid = tid >> 5, lane = tid & 31;
    const int warp_m = wid & 1, warp_n = wid >> 1;
    const int grp = lane >> 2, tig = lane & 3;

#pragma unroll
    for (int mt = 0; mt < 4; ++mt)
#pragma unroll
        for (int half = 0; half < 2; ++half) {
            const int row = bm + warp_m * 64 + mt * 16 + grp + half * 8;
            if (row >= NSEQ) continue;
#pragma unroll
            for (int nt = 0; nt < 4; ++nt) {
                const int col = bn + warp_n * 32 + nt * 8 + tig * 2;
                const int h = (col & 1023) >> 6;
                const int d = col & 63;
                float2 v;
                v.x = acc[mt][nt][half * 2 + 0];
                v.y = acc[mt][nt][half * 2 + 1];
                *(float2*)&g_v[((size_t)h * NPAD + row) * DH + d] = v;
            }
        }
}

// ---- proj: 1xTF32 + bias ----
__global__ __launch_bounds__(256, 2) void gemm_proj_kern(
    const float* __restrict__ B, const float* __restrict__ bias,
    float* __restrict__ C)
{
    const int bm = blockIdx.y * 128;
    const int bn = blockIdx.x * 128;
    float acc[4][4][4];
#pragma unroll
    for (int a = 0; a < 4; a++)
#pragma unroll
        for (int b = 0; b < 4; b++)
#pragma unroll
            for (int cc = 0; cc < 4; cc++) acc[a][b][cc] = 0.0f;

    gemm_db<1>(g_attn, B, bm, bn, NSEQ, dynsm, acc);

    const int tid = threadIdx.x;
    const int wid = tid >> 5, lane = tid & 31;
    const int warp_m = wid & 1, warp_n = wid >> 1;
    const int grp = lane >> 2, tig = lane & 3;

#pragma unroll
    for (int mt = 0; mt < 4; ++mt)
#pragma unroll
        for (int half = 0; half < 2; ++half) {
            const int row = bm + warp_m * 64 + mt * 16 + grp + half * 8;
            if (row >= NSEQ) continue;
#pragma unroll
            for (int nt = 0; nt < 4; ++nt) {
                const int col = bn + warp_n * 32 + nt * 8 + tig * 2;
                float2 v;
                v.x = acc[mt][nt][half * 2 + 0] + bias[col];
                v.y = acc[mt][nt][half * 2 + 1] + bias[col + 1];
                *(float2*)&C[(size_t)row * 1024 + col] = v;
            }
        }
}

// ============================================================
// RoPE on q and k, rows PREFIX..NSEQ-1
// ============================================================
__global__ void rope_kernel(const float* __restrict__ rope)
{
    int idx = blockIdx.x * blockDim.x + threadIdx.x;
    if (idx >= HWLEN * NH * 32) return;
    const int d = idx & 31;
    const int h = (idx >> 5) & 15;
    const int p = idx >> 9;
    const int n = PREFIX + p;

    const float s0 = rope[p * 64 + d];
    const float s1 = rope[p * 64 + d + 32];
    const float c0 = rope[HWLEN * 64 + p * 64 + d];
    const float c1 = rope[HWLEN * 64 + p * 64 + d + 32];

    const size_t base = ((size_t)h * NPAD + n) * DH;

    float q0 = g_q[base + d], q1 = g_q[base + d + 32];
    g_q[base + d]      = q0 * c0 - q1 * s0;
    g_q[base + d + 32] = q1 * c1 + q0 * s1;

    float k0 = g_k[base + d], k1 = g_k[base + d + 32];
    g_k[base + d]      = k0 * c0 - k1 * s0;
    g_k[base + d + 32] = k1 * c1 + k0 * s1;
}

// ============================================================
// Flash attention v2: q-tile 64, k-tile 32, 2 CTAs/SM,
// V in natural [key][d] layout (no transpose), register prefetch.
// grid (26, 16), 256 threads, ~79 KB dynamic smem.
// ============================================================
#define QST 68
#define VST 72
#define PST 36
#define A_QH 0
#define A_QL 4352
#define A_KH 8704
#define A_KL 10880
#define A_VH 13056
#define A_VL 15360
#define A_PS 17664
#define A_M  19968
#define A_L  20032
#define A_AL 20096
#define ATTN_SMEM_BYTES (20160 * 4)

__global__ __launch_bounds__(256, 2) void attn_mma_kernel()
{
    float* Qh = dynsm + A_QH;  float* Ql = dynsm + A_QL;
    float* Kh = dynsm + A_KH;  float* Kl = dynsm + A_KL;
    float* Vh = dynsm + A_VH;  float* Vl = dynsm + A_VL;
    float* Ps = dynsm + A_PS;
    float* m_s = dynsm + A_M;  float* l_s = dynsm + A_L;  float* al_s = dynsm + A_AL;

    const int h  = blockIdx.y;
    const int qb = blockIdx.x * 64;
    const int tid = threadIdx.x;
    const int wid = tid >> 5, lane = tid & 31;
    const int warp_m = wid & 1;          // 2 x 32 q-rows
    const int warp_n = wid >> 1;         // 4 x (8 keys | 16 d)
    const int grp = lane >> 2, tig = lane & 3;

    const float* __restrict__ Qg = g_q + (size_t)h * NPAD * DH;
    const float* __restrict__ Kg = g_k + (size_t)h * NPAD * DH;
    const float* __restrict__ Vg = g_v + (size_t)h * NPAD * DH;

    // ---- prologue: Q tile 64x64 -> hi/lo ----
#pragma unroll
    for (int t = 0; t < 4; ++t) {
        const int idx = tid + t * 256;
        const int r = idx >> 4, c4 = (idx & 15) * 4;
        float4 v = *(const float4*)(Qg + (size_t)(qb + r) * DH + c4);
        float4 hi, lo; split4(v, hi, lo);
        *(float4*)(Qh + r * QST + c4) = hi;
        *(float4*)(Ql + r * QST + c4) = lo;
    }
    if (tid < 64) { m_s[tid] = -1e38f; l_s[tid] = 0.0f; }

    // ---- K/V tile 0 into regs, then smem ----
    const int lr = tid >> 4;              // 0..15, +16 per t
    const int lc4 = (tid & 15) * 4;
    float4 pk[2], pv[2];
#pragma unroll
    for (int t = 0; t < 2; ++t) {
        const int r = lr + t * 16;
        pk[t] = *(const float4*)(Kg + (size_t)r * DH + lc4);
        pv[t] = *(const float4*)(Vg + (size_t)r * DH + lc4);
    }
#pragma unroll
    for (int t = 0; t < 2; ++t) {
        const int r = lr + t * 16;
        float4 hi, lo;
        split4(pk[t], hi, lo);
        *(float4*)(Kh + r * QST + lc4) = hi;
        *(float4*)(Kl + r * QST + lc4) = lo;
        split4(pv[t], hi, lo);
        *(float4*)(Vh + r * VST + lc4) = hi;
        *(float4*)(Vl + r * VST + lc4) = lo;
    }
    __syncthreads();

    float o[2][2][4];
#pragma unroll
    for (int mt = 0; mt < 2; mt++)
#pragma unroll
        for (int nt = 0; nt < 2; nt++)
#pragma unroll
            for (int i = 0; i < 4; i++) o[mt][nt][i] = 0.0f;

    const int nkt = (NSEQ + 31) / 32;    // 51
    for (int kt = 0; kt < nkt; ++kt) {
        const int key0 = kt * 32;

        // ---- S = Q K^T (3xTF32): warp tile 32q x 8keys ----
        float sacc[2][4];
#pragma unroll
        for (int mt = 0; mt < 2; mt++)
#pragma unroll
            for (int i = 0; i < 4; i++) sacc[mt][i] = 0.0f;

#pragma unroll
        for (int ks = 0; ks < 8; ++ks) {
            const int k0 = ks * 8;
            uint32_t ah[2][4], al[2][4], bh[2], bl[2];
#pragma unroll
            for (int mt = 0; mt < 2; ++mt) {
                const int rm = warp_m * 32 + mt * 16;
                ah[mt][0] = __float_as_uint(Qh[(rm + grp) * QST + k0 + tig]);
                ah[mt][1] = __float_as_uint(Qh[(rm + grp + 8) * QST + k0 + tig]);
                ah[mt][2] = __float_as_uint(Qh[(rm + grp) * QST + k0 + tig + 4]);
                ah[mt][3] = __float_as_uint(Qh[(rm + grp + 8) * QST + k0 + tig + 4]);
                al[mt][0] = __float_as_uint(Ql[(rm + grp) * QST + k0 + tig]);
                al[mt][1] = __float_as_uint(Ql[(rm + grp + 8) * QST + k0 + tig]);
                al[mt][2] = __float_as_uint(Ql[(rm + grp) * QST + k0 + tig + 4]);
                al[mt][3] = __float_as_uint(Ql[(rm + grp + 8) * QST + k0 + tig + 4]);
            }
            {
                const int rn = warp_n * 8 + grp;
                bh[0] = __float_as_uint(Kh[rn * QST + k0 + tig]);
                bh[1] = __float_as_uint(Kh[rn * QST + k0 + tig + 4]);
                bl[0] = __float_as_uint(Kl[rn * QST + k0 + tig]);
                bl[1] = __float_as_uint(Kl[rn * QST + k0 + tig + 4]);
            }
#pragma unroll
            for (int mt = 0; mt < 2; ++mt) {
                MMA_TF32(sacc[mt], ah[mt][0], ah[mt][1], ah[mt][2], ah[mt][3], bh[0], bh[1]);
                MMA_TF32(sacc[mt], ah[mt][0], ah[mt][1], ah[mt][2], ah[mt][3], bl[0], bl[1]);
                MMA_TF32(sacc[mt], al[mt][0], al[mt][1], al[mt][2], al[mt][3], bh[0], bh[1]);
            }
        }

        // write S tile to Ps [64 rows][32 cols, stride 36]
#pragma unroll
        for (int mt = 0; mt < 2; ++mt) {
            const int r1 = warp_m * 32 + mt * 16 + grp;
            const int col = warp_n * 8 + tig * 2;
            *(float2*)(Ps + r1 * PST + col) = make_float2(sacc[mt][0], sacc[mt][1]);
            *(float2*)(Ps + (r1 + 8) * PST + col) = make_float2(sacc[mt][2], sacc[mt][3]);
        }
        __syncthreads();

        // ---- online softmax: 4 lanes per row, 8 cols each, vectorized ----
        {
            const int row = tid >> 2, part = tid & 3;
            float* prow = Ps + row * PST + part * 8;
            const int kbase = key0 + part * 8;
            float4 v0 = *(float4*)prow;
            float4 v1 = *(float4*)(prow + 4);
            float pv8[8] = {v0.x, v0.y, v0.z, v0.w, v1.x, v1.y, v1.z, v1.w};
            float mx = -1e30f;
#pragma unroll
            for (int c = 0; c < 8; ++c) {
                if (kbase + c >= NSEQ) pv8[c] = -1e30f;
                mx = fmaxf(mx, pv8[c]);
            }
            mx = fmaxf(mx, __shfl_xor_sync(0xffffffffu, mx, 1));
            mx = fmaxf(mx, __shfl_xor_sync(0xffffffffu, mx, 2));
            const float mold = m_s[row];
            const float mnew = fmaxf(mold, mx);
            const float a = __expf(mold - mnew);
            float ssum = 0.0f;
#pragma unroll
            for (int c = 0; c < 8; ++c) {
                pv8[c] = __expf(pv8[c] - mnew);
                ssum += pv8[c];
            }
            *(float4*)prow = make_float4(pv8[0], pv8[1], pv8[2], pv8[3]);
            *(float4*)(prow + 4) = make_float4(pv8[4], pv8[5], pv8[6], pv8[7]);
            ssum += __shfl_xor_sync(0xffffffffu, ssum, 1);
            ssum += __shfl_xor_sync(0xffffffffu, ssum, 2);
            if (part == 0) {
                m_s[row] = mnew;
                l_s[row] = l_s[row] * a + ssum;
                al_s[row] = a;
            }
        }
        __syncthreads();

        // ---- prefetch next K/V tile into regs (hidden under PV) ----
        if (kt + 1 < nkt) {
            const int nk0 = key0 + 32;
#pragma unroll
            for (int t = 0; t < 2; ++t) {
                const int r = nk0 + lr + t * 16;
                pk[t] = *(const float4*)(Kg + (size_t)r * DH + lc4);
                pv[t] = *(const float4*)(Vg + (size_t)r * DH + lc4);
            }
        }

        // ---- rescale O, then O += P V (V natural layout, 2-pass) ----
#pragma unroll
        for (int mt = 0; mt < 2; ++mt) {
            const int r1 = warp_m * 32 + mt * 16 + grp;
            const float a1 = al_s[r1];
            const float a2 = al_s[r1 + 8];
#pragma unroll
            for (int nt = 0; nt < 2; ++nt) {
                o[mt][nt][0] *= a1; o[mt][nt][1] *= a1;
                o[mt][nt][2] *= a2; o[mt][nt][3] *= a2;
            }
        }
#pragma unroll
        for (int kk = 0; kk < 4; ++kk) {
            const int k0 = kk * 8;
            uint32_t pa_[2][4], vb_h[2][2], vb_l[2][2];
#pragma unroll
            for (int mt = 0; mt < 2; ++mt) {
                const int rm = warp_m * 32 + mt * 16;
                pa_[mt][0] = f2tf32(Ps[(rm + grp) * PST + k0 + tig]);
                pa_[mt][1] = f2tf32(Ps[(rm + grp + 8) * PST + k0 + tig]);
                pa_[mt][2] = f2tf32(Ps[(rm + grp) * PST + k0 + tig + 4]);
                pa_[mt][3] = f2tf32(Ps[(rm + grp + 8) * PST + k0 + tig + 4]);
            }
#pragma unroll
            for (int nt = 0; nt < 2; ++nt) {
                const int d = warp_n * 16 + nt * 8 + grp;
                vb_h[nt][0] = __float_as_uint(Vh[(k0 + tig) * VST + d]);
                vb_h[nt][1] = __float_as_uint(Vh[(k0 + tig + 4) * VST + d]);
                vb_l[nt][0] = __float_as_uint(Vl[(k0 + tig) * VST + d]);
                vb_l[nt][1] = __float_as_uint(Vl[(k0 + tig + 4) * VST + d]);
            }
#pragma unroll
            for (int mt = 0; mt < 2; ++mt)
#pragma unroll
                for (int nt = 0; nt < 2; ++nt) {
                    MMA_TF32(o[mt][nt], pa_[mt][0], pa_[mt][1], pa_[mt][2], pa_[mt][3],
                             vb_h[nt][0], vb_h[nt][1]);
                    MMA_TF32(o[mt][nt], pa_[mt][0], pa_[mt][1], pa_[mt][2], pa_[mt][3],
                             vb_l[nt][0], vb_l[nt][1]);
                }
        }
        __syncthreads();

        // ---- store prefetched tile into K/V smem ----
        if (kt + 1 < nkt) {
#pragma unroll
            for (int t = 0; t < 2; ++t) {
                const int r = lr + t * 16;
                float4 hi, lo;
                split4(pk[t], hi, lo);
                *(float4*)(Kh + r * QST + lc4) = hi;
                *(float4*)(Kl + r * QST + lc4) = lo;
                split4(pv[t], hi, lo);
                *(float4*)(Vh + r * VST + lc4) = hi;
                *(float4*)(Vl + r * VST + lc4) = lo;
            }
            __syncthreads();
        }
    }

    // ---- epilogue: normalize, write g_attn ----
#pragma unroll
    for (int mt = 0; mt < 2; ++mt) {
        const int r1 = warp_m * 32 + mt * 16 + grp;
        const int n1 = qb + r1, n2 = n1 + 8;
        const float inv1 = 1.0f / l_s[r1];
        const float inv2 = 1.0f / l_s[r1 + 8];
#pragma unroll
        for (int nt = 0; nt < 2; ++nt) {
            const int col = warp_n * 16 + nt * 8 + tig * 2;
            if (n1 < NSEQ)
                *(float2*)&g_attn[(size_t)n1 * DIMF + h * DH + col] =
                    make_float2(o[mt][nt][0] * inv1, o[mt][nt][1] * inv1);
            if (n2 < NSEQ)
                *(float2*)&g_attn[(size_t)n2 * DIMF + h * DH + col] =
                    make_float2(o[mt][nt][2] * inv2, o[mt][nt][3] * inv2);
        }
    }
}

// ============================================================
extern "C" void kernel_launch(void* const* d_in, const int* in_sizes, int n_in,
                              void* d_out, int out_size)
{
    (void)in_sizes; (void)n_in; (void)out_size;
    const float* x     = (const float*)d_in[0];
    const float* rope  = (const float*)d_in[1];
    const float* Wqkv  = (const float*)d_in[2];
    const float* Wproj = (const float*)d_in[3];
    const float* bproj = (const float*)d_in[4];
    float* out = (float*)d_out;

    static int configured = 0;
    if (!configured) {
        cudaFuncSetAttribute(gemm_qk_kern,    cudaFuncAttributeMaxDynamicSharedMemorySize, GSMEM3);
        cudaFuncSetAttribute(gemm_v_kern,     cudaFuncAttributeMaxDynamicSharedMemorySize, GSMEM1);
        cudaFuncSetAttribute(gemm_proj_kern,  cudaFuncAttributeMaxDynamicSharedMemorySize, GSMEM1);
        cudaFuncSetAttribute(attn_mma_kernel, cudaFuncAttributeMaxDynamicSharedMemorySize, ATTN_SMEM_BYTES);
        configured = 1;
    }

    gemm_qk_kern<<<dim3(16, 13), 256, GSMEM3>>>(x, Wqkv);
    gemm_v_kern<<<dim3(8, 13), 256, GSMEM1>>>(x, Wqkv);
    rope_kernel<<<(HWLEN * NH * 32 + 255) / 256, 256>>>(rope);
    attn_mma_kernel<<<dim3(26, NH), 256, ATTN_SMEM_BYTES>>>();
    gemm_proj_kern<<<dim3(8, 13), 256, GSMEM1>>>(Wproj, bproj, out);
}

// round 6
// speedup vs baseline: 1.6767x; 1.0067x over previous
#include <cuda_runtime.h>
#include <cstdint>

#define NSEQ   1605
#define DIMF   1024
#define NH     16
#define DH     64
#define HWLEN  1600
#define PREFIX 5
#define NPAD   1664   // 26 * 64

// ---- scratch (device globals; zero-initialized at module load) ----
__device__ float g_q[(size_t)NH * NPAD * DH];
__device__ float g_k[(size_t)NH * NPAD * DH];
__device__ float g_v[(size_t)NH * NPAD * DH];
__device__ float g_attn[(size_t)NSEQ * DIMF];

// ============================================================
// mma.sync tf32 helpers
// ============================================================
__device__ __forceinline__ uint32_t f2tf32(float a) {
    uint32_t u; asm("cvt.rna.tf32.f32 %0, %1;" : "=r"(u) : "f"(a));
    return u;
}

#define MMA_TF32(d, a0, a1, a2, a3, b0, b1) \
    asm volatile("mma.sync.aligned.m16n8k8.row.col.f32.tf32.tf32.f32 " \
        "{%0,%1,%2,%3}, {%4,%5,%6,%7}, {%8,%9}, {%0,%1,%2,%3};" \
        : "+f"((d)[0]), "+f"((d)[1]), "+f"((d)[2]), "+f"((d)[3]) \
        : "r"(a0), "r"(a1), "r"(a2), "r"(a3), "r"(b0), "r"(b1))

// split one raw float into tf32 hi/lo (both tf32-rounded)
#define SPLIT1(v, hi, lo) do { \
    hi = f2tf32(v); \
    lo = f2tf32((v) - __uint_as_float(hi)); \
} while (0)

__device__ __forceinline__ void hi4(const float4 v, float4& hi) {
    hi.x = __uint_as_float(f2tf32(v.x));
    hi.y = __uint_as_float(f2tf32(v.y));
    hi.z = __uint_as_float(f2tf32(v.z));
    hi.w = __uint_as_float(f2tf32(v.w));
}

extern __shared__ float dynsm[];

// ============================================================
// 3xTF32 GEMM, RAW smem + split-at-read, double-buffered.
// acc += A[bm:+128,0:1024] @ B[bn:+128,0:1024]^T
// smem: 2 buffers x (A 128x20 + B 128x20) raw = 40960 B
// ============================================================
#define GST 20
#define GTILE (128 * GST)

__device__ __forceinline__ void gemm_db3r(
    const float* __restrict__ A, const float* __restrict__ B,
    int bm, int bn, int aRows, float* __restrict__ smem,
    float acc[4][4][4])
{
    const int tid = threadIdx.x;
    const int wid = tid >> 5, lane = tid & 31;
    const int warp_m = wid & 1, warp_n = wid >> 1;
    const int grp = lane >> 2, tig = lane & 3;
    const int r0 = tid >> 2;
    const int f0 = (tid & 3) * 4;

    float4 pa[2], pb[2];

#define G3_LOAD(k0) do { \
    _Pragma("unroll") \
    for (int t = 0; t < 2; ++t) { \
        const int r = r0 + t * 64; \
        pa[t] = make_float4(0.f, 0.f, 0.f, 0.f); \
        if (bm + r < aRows) \
            pa[t] = *(const float4*)(A + (size_t)(bm + r) * 1024 + (k0) + f0); \
        pb[t] = *(const float4*)(B + (size_t)(bn + r) * 1024 + (k0) + f0); \
    } } while (0)

#define G3_STORE(bufp) do { \
    float* Ar_ = (bufp); \
    float* Br_ = (bufp) + GTILE; \
    _Pragma("unroll") \
    for (int t = 0; t < 2; ++t) { \
        const int r = r0 + t * 64; \
        *(float4*)(Ar_ + r * GST + f0) = pa[t]; \
        *(float4*)(Br_ + r * GST + f0) = pb[t]; \
    } } while (0)

    G3_LOAD(0);
    G3_STORE(smem);
    __syncthreads();

    for (int c = 0; c < 64; ++c) {
        float* cur = smem + (c & 1) * (2 * GTILE);
        if (c < 63) G3_LOAD((c + 1) * 16);

        float* Ar = cur;
        float* Br = cur + GTILE;

#pragma unroll
        for (int ks = 0; ks < 2; ++ks) {
            const int kc = ks * 8 + tig;
            uint32_t ah[4][4], al[4][4];
#pragma unroll
            for (int mt = 0; mt < 4; ++mt) {
                const int ra = (warp_m * 64 + mt * 16 + grp) * GST;
                float a0 = Ar[ra + kc];
                float a1 = Ar[ra + 8 * GST + kc];
                float a2 = Ar[ra + kc + 4];
                float a3 = Ar[ra + 8 * GST + kc + 4];
                SPLIT1(a0, ah[mt][0], al[mt][0]);
                SPLIT1(a1, ah[mt][1], al[mt][1]);
                SPLIT1(a2, ah[mt][2], al[mt][2]);
                SPLIT1(a3, ah[mt][3], al[mt][3]);
            }
#pragma unroll
            for (int nt = 0; nt < 4; ++nt) {
                const int rb = (warp_n * 32 + nt * 8 + grp) * GST + kc;
                float b0 = Br[rb];
                float b1 = Br[rb + 4];
                uint32_t bh0, bl0, bh1, bl1;
                SPLIT1(b0, bh0, bl0);
                SPLIT1(b1, bh1, bl1);
#pragma unroll
                for (int mt = 0; mt < 4; ++mt) {
                    MMA_TF32(acc[mt][nt], ah[mt][0], ah[mt][1], ah[mt][2], ah[mt][3], bh0, bh1);
                    MMA_TF32(acc[mt][nt], ah[mt][0], ah[mt][1], ah[mt][2], ah[mt][3], bl0, bl1);
                    MMA_TF32(acc[mt][nt], al[mt][0], al[mt][1], al[mt][2], al[mt][3], bh0, bh1);
                }
            }
        }
        if (c < 63) G3_STORE(smem + ((c + 1) & 1) * (2 * GTILE));
        __syncthreads();
    }
#undef G3_LOAD
#undef G3_STORE
}

// ============================================================
// 1xTF32 GEMM (unchanged from round 5, pre-converted hi)
// ============================================================
__device__ __forceinline__ void gemm_db1(
    const float* __restrict__ A, const float* __restrict__ B,
    int bm, int bn, int aRows, float* __restrict__ smem,
    float acc[4][4][4])
{
    const int tid = threadIdx.x;
    const int wid = tid >> 5, lane = tid & 31;
    const int warp_m = wid & 1, warp_n = wid >> 1;
    const int grp = lane >> 2, tig = lane & 3;
    const int r0 = tid >> 2;
    const int f0 = (tid & 3) * 4;

    float4 pa[2], pb[2];

#define G1_LOAD(k0) do { \
    _Pragma("unroll") \
    for (int t = 0; t < 2; ++t) { \
        const int r = r0 + t * 64; \
        pa[t] = make_float4(0.f, 0.f, 0.f, 0.f); \
        if (bm + r < aRows) \
            pa[t] = *(const float4*)(A + (size_t)(bm + r) * 1024 + (k0) + f0); \
        pb[t] = *(const float4*)(B + (size_t)(bn + r) * 1024 + (k0) + f0); \
    } } while (0)

#define G1_STORE(bufp) do { \
    float* Ah_ = (bufp); \
    float* Bh_ = (bufp) + GTILE; \
    _Pragma("unroll") \
    for (int t = 0; t < 2; ++t) { \
        const int r = r0 + t * 64; \
        float4 hi; \
        hi4(pa[t], hi); *(float4*)(Ah_ + r * GST + f0) = hi; \
        hi4(pb[t], hi); *(float4*)(Bh_ + r * GST + f0) = hi; \
    } } while (0)

    G1_LOAD(0);
    G1_STORE(smem);
    __syncthreads();

    for (int c = 0; c < 64; ++c) {
        float* cur = smem + (c & 1) * (2 * GTILE);
        if (c < 63) G1_LOAD((c + 1) * 16);

        float* Ah = cur;
        float* Bh = cur + GTILE;

#pragma unroll
        for (int ks = 0; ks < 2; ++ks) {
            const int kc = ks * 8 + tig;
            uint32_t ah[4][4];
#pragma unroll
            for (int mt = 0; mt < 4; ++mt) {
                const int ra = (warp_m * 64 + mt * 16 + grp) * GST;
                ah[mt][0] = __float_as_uint(Ah[ra + kc]);
                ah[mt][1] = __float_as_uint(Ah[ra + 8 * GST + kc]);
                ah[mt][2] = __float_as_uint(Ah[ra + kc + 4]);
                ah[mt][3] = __float_as_uint(Ah[ra + 8 * GST + kc + 4]);
            }
#pragma unroll
            for (int nt = 0; nt < 4; ++nt) {
                const int rb = (warp_n * 32 + nt * 8 + grp) * GST + kc;
                uint32_t bh0 = __float_as_uint(Bh[rb]);
                uint32_t bh1 = __float_as_uint(Bh[rb + 4]);
#pragma unroll
                for (int mt = 0; mt < 4; ++mt)
                    MMA_TF32(acc[mt][nt], ah[mt][0], ah[mt][1], ah[mt][2], ah[mt][3], bh0, bh1);
            }
        }
        if (c < 63) G1_STORE(smem + ((c + 1) & 1) * (2 * GTILE));
        __syncthreads();
    }
#undef G1_LOAD
#undef G1_STORE
}

#define GSMEM_B (2 * 2 * GTILE * 4)   // 40960 B (both variants)

// ---- qkv (q,k columns): 3xTF32 raw ----
__global__ __launch_bounds__(256, 2) void gemm_qk_kern(
    const float* __restrict__ A, const float* __restrict__ B)
{
    const int bm = blockIdx.y * 128;
    const int bn = blockIdx.x * 128;
    float acc[4][4][4];
#pragma unroll
    for (int a = 0; a < 4; a++)
#pragma unroll
        for (int b = 0; b < 4; b++)
#pragma unroll
            for (int cc = 0; cc < 4; cc++) acc[a][b][cc] = 0.0f;

    gemm_db3r(A, B, bm, bn, NSEQ, dynsm, acc);

    const int tid = threadIdx.x;
    const int wid = tid >> 5, lane = tid & 31;
    const int warp_m = wid & 1, warp_n = wid >> 1;
    const int grp = lane >> 2, tig = lane & 3;

    const int s = bn >> 10;
    float* __restrict__ dst = (s == 0) ? g_q : g_k;
    const float scale = (s == 0) ? 0.125f : 1.0f;

#pragma unroll
    for (int mt = 0; mt < 4; ++mt)
#pragma unroll
        for (int half = 0; half < 2; ++half) {
            const int row = bm + warp_m * 64 + mt * 16 + grp + half * 8;
            if (row >= NSEQ) continue;
#pragma unroll
            for (int nt = 0; nt < 4; ++nt) {
                const int col = bn + warp_n * 32 + nt * 8 + tig * 2;
                const int h = (col & 1023) >> 6;
                const int d = col & 63;
                float2 v;
                v.x = acc[mt][nt][half * 2 + 0] * scale;
                v.y = acc[mt][nt][half * 2 + 1] * scale;
                *(float2*)&dst[((size_t)h * NPAD + row) * DH + d] = v;
            }
        }
}

// ---- qkv (v columns): 1xTF32 ----
__global__ __launch_bounds__(256, 2) void gemm_v_kern(
    const float* __restrict__ A, const float* __restrict__ B)
{
    const int bm = blockIdx.y * 128;
    const int bn = 2048 + blockIdx.x * 128;
    float acc[4][4][4];
#pragma unroll
    for (int a = 0; a < 4; a++)
#pragma unroll
        for (int b = 0; b < 4; b++)
#pragma unroll
            for (int cc = 0; cc < 4; cc++) acc[a][b][cc] = 0.0f;

    gemm_db1(A, B, bm, bn, NSEQ, dynsm, acc);

    const int tid = threadIdx.x;
    const int wid = tid >> 5, lane = tid & 31;
    const int warp_m = wid & 1, warp_n = wid >> 1;
    const int grp = lane >> 2, tig = lane & 3;

#pragma unroll
    for (int mt = 0; mt < 4; ++mt)
#pragma unroll
        for (int half = 0; half < 2; ++half) {
            const int row = bm + warp_m * 64 + mt * 16 + grp + half * 8;
            if (row >= NSEQ) continue;
#pragma unroll
            for (int nt = 0; nt < 4; ++nt) {
                const int col = bn + warp_n * 32 + nt * 8 + tig * 2;
                const int h = (col & 1023) >> 6;
                const int d = col & 63;
                float2 v;
                v.x = acc[mt][nt][half * 2 + 0];
                v.y = acc[mt][nt][half * 2 + 1];
                *(float2*)&g_v[((size_t)h * NPAD + row) * DH + d] = v;
            }
        }
}

// ---- proj: 1xTF32 + bias ----
__global__ __launch_bounds__(256, 2) void gemm_proj_kern(
    const float* __restrict__ B, const float* __restrict__ bias,
    float* __restrict__ C)
{
    const int bm = blockIdx.y * 128;
    const int bn = blockIdx.x * 128;
    float acc[4][4][4];
#pragma unroll
    for (int a = 0; a < 4; a++)
#pragma unroll
        for (int b = 0; b < 4; b++)
#pragma unroll
            for (int cc = 0; cc < 4; cc++) acc[a][b][cc] = 0.0f;

    gemm_db1(g_attn, B, bm, bn, NSEQ, dynsm, acc);

    const int tid = threadIdx.x;
    const int wid = tid >> 5, lane = tid & 31;
    const int warp_m = wid & 1, warp_n = wid >> 1;
    const int grp = lane >> 2, tig = lane & 3;

#pragma unroll
    for (int mt = 0; mt < 4; ++mt)
#pragma unroll
        for (int half = 0; half < 2; ++half) {
            const int row = bm + warp_m * 64 + mt * 16 + grp + half * 8;
            if (row >= NSEQ) continue;
#pragma unroll
            for (int nt = 0; nt < 4; ++nt) {
                const int col = bn + warp_n * 32 + nt * 8 + tig * 2;
                float2 v;
                v.x = acc[mt][nt][half * 2 + 0] + bias[col];
                v.y = acc[mt][nt][half * 2 + 1] + bias[col + 1];
                *(float2*)&C[(size_t)row * 1024 + col] = v;
            }
        }
}

// ============================================================
// RoPE on q and k, rows PREFIX..NSEQ-1
// ============================================================
__global__ void rope_kernel(const float* __restrict__ rope)
{
    int idx = blockIdx.x * blockDim.x + threadIdx.x;
    if (idx >= HWLEN * NH * 32) return;
    const int d = idx & 31;
    const int h = (idx >> 5) & 15;
    const int p = idx >> 9;
    const int n = PREFIX + p;

    const float s0 = rope[p * 64 + d];
    const float s1 = rope[p * 64 + d + 32];
    const float c0 = rope[HWLEN * 64 + p * 64 + d];
    const float c1 = rope[HWLEN * 64 + p * 64 + d + 32];

    const size_t base = ((size_t)h * NPAD + n) * DH;

    float q0 = g_q[base + d], q1 = g_q[base + d + 32];
    g_q[base + d]      = q0 * c0 - q1 * s0;
    g_q[base + d + 32] = q1 * c1 + q0 * s1;

    float k0 = g_k[base + d], k1 = g_k[base + d + 32];
    g_k[base + d]      = k0 * c0 - k1 * s0;
    g_k[base + d + 32] = k1 * c1 + k0 * s1;
}

// ============================================================
// Flash attention v3: 128 threads, 4 warps, warp = 16 q-rows x 32 keys.
// Raw smem + split-at-read; register softmax; warp-private P.
// smem 44 KB -> up to 4 CTAs/SM. grid (26, 16).
// ============================================================
#define A_Q 0                       // 64*68 = 4352
#define A_K 4352                    // 32*68 = 2176
#define A_V 6528                    // 32*72 = 2304
#define A_P 8832                    // 4 warps * 16*36 = 2304
#define ATTN_SMEM_BYTES ((8832 + 2304) * 4)

__global__ __launch_bounds__(128, 4) void attn_mma3()
{
    float* Qs = dynsm + A_Q;
    float* Ks = dynsm + A_K;
    float* Vs = dynsm + A_V;

    const int h  = blockIdx.y;
    const int qb = blockIdx.x * 64;
    const int tid = threadIdx.x;
    const int wid = tid >> 5, lane = tid & 31;
    const int grp = lane >> 2, tig = lane & 3;
    const int row0 = wid * 16;

    float* Pw = dynsm + A_P + wid * 576;

    const float* __restrict__ Qg = g_q + (size_t)h * NPAD * DH;
    const float* __restrict__ Kg = g_k + (size_t)h * NPAD * DH;
    const float* __restrict__ Vg = g_v + (size_t)h * NPAD * DH;

    // ---- prologue: Q tile 64x64 raw ----
#pragma unroll
    for (int t = 0; t < 8; ++t) {
        const int idx = tid + t * 128;
        const int r = idx >> 4, c4 = (idx & 15) * 4;
        *(float4*)(Qs + r * 68 + c4) =
            *(const float4*)(Qg + (size_t)(qb + r) * DH + c4);
    }

    // ---- K/V tile 0: regs -> smem ----
    const int lr = tid >> 4;              // 0..7, +8 per t
    const int lc4 = (tid & 15) * 4;
    float4 pk[4], pv[4];
#pragma unroll
    for (int t = 0; t < 4; ++t) {
        const int r = lr + t * 8;
        pk[t] = *(const float4*)(Kg + (size_t)r * DH + lc4);
        pv[t] = *(const float4*)(Vg + (size_t)r * DH + lc4);
    }
#pragma unroll
    for (int t = 0; t < 4; ++t) {
        const int r = lr + t * 8;
        *(float4*)(Ks + r * 68 + lc4) = pk[t];
        *(float4*)(Vs + r * 72 + lc4) = pv[t];
    }
    __syncthreads();

    float m0 = -1e38f, m1 = -1e38f, l0 = 0.0f, l1 = 0.0f;
    float o[8][4];
#pragma unroll
    for (int nt = 0; nt < 8; nt++)
#pragma unroll
        for (int i = 0; i < 4; i++) o[nt][i] = 0.0f;

    const int nkt = (NSEQ + 31) / 32;    // 51
    for (int kt = 0; kt < nkt; ++kt) {
        const int key0 = kt * 32;

        // ---- S = Q K^T (3xTF32), warp = 16 rows x 32 keys ----
        float sacc[4][4];
#pragma unroll
        for (int nt = 0; nt < 4; nt++)
#pragma unroll
            for (int i = 0; i < 4; i++) sacc[nt][i] = 0.0f;

#pragma unroll
        for (int ks = 0; ks < 8; ++ks) {
            const int k0 = ks * 8;
            uint32_t ah[4], al[4];
            {
                float a0 = Qs[(row0 + grp) * 68 + k0 + tig];
                float a1 = Qs[(row0 + grp + 8) * 68 + k0 + tig];
                float a2 = Qs[(row0 + grp) * 68 + k0 + tig + 4];
                float a3 = Qs[(row0 + grp + 8) * 68 + k0 + tig + 4];
                SPLIT1(a0, ah[0], al[0]);
                SPLIT1(a1, ah[1], al[1]);
                SPLIT1(a2, ah[2], al[2]);
                SPLIT1(a3, ah[3], al[3]);
            }
#pragma unroll
            for (int nt = 0; nt < 4; ++nt) {
                const int key = nt * 8 + grp;
                float b0 = Ks[key * 68 + k0 + tig];
                float b1 = Ks[key * 68 + k0 + tig + 4];
                uint32_t bh0, bl0, bh1, bl1;
                SPLIT1(b0, bh0, bl0);
                SPLIT1(b1, bh1, bl1);
                MMA_TF32(sacc[nt], ah[0], ah[1], ah[2], ah[3], bh0, bh1);
                MMA_TF32(sacc[nt], ah[0], ah[1], ah[2], ah[3], bl0, bl1);
                MMA_TF32(sacc[nt], al[0], al[1], al[2], al[3], bh0, bh1);
            }
        }

        // ---- prefetch next K/V into regs (latency hidden under softmax+PV) ----
        if (kt + 1 < nkt) {
            const int nk0 = key0 + 32;
#pragma unroll
            for (int t = 0; t < 4; ++t) {
                const int r = nk0 + lr + t * 8;
                pk[t] = *(const float4*)(Kg + (size_t)r * DH + lc4);
                pv[t] = *(const float4*)(Vg + (size_t)r * DH + lc4);
            }
        }

        // ---- register softmax (rows grp, grp+8; cols nt*8 + 2tig{,+1}) ----
        {
            float mx0 = -1e30f, mx1 = -1e30f;
#pragma unroll
            for (int nt = 0; nt < 4; ++nt) {
                const int c0 = key0 + nt * 8 + tig * 2;
                if (c0 >= NSEQ)     { sacc[nt][0] = -1e30f; sacc[nt][2] = -1e30f; }
                if (c0 + 1 >= NSEQ) { sacc[nt][1] = -1e30f; sacc[nt][3] = -1e30f; }
                mx0 = fmaxf(mx0, fmaxf(sacc[nt][0], sacc[nt][1]));
                mx1 = fmaxf(mx1, fmaxf(sacc[nt][2], sacc[nt][3]));
            }
            mx0 = fmaxf(mx0, __shfl_xor_sync(0xffffffffu, mx0, 1));
            mx0 = fmaxf(mx0, __shfl_xor_sync(0xffffffffu, mx0, 2));
            mx1 = fmaxf(mx1, __shfl_xor_sync(0xffffffffu, mx1, 1));
            mx1 = fmaxf(mx1, __shfl_xor_sync(0xffffffffu, mx1, 2));

            const float mn0 = fmaxf(m0, mx0);
            const float mn1 = fmaxf(m1, mx1);
            const float a0 = __expf(m0 - mn0);
            const float a1 = __expf(m1 - mn1);
            m0 = mn0; m1 = mn1;

            float s0 = 0.0f, s1 = 0.0f;
#pragma unroll
            for (int nt = 0; nt < 4; ++nt) {
                sacc[nt][0] = __expf(sacc[nt][0] - mn0); s0 += sacc[nt][0];
                sacc[nt][1] = __expf(sacc[nt][1] - mn0); s0 += sacc[nt][1];
                sacc[nt][2] = __expf(sacc[nt][2] - mn1); s1 += sacc[nt][2];
                sacc[nt][3] = __expf(sacc[nt][3] - mn1); s1 += sacc[nt][3];
            }
            s0 += __shfl_xor_sync(0xffffffffu, s0, 1);
            s0 += __shfl_xor_sync(0xffffffffu, s0, 2);
            s1 += __shfl_xor_sync(0xffffffffu, s1, 1);
            s1 += __shfl_xor_sync(0xffffffffu, s1, 2);
            l0 = l0 * a0 + s0;
            l1 = l1 * a1 + s1;

            // store P to warp-private smem
#pragma unroll
            for (int nt = 0; nt < 4; ++nt) {
                const int col = nt * 8 + tig * 2;
                *(float2*)(Pw + grp * 36 + col) = make_float2(sacc[nt][0], sacc[nt][1]);
                *(float2*)(Pw + (grp + 8) * 36 + col) = make_float2(sacc[nt][2], sacc[nt][3]);
            }
            __syncwarp();

            // rescale O
#pragma unroll
            for (int nt = 0; nt < 8; ++nt) {
                o[nt][0] *= a0; o[nt][1] *= a0;
                o[nt][2] *= a1; o[nt][3] *= a1;
            }
        }

        // ---- O += P V (V natural layout, split-at-read, 2-pass) ----
#pragma unroll
        for (int kk = 0; kk < 4; ++kk) {
            const int k0 = kk * 8;
            uint32_t pa0 = f2tf32(Pw[grp * 36 + k0 + tig]);
            uint32_t pa1 = f2tf32(Pw[(grp + 8) * 36 + k0 + tig]);
            uint32_t pa2 = f2tf32(Pw[grp * 36 + k0 + tig + 4]);
            uint32_t pa3 = f2tf32(Pw[(grp + 8) * 36 + k0 + tig + 4]);
#pragma unroll
            for (int nt = 0; nt < 8; ++nt) {
                const int d = nt * 8 + grp;
                float v0 = Vs[(k0 + tig) * 72 + d];
                float v1 = Vs[(k0 + tig + 4) * 72 + d];
                uint32_t vh0, vl0, vh1, vl1;
                SPLIT1(v0, vh0, vl0);
                SPLIT1(v1, vh1, vl1);
                MMA_TF32(o[nt], pa0, pa1, pa2, pa3, vh0, vh1);
                MMA_TF32(o[nt], pa0, pa1, pa2, pa3, vl0, vl1);
            }
        }
        __syncthreads();

        // ---- store prefetched K/V tile ----
        if (kt + 1 < nkt) {
#pragma unroll
            for (int t = 0; t < 4; ++t) {
                const int r = lr + t * 8;
                *(float4*)(Ks + r * 68 + lc4) = pk[t];
                *(float4*)(Vs + r * 72 + lc4) = pv[t];
            }
            __syncthreads();
        }
    }

    // ---- epilogue: normalize, write g_attn ----
    const float inv0 = 1.0f / l0;
    const float inv1 = 1.0f / l1;
    const int n0 = qb + row0 + grp;
    const int n1 = n0 + 8;
#pragma unroll
    for (int nt = 0; nt < 8; ++nt) {
        const int col = h * DH + nt * 8 + tig * 2;
        if (n0 < NSEQ)
            *(float2*)&g_attn[(size_t)n0 * DIMF + col] =
                make_float2(o[nt][0] * inv0, o[nt][1] * inv0);
        if (n1 < NSEQ)
            *(float2*)&g_attn[(size_t)n1 * DIMF + col] =
                make_float2(o[nt][2] * inv1, o[nt][3] * inv1);
    }
}

// ============================================================
extern "C" void kernel_launch(void* const* d_in, const int* in_sizes, int n_in,
                              void* d_out, int out_size)
{
    (void)in_sizes; (void)n_in; (void)out_size;
    const float* x     = (const float*)d_in[0];
    const float* rope  = (const float*)d_in[1];
    const float* Wqkv  = (const float*)d_in[2];
    const float* Wproj = (const float*)d_in[3];
    const float* bproj = (const float*)d_in[4];
    float* out = (float*)d_out;

    static int configured = 0;
    if (!configured) {
        cudaFuncSetAttribute(gemm_qk_kern,   cudaFuncAttributeMaxDynamicSharedMemorySize, GSMEM_B);
        cudaFuncSetAttribute(gemm_v_kern,    cudaFuncAttributeMaxDynamicSharedMemorySize, GSMEM_B);
        cudaFuncSetAttribute(gemm_proj_kern, cudaFuncAttributeMaxDynamicSharedMemorySize, GSMEM_B);
        cudaFuncSetAttribute(attn_mma3,      cudaFuncAttributeMaxDynamicSharedMemorySize, ATTN_SMEM_BYTES);
        configured = 1;
    }

    gemm_qk_kern<<<dim3(16, 13), 256, GSMEM_B>>>(x, Wqkv);
    gemm_v_kern<<<dim3(8, 13), 256, GSMEM_B>>>(x, Wqkv);
    rope_kernel<<<(HWLEN * NH * 32 + 255) / 256, 256>>>(rope);
    attn_mma3<<<dim3(26, NH), 128, ATTN_SMEM_BYTES>>>();
    gemm_proj_kern<<<dim3(8, 13), 256, GSMEM_B>>>(Wproj, bproj, out);
}

// round 7
// speedup vs baseline: 1.7476x; 1.0423x over previous
#include <cuda_runtime.h>
#include <cstdint>

#define NSEQ   1605
#define DIMF   1024
#define NH     16
#define DH     64
#define HWLEN  1600
#define PREFIX 5
#define NPAD   1664   // 26 * 64

// ---- scratch (device globals; zero-initialized at module load) ----
__device__ float g_q[(size_t)NH * NPAD * DH];
__device__ float g_k[(size_t)NH * NPAD * DH];
__device__ float g_v[(size_t)NH * NPAD * DH];
__device__ float g_attn[(size_t)NSEQ * DIMF];

// ============================================================
// mma.sync tf32 helpers
// ============================================================
__device__ __forceinline__ uint32_t f2tf32(float a) {
    uint32_t u; asm("cvt.rna.tf32.f32 %0, %1;" : "=r"(u) : "f"(a));
    return u;
}

#define MMA_TF32(d, a0, a1, a2, a3, b0, b1) \
    asm volatile("mma.sync.aligned.m16n8k8.row.col.f32.tf32.tf32.f32 " \
        "{%0,%1,%2,%3}, {%4,%5,%6,%7}, {%8,%9}, {%0,%1,%2,%3};" \
        : "+f"((d)[0]), "+f"((d)[1]), "+f"((d)[2]), "+f"((d)[3]) \
        : "r"(a0), "r"(a1), "r"(a2), "r"(a3), "r"(b0), "r"(b1))

// split one raw float into tf32 hi/lo (both tf32-rounded)
#define SPLIT1(v, hi, lo) do { \
    hi = f2tf32(v); \
    lo = f2tf32((v) - __uint_as_float(hi)); \
} while (0)

__device__ __forceinline__ void split4(const float4 v, float4& hi, float4& lo) {
    hi.x = __uint_as_float(f2tf32(v.x)); lo.x = __uint_as_float(f2tf32(v.x - hi.x));
    hi.y = __uint_as_float(f2tf32(v.y)); lo.y = __uint_as_float(f2tf32(v.y - hi.y));
    hi.z = __uint_as_float(f2tf32(v.z)); lo.z = __uint_as_float(f2tf32(v.z - hi.z));
    hi.w = __uint_as_float(f2tf32(v.w)); lo.w = __uint_as_float(f2tf32(v.w - hi.w));
}
__device__ __forceinline__ void hi4(const float4 v, float4& hi) {
    hi.x = __uint_as_float(f2tf32(v.x));
    hi.y = __uint_as_float(f2tf32(v.y));
    hi.z = __uint_as_float(f2tf32(v.z));
    hi.w = __uint_as_float(f2tf32(v.w));
}

extern __shared__ float dynsm[];

// ============================================================
// 3xTF32 GEMM, RAW smem + split-at-read, double-buffered.
// (A/B splits here are NOT warp-redundant: each fragment split is
// reused across the 4-wide other-tile loop, ~1 cvt per MMA.)
// ============================================================
#define GST 20
#define GTILE (128 * GST)

__device__ __forceinline__ void gemm_db3r(
    const float* __restrict__ A, const float* __restrict__ B,
    int bm, int bn, int aRows, float* __restrict__ smem,
    float acc[4][4][4])
{
    const int tid = threadIdx.x;
    const int wid = tid >> 5, lane = tid & 31;
    const int warp_m = wid & 1, warp_n = wid >> 1;
    const int grp = lane >> 2, tig = lane & 3;
    const int r0 = tid >> 2;
    const int f0 = (tid & 3) * 4;

    float4 pa[2], pb[2];

#define G3_LOAD(k0) do { \
    _Pragma("unroll") \
    for (int t = 0; t < 2; ++t) { \
        const int r = r0 + t * 64; \
        pa[t] = make_float4(0.f, 0.f, 0.f, 0.f); \
        if (bm + r < aRows) \
            pa[t] = *(const float4*)(A + (size_t)(bm + r) * 1024 + (k0) + f0); \
        pb[t] = *(const float4*)(B + (size_t)(bn + r) * 1024 + (k0) + f0); \
    } } while (0)

#define G3_STORE(bufp) do { \
    float* Ar_ = (bufp); \
    float* Br_ = (bufp) + GTILE; \
    _Pragma("unroll") \
    for (int t = 0; t < 2; ++t) { \
        const int r = r0 + t * 64; \
        *(float4*)(Ar_ + r * GST + f0) = pa[t]; \
        *(float4*)(Br_ + r * GST + f0) = pb[t]; \
    } } while (0)

    G3_LOAD(0);
    G3_STORE(smem);
    __syncthreads();

    for (int c = 0; c < 64; ++c) {
        float* cur = smem + (c & 1) * (2 * GTILE);
        if (c < 63) G3_LOAD((c + 1) * 16);

        float* Ar = cur;
        float* Br = cur + GTILE;

#pragma unroll
        for (int ks = 0; ks < 2; ++ks) {
            const int kc = ks * 8 + tig;
            uint32_t ah[4][4], al[4][4];
#pragma unroll
            for (int mt = 0; mt < 4; ++mt) {
                const int ra = (warp_m * 64 + mt * 16 + grp) * GST;
                float a0 = Ar[ra + kc];
                float a1 = Ar[ra + 8 * GST + kc];
                float a2 = Ar[ra + kc + 4];
                float a3 = Ar[ra + 8 * GST + kc + 4];
                SPLIT1(a0, ah[mt][0], al[mt][0]);
                SPLIT1(a1, ah[mt][1], al[mt][1]);
                SPLIT1(a2, ah[mt][2], al[mt][2]);
                SPLIT1(a3, ah[mt][3], al[mt][3]);
            }
#pragma unroll
            for (int nt = 0; nt < 4; ++nt) {
                const int rb = (warp_n * 32 + nt * 8 + grp) * GST + kc;
                float b0 = Br[rb];
                float b1 = Br[rb + 4];
                uint32_t bh0, bl0, bh1, bl1;
                SPLIT1(b0, bh0, bl0);
                SPLIT1(b1, bh1, bl1);
#pragma unroll
                for (int mt = 0; mt < 4; ++mt) {
                    MMA_TF32(acc[mt][nt], ah[mt][0], ah[mt][1], ah[mt][2], ah[mt][3], bh0, bh1);
                    MMA_TF32(acc[mt][nt], ah[mt][0], ah[mt][1], ah[mt][2], ah[mt][3], bl0, bl1);
                    MMA_TF32(acc[mt][nt], al[mt][0], al[mt][1], al[mt][2], al[mt][3], bh0, bh1);
                }
            }
        }
        if (c < 63) G3_STORE(smem + ((c + 1) & 1) * (2 * GTILE));
        __syncthreads();
    }
#undef G3_LOAD
#undef G3_STORE
}

// ============================================================
// 1xTF32 GEMM (pre-converted hi in smem)
// ============================================================
__device__ __forceinline__ void gemm_db1(
    const float* __restrict__ A, const float* __restrict__ B,
    int bm, int bn, int aRows, float* __restrict__ smem,
    float acc[4][4][4])
{
    const int tid = threadIdx.x;
    const int wid = tid >> 5, lane = tid & 31;
    const int warp_m = wid & 1, warp_n = wid >> 1;
    const int grp = lane >> 2, tig = lane & 3;
    const int r0 = tid >> 2;
    const int f0 = (tid & 3) * 4;

    float4 pa[2], pb[2];

#define G1_LOAD(k0) do { \
    _Pragma("unroll") \
    for (int t = 0; t < 2; ++t) { \
        const int r = r0 + t * 64; \
        pa[t] = make_float4(0.f, 0.f, 0.f, 0.f); \
        if (bm + r < aRows) \
            pa[t] = *(const float4*)(A + (size_t)(bm + r) * 1024 + (k0) + f0); \
        pb[t] = *(const float4*)(B + (size_t)(bn + r) * 1024 + (k0) + f0); \
    } } while (0)

#define G1_STORE(bufp) do { \
    float* Ah_ = (bufp); \
    float* Bh_ = (bufp) + GTILE; \
    _Pragma("unroll") \
    for (int t = 0; t < 2; ++t) { \
        const int r = r0 + t * 64; \
        float4 hi; \
        hi4(pa[t], hi); *(float4*)(Ah_ + r * GST + f0) = hi; \
        hi4(pb[t], hi); *(float4*)(Bh_ + r * GST + f0) = hi; \
    } } while (0)

    G1_LOAD(0);
    G1_STORE(smem);
    __syncthreads();

    for (int c = 0; c < 64; ++c) {
        float* cur = smem + (c & 1) * (2 * GTILE);
        if (c < 63) G1_LOAD((c + 1) * 16);

        float* Ah = cur;
        float* Bh = cur + GTILE;

#pragma unroll
        for (int ks = 0; ks < 2; ++ks) {
            const int kc = ks * 8 + tig;
            uint32_t ah[4][4];
#pragma unroll
            for (int mt = 0; mt < 4; ++mt) {
                const int ra = (warp_m * 64 + mt * 16 + grp) * GST;
                ah[mt][0] = __float_as_uint(Ah[ra + kc]);
                ah[mt][1] = __float_as_uint(Ah[ra + 8 * GST + kc]);
                ah[mt][2] = __float_as_uint(Ah[ra + kc + 4]);
                ah[mt][3] = __float_as_uint(Ah[ra + 8 * GST + kc + 4]);
            }
#pragma unroll
            for (int nt = 0; nt < 4; ++nt) {
                const int rb = (warp_n * 32 + nt * 8 + grp) * GST + kc;
                uint32_t bh0 = __float_as_uint(Bh[rb]);
                uint32_t bh1 = __float_as_uint(Bh[rb + 4]);
#pragma unroll
                for (int mt = 0; mt < 4; ++mt)
                    MMA_TF32(acc[mt][nt], ah[mt][0], ah[mt][1], ah[mt][2], ah[mt][3], bh0, bh1);
            }
        }
        if (c < 63) G1_STORE(smem + ((c + 1) & 1) * (2 * GTILE));
        __syncthreads();
    }
#undef G1_LOAD
#undef G1_STORE
}

#define GSMEM_B (2 * 2 * GTILE * 4)   // 40960 B

// ---- qkv (q,k columns): 3xTF32 raw ----
__global__ __launch_bounds__(256, 2) void gemm_qk_kern(
    const float* __restrict__ A, const float* __restrict__ B)
{
    const int bm = blockIdx.y * 128;
    const int bn = blockIdx.x * 128;
    float acc[4][4][4];
#pragma unroll
    for (int a = 0; a < 4; a++)
#pragma unroll
        for (int b = 0; b < 4; b++)
#pragma unroll
            for (int cc = 0; cc < 4; cc++) acc[a][b][cc] = 0.0f;

    gemm_db3r(A, B, bm, bn, NSEQ, dynsm, acc);

    const int tid = threadIdx.x;
    const int wid = tid >> 5, lane = tid & 31;
    const int warp_m = wid & 1, warp_n = wid >> 1;
    const int grp = lane >> 2, tig = lane & 3;

    const int s = bn >> 10;
    float* __restrict__ dst = (s == 0) ? g_q : g_k;
    const float scale = (s == 0) ? 0.125f : 1.0f;

#pragma unroll
    for (int mt = 0; mt < 4; ++mt)
#pragma unroll
        for (int half = 0; half < 2; ++half) {
            const int row = bm + warp_m * 64 + mt * 16 + grp + half * 8;
            if (row >= NSEQ) continue;
#pragma unroll
            for (int nt = 0; nt < 4; ++nt) {
                const int col = bn + warp_n * 32 + nt * 8 + tig * 2;
                const int h = (col & 1023) >> 6;
                const int d = col & 63;
                float2 v;
                v.x = acc[mt][nt][half * 2 + 0] * scale;
                v.y = acc[mt][nt][half * 2 + 1] * scale;
                *(float2*)&dst[((size_t)h * NPAD + row) * DH + d] = v;
            }
        }
}

// ---- qkv (v columns): 1xTF32 ----
__global__ __launch_bounds__(256, 2) void gemm_v_kern(
    const float* __restrict__ A, const float* __restrict__ B)
{
    const int bm = blockIdx.y * 128;
    const int bn = 2048 + blockIdx.x * 128;
    float acc[4][4][4];
#pragma unroll
    for (int a = 0; a < 4; a++)
#pragma unroll
        for (int b = 0; b < 4; b++)
#pragma unroll
            for (int cc = 0; cc < 4; cc++) acc[a][b][cc] = 0.0f;

    gemm_db1(A, B, bm, bn, NSEQ, dynsm, acc);

    const int tid = threadIdx.x;
    const int wid = tid >> 5, lane = tid & 31;
    const int warp_m = wid & 1, warp_n = wid >> 1;
    const int grp = lane >> 2, tig = lane & 3;

#pragma unroll
    for (int mt = 0; mt < 4; ++mt)
#pragma unroll
        for (int half = 0; half < 2; ++half) {
            const int row = bm + warp_m * 64 + mt * 16 + grp + half * 8;
            if (row >= NSEQ) continue;
#pragma unroll
            for (int nt = 0; nt < 4; ++nt) {
                const int col = bn + warp_n * 32 + nt * 8 + tig * 2;
                const int h = (col & 1023) >> 6;
                const int d = col & 63;
                float2 v;
                v.x = acc[mt][nt][half * 2 + 0];
                v.y = acc[mt][nt][half * 2 + 1];
                *(float2*)&g_v[((size_t)h * NPAD + row) * DH + d] = v;
            }
        }
}

// ---- proj: 1xTF32 + bias ----
__global__ __launch_bounds__(256, 2) void gemm_proj_kern(
    const float* __restrict__ B, const float* __restrict__ bias,
    float* __restrict__ C)
{
    const int bm = blockIdx.y * 128;
    const int bn = blockIdx.x * 128;
    float acc[4][4][4];
#pragma unroll
    for (int a = 0; a < 4; a++)
#pragma unroll
        for (int b = 0; b < 4; b++)
#pragma unroll
            for (int cc = 0; cc < 4; cc++) acc[a][b][cc] = 0.0f;

    gemm_db1(g_attn, B, bm, bn, NSEQ, dynsm, acc);

    const int tid = threadIdx.x;
    const int wid = tid >> 5, lane = tid & 31;
    const int warp_m = wid & 1, warp_n = wid >> 1;
    const int grp = lane >> 2, tig = lane & 3;

#pragma unroll
    for (int mt = 0; mt < 4; ++mt)
#pragma unroll
        for (int half = 0; half < 2; ++half) {
            const int row = bm + warp_m * 64 + mt * 16 + grp + half * 8;
            if (row >= NSEQ) continue;
#pragma unroll
            for (int nt = 0; nt < 4; ++nt) {
                const int col = bn + warp_n * 32 + nt * 8 + tig * 2;
                float2 v;
                v.x = acc[mt][nt][half * 2 + 0] + bias[col];
                v.y = acc[mt][nt][half * 2 + 1] + bias[col + 1];
                *(float2*)&C[(size_t)row * 1024 + col] = v;
            }
        }
}

// ============================================================
// RoPE on q and k, rows PREFIX..NSEQ-1
// ============================================================
__global__ void rope_kernel(const float* __restrict__ rope)
{
    int idx = blockIdx.x * blockDim.x + threadIdx.x;
    if (idx >= HWLEN * NH * 32) return;
    const int d = idx & 31;
    const int h = (idx >> 5) & 15;
    const int p = idx >> 9;
    const int n = PREFIX + p;

    const float s0 = rope[p * 64 + d];
    const float s1 = rope[p * 64 + d + 32];
    const float c0 = rope[HWLEN * 64 + p * 64 + d];
    const float c1 = rope[HWLEN * 64 + p * 64 + d + 32];

    const size_t base = ((size_t)h * NPAD + n) * DH;

    float q0 = g_q[base + d], q1 = g_q[base + d + 32];
    g_q[base + d]      = q0 * c0 - q1 * s0;
    g_q[base + d + 32] = q1 * c1 + q0 * s1;

    float k0 = g_k[base + d], k1 = g_k[base + d + 32];
    g_k[base + d]      = k0 * c0 - k1 * s0;
    g_k[base + d + 32] = k1 * c1 + k0 * s1;
}

// ============================================================
// Flash attention v4: 128 threads, 4 warps, warp = 16 q-rows x 32 keys.
// Q raw smem (split-at-read); K/V PRE-SPLIT hi/lo at tile store
// (amortized across warps). Register softmax; warp-private P.
// smem 62.5 KB -> 3 CTAs/SM. grid (26, 16).
// ============================================================
#define A_Q  0                      // 64*68  = 4352
#define A_KH 4352                   // 32*68  = 2176
#define A_KL 6528                   // 2176
#define A_VH 8704                   // 32*72  = 2304
#define A_VL 11008                  // 2304
#define A_P  13312                  // 4 * 576 = 2304
#define ATTN_SMEM_BYTES ((13312 + 2304) * 4)   // 62464

__global__ __launch_bounds__(128, 3) void attn_mma4()
{
    float* Qs = dynsm + A_Q;
    float* Kh = dynsm + A_KH;
    float* Kl = dynsm + A_KL;
    float* Vh = dynsm + A_VH;
    float* Vl = dynsm + A_VL;

    const int h  = blockIdx.y;
    const int qb = blockIdx.x * 64;
    const int tid = threadIdx.x;
    const int wid = tid >> 5, lane = tid & 31;
    const int grp = lane >> 2, tig = lane & 3;
    const int row0 = wid * 16;

    float* Pw = dynsm + A_P + wid * 576;

    const float* __restrict__ Qg = g_q + (size_t)h * NPAD * DH;
    const float* __restrict__ Kg = g_k + (size_t)h * NPAD * DH;
    const float* __restrict__ Vg = g_v + (size_t)h * NPAD * DH;

    // ---- prologue: Q tile 64x64 raw ----
#pragma unroll
    for (int t = 0; t < 8; ++t) {
        const int idx = tid + t * 128;
        const int r = idx >> 4, c4 = (idx & 15) * 4;
        *(float4*)(Qs + r * 68 + c4) =
            *(const float4*)(Qg + (size_t)(qb + r) * DH + c4);
    }

    // ---- K/V tile 0: load, split, store hi/lo ----
    const int lr = tid >> 4;              // 0..7, +8 per t
    const int lc4 = (tid & 15) * 4;
    float4 pk[4], pv[4];
#pragma unroll
    for (int t = 0; t < 4; ++t) {
        const int r = lr + t * 8;
        pk[t] = *(const float4*)(Kg + (size_t)r * DH + lc4);
        pv[t] = *(const float4*)(Vg + (size_t)r * DH + lc4);
    }
#pragma unroll
    for (int t = 0; t < 4; ++t) {
        const int r = lr + t * 8;
        float4 hi, lo;
        split4(pk[t], hi, lo);
        *(float4*)(Kh + r * 68 + lc4) = hi;
        *(float4*)(Kl + r * 68 + lc4) = lo;
        split4(pv[t], hi, lo);
        *(float4*)(Vh + r * 72 + lc4) = hi;
        *(float4*)(Vl + r * 72 + lc4) = lo;
    }
    __syncthreads();

    float m0 = -1e38f, m1 = -1e38f, l0 = 0.0f, l1 = 0.0f;
    float o[8][4];
#pragma unroll
    for (int nt = 0; nt < 8; nt++)
#pragma unroll
        for (int i = 0; i < 4; i++) o[nt][i] = 0.0f;

    const int nkt = (NSEQ + 31) / 32;    // 51
    for (int kt = 0; kt < nkt; ++kt) {
        const int key0 = kt * 32;

        // ---- S = Q K^T (3xTF32): Q split-at-read, K pre-split ----
        float sacc[4][4];
#pragma unroll
        for (int nt = 0; nt < 4; nt++)
#pragma unroll
            for (int i = 0; i < 4; i++) sacc[nt][i] = 0.0f;

#pragma unroll
        for (int ks = 0; ks < 8; ++ks) {
            const int k0 = ks * 8;
            uint32_t ah[4], al[4];
            {
                float a0 = Qs[(row0 + grp) * 68 + k0 + tig];
                float a1 = Qs[(row0 + grp + 8) * 68 + k0 + tig];
                float a2 = Qs[(row0 + grp) * 68 + k0 + tig + 4];
                float a3 = Qs[(row0 + grp + 8) * 68 + k0 + tig + 4];
                SPLIT1(a0, ah[0], al[0]);
                SPLIT1(a1, ah[1], al[1]);
                SPLIT1(a2, ah[2], al[2]);
                SPLIT1(a3, ah[3], al[3]);
            }
#pragma unroll
            for (int nt = 0; nt < 4; ++nt) {
                const int rk = (nt * 8 + grp) * 68 + k0 + tig;
                uint32_t bh0 = __float_as_uint(Kh[rk]);
                uint32_t bh1 = __float_as_uint(Kh[rk + 4]);
                uint32_t bl0 = __float_as_uint(Kl[rk]);
                uint32_t bl1 = __float_as_uint(Kl[rk + 4]);
                MMA_TF32(sacc[nt], ah[0], ah[1], ah[2], ah[3], bh0, bh1);
                MMA_TF32(sacc[nt], ah[0], ah[1], ah[2], ah[3], bl0, bl1);
                MMA_TF32(sacc[nt], al[0], al[1], al[2], al[3], bh0, bh1);
            }
        }

        // ---- prefetch next K/V into regs ----
        if (kt + 1 < nkt) {
            const int nk0 = key0 + 32;
#pragma unroll
            for (int t = 0; t < 4; ++t) {
                const int r = nk0 + lr + t * 8;
                pk[t] = *(const float4*)(Kg + (size_t)r * DH + lc4);
                pv[t] = *(const float4*)(Vg + (size_t)r * DH + lc4);
            }
        }

        // ---- register softmax ----
        {
            float mx0 = -1e30f, mx1 = -1e30f;
#pragma unroll
            for (int nt = 0; nt < 4; ++nt) {
                const int c0 = key0 + nt * 8 + tig * 2;
                if (c0 >= NSEQ)     { sacc[nt][0] = -1e30f; sacc[nt][2] = -1e30f; }
                if (c0 + 1 >= NSEQ) { sacc[nt][1] = -1e30f; sacc[nt][3] = -1e30f; }
                mx0 = fmaxf(mx0, fmaxf(sacc[nt][0], sacc[nt][1]));
                mx1 = fmaxf(mx1, fmaxf(sacc[nt][2], sacc[nt][3]));
            }
            mx0 = fmaxf(mx0, __shfl_xor_sync(0xffffffffu, mx0, 1));
            mx0 = fmaxf(mx0, __shfl_xor_sync(0xffffffffu, mx0, 2));
            mx1 = fmaxf(mx1, __shfl_xor_sync(0xffffffffu, mx1, 1));
            mx1 = fmaxf(mx1, __shfl_xor_sync(0xffffffffu, mx1, 2));

            const float mn0 = fmaxf(m0, mx0);
            const float mn1 = fmaxf(m1, mx1);
            const float a0 = __expf(m0 - mn0);
            const float a1 = __expf(m1 - mn1);
            m0 = mn0; m1 = mn1;

            float s0 = 0.0f, s1 = 0.0f;
#pragma unroll
            for (int nt = 0; nt < 4; ++nt) {
                sacc[nt][0] = __expf(sacc[nt][0] - mn0); s0 += sacc[nt][0];
                sacc[nt][1] = __expf(sacc[nt][1] - mn0); s0 += sacc[nt][1];
                sacc[nt][2] = __expf(sacc[nt][2] - mn1); s1 += sacc[nt][2];
                sacc[nt][3] = __expf(sacc[nt][3] - mn1); s1 += sacc[nt][3];
            }
            s0 += __shfl_xor_sync(0xffffffffu, s0, 1);
            s0 += __shfl_xor_sync(0xffffffffu, s0, 2);
            s1 += __shfl_xor_sync(0xffffffffu, s1, 1);
            s1 += __shfl_xor_sync(0xffffffffu, s1, 2);
            l0 = l0 * a0 + s0;
            l1 = l1 * a1 + s1;

#pragma unroll
            for (int nt = 0; nt < 4; ++nt) {
                const int col = nt * 8 + tig * 2;
                *(float2*)(Pw + grp * 36 + col) = make_float2(sacc[nt][0], sacc[nt][1]);
                *(float2*)(Pw + (grp + 8) * 36 + col) = make_float2(sacc[nt][2], sacc[nt][3]);
            }
            __syncwarp();

#pragma unroll
            for (int nt = 0; nt < 8; ++nt) {
                o[nt][0] *= a0; o[nt][1] *= a0;
                o[nt][2] *= a1; o[nt][3] *= a1;
            }
        }

        // ---- O += P V (V pre-split, natural layout, 2-pass) ----
#pragma unroll
        for (int kk = 0; kk < 4; ++kk) {
            const int k0 = kk * 8;
            uint32_t pa0 = f2tf32(Pw[grp * 36 + k0 + tig]);
            uint32_t pa1 = f2tf32(Pw[(grp + 8) * 36 + k0 + tig]);
            uint32_t pa2 = f2tf32(Pw[grp * 36 + k0 + tig + 4]);
            uint32_t pa3 = f2tf32(Pw[(grp + 8) * 36 + k0 + tig + 4]);
#pragma unroll
            for (int nt = 0; nt < 8; ++nt) {
                const int d = nt * 8 + grp;
                uint32_t vh0 = __float_as_uint(Vh[(k0 + tig) * 72 + d]);
                uint32_t vh1 = __float_as_uint(Vh[(k0 + tig + 4) * 72 + d]);
                uint32_t vl0 = __float_as_uint(Vl[(k0 + tig) * 72 + d]);
                uint32_t vl1 = __float_as_uint(Vl[(k0 + tig + 4) * 72 + d]);
                MMA_TF32(o[nt], pa0, pa1, pa2, pa3, vh0, vh1);
                MMA_TF32(o[nt], pa0, pa1, pa2, pa3, vl0, vl1);
            }
        }
        __syncthreads();

        // ---- store prefetched K/V tile (split once, shared) ----
        if (kt + 1 < nkt) {
#pragma unroll
            for (int t = 0; t < 4; ++t) {
                const int r = lr + t * 8;
                float4 hi, lo;
                split4(pk[t], hi, lo);
                *(float4*)(Kh + r * 68 + lc4) = hi;
                *(float4*)(Kl + r * 68 + lc4) = lo;
                split4(pv[t], hi, lo);
                *(float4*)(Vh + r * 72 + lc4) = hi;
                *(float4*)(Vl + r * 72 + lc4) = lo;
            }
            __syncthreads();
        }
    }

    // ---- epilogue: normalize, write g_attn ----
    const float inv0 = 1.0f / l0;
    const float inv1 = 1.0f / l1;
    const int n0 = qb + row0 + grp;
    const int n1 = n0 + 8;
#pragma unroll
    for (int nt = 0; nt < 8; ++nt) {
        const int col = h * DH + nt * 8 + tig * 2;
        if (n0 < NSEQ)
            *(float2*)&g_attn[(size_t)n0 * DIMF + col] =
                make_float2(o[nt][0] * inv0, o[nt][1] * inv0);
        if (n1 < NSEQ)
            *(float2*)&g_attn[(size_t)n1 * DIMF + col] =
                make_float2(o[nt][2] * inv1, o[nt][3] * inv1);
    }
}

// ============================================================
extern "C" void kernel_launch(void* const* d_in, const int* in_sizes, int n_in,
                              void* d_out, int out_size)
{
    (void)in_sizes; (void)n_in; (void)out_size;
    const float* x     = (const float*)d_in[0];
    const float* rope  = (const float*)d_in[1];
    const float* Wqkv  = (const float*)d_in[2];
    const float* Wproj = (const float*)d_in[3];
    const float* bproj = (const float*)d_in[4];
    float* out = (float*)d_out;

    static int configured = 0;
    if (!configured) {
        cudaFuncSetAttribute(gemm_qk_kern,   cudaFuncAttributeMaxDynamicSharedMemorySize, GSMEM_B);
        cudaFuncSetAttribute(gemm_v_kern,    cudaFuncAttributeMaxDynamicSharedMemorySize, GSMEM_B);
        cudaFuncSetAttribute(gemm_proj_kern, cudaFuncAttributeMaxDynamicSharedMemorySize, GSMEM_B);
        cudaFuncSetAttribute(attn_mma4,      cudaFuncAttributeMaxDynamicSharedMemorySize, ATTN_SMEM_BYTES);
        configured = 1;
    }

    gemm_qk_kern<<<dim3(16, 13), 256, GSMEM_B>>>(x, Wqkv);
    gemm_v_kern<<<dim3(8, 13), 256, GSMEM_B>>>(x, Wqkv);
    rope_kernel<<<(HWLEN * NH * 32 + 255) / 256, 256>>>(rope);
    attn_mma4<<<dim3(26, NH), 128, ATTN_SMEM_BYTES>>>();
    gemm_proj_kern<<<dim3(8, 13), 256, GSMEM_B>>>(Wproj, bproj, out);
}

// round 8
// speedup vs baseline: 2.4588x; 1.4070x over previous
#include <cuda_runtime.h>
#include <cstdint>

#define NSEQ   1605
#define DIMF   1024
#define NH     16
#define DH     64
#define HWLEN  1600
#define PREFIX 5
#define NPAD   1664   // 26 * 64

// ---- scratch (device globals; zero-initialized at module load) ----
__device__ float g_q[(size_t)NH * NPAD * DH];
__device__ float g_k[(size_t)NH * NPAD * DH];
__device__ float g_v[(size_t)NH * NPAD * DH];
__device__ float g_attn[(size_t)NSEQ * DIMF];

// ============================================================
// mma helpers
// ============================================================
__device__ __forceinline__ uint32_t f2tf32(float a) {
    uint32_t u; asm("cvt.rna.tf32.f32 %0, %1;" : "=r"(u) : "f"(a));
    return u;
}

#define MMA_TF32(d, a0, a1, a2, a3, b0, b1) \
    asm volatile("mma.sync.aligned.m16n8k8.row.col.f32.tf32.tf32.f32 " \
        "{%0,%1,%2,%3}, {%4,%5,%6,%7}, {%8,%9}, {%0,%1,%2,%3};" \
        : "+f"((d)[0]), "+f"((d)[1]), "+f"((d)[2]), "+f"((d)[3]) \
        : "r"(a0), "r"(a1), "r"(a2), "r"(a3), "r"(b0), "r"(b1))

#define MMA_BF16(d, a0, a1, a2, a3, b0, b1) \
    asm volatile("mma.sync.aligned.m16n8k16.row.col.f32.bf16.bf16.f32 " \
        "{%0,%1,%2,%3}, {%4,%5,%6,%7}, {%8,%9}, {%0,%1,%2,%3};" \
        : "+f"((d)[0]), "+f"((d)[1]), "+f"((d)[2]), "+f"((d)[3]) \
        : "r"(a0), "r"(a1), "r"(a2), "r"(a3), "r"(b0), "r"(b1))

// pack two floats to bf16x2: 'lo' -> bits[0:16), 'hi' -> bits[16:32)
__device__ __forceinline__ uint32_t pack_bf16x2(float lo, float hi) {
    uint32_t w;
    asm("cvt.rn.bf16x2.f32 %0, %1, %2;" : "=r"(w) : "f"(hi), "f"(lo));
    return w;
}
__device__ __forceinline__ float lo_bf16(uint32_t w) { return __uint_as_float(w << 16); }
__device__ __forceinline__ float hi_bf16(uint32_t w) { return __uint_as_float(w & 0xFFFF0000u); }

// split adjacent pair (e=even slot, o=odd slot) into bf16x2 hi-word + lo-word
__device__ __forceinline__ void split2(float e, float o, uint32_t& h, uint32_t& l) {
    h = pack_bf16x2(e, o);
    l = pack_bf16x2(e - lo_bf16(h), o - hi_bf16(h));
}

__device__ __forceinline__ void hi4(const float4 v, float4& hi) {
    hi.x = __uint_as_float(f2tf32(v.x));
    hi.y = __uint_as_float(f2tf32(v.y));
    hi.z = __uint_as_float(f2tf32(v.z));
    hi.w = __uint_as_float(f2tf32(v.w));
}

extern __shared__ float dynsm[];

// ============================================================
// bf16x3 GEMM (qk): packed bf16x2 hi/lo in smem, double-buffered.
// acc += A[bm:+128,0:1024] @ B[bn:+128,0:1024]^T, fp32-grade.
// ============================================================
#define BST 12                       // words per row (8 used + 4 pad)
#define BTILE (128 * BST)            // 1536 words per tile

__device__ __forceinline__ void gemm_db3b(
    const float* __restrict__ A, const float* __restrict__ B,
    int bm, int bn, int aRows, uint32_t* __restrict__ smem,
    float acc[4][4][4])
{
    const int tid = threadIdx.x;
    const int wid = tid >> 5, lane = tid & 31;
    const int warp_m = wid & 1, warp_n = wid >> 1;
    const int grp = lane >> 2, tig = lane & 3;
    const int r0 = tid >> 2;
    const int f0 = (tid & 3) * 4;
    const int w0 = (tid & 3) * 2;

    float4 pa[2], pb[2];

#define GB_LOAD(k0) do { \
    _Pragma("unroll") \
    for (int t = 0; t < 2; ++t) { \
        const int r = r0 + t * 64; \
        pa[t] = make_float4(0.f, 0.f, 0.f, 0.f); \
        if (bm + r < aRows) \
            pa[t] = *(const float4*)(A + (size_t)(bm + r) * 1024 + (k0) + f0); \
        pb[t] = *(const float4*)(B + (size_t)(bn + r) * 1024 + (k0) + f0); \
    } } while (0)

#define GB_STORE(bufp) do { \
    uint32_t* Ah_ = (bufp); \
    uint32_t* Al_ = (bufp) + BTILE; \
    uint32_t* Bh_ = (bufp) + 2 * BTILE; \
    uint32_t* Bl_ = (bufp) + 3 * BTILE; \
    _Pragma("unroll") \
    for (int t = 0; t < 2; ++t) { \
        const int r = r0 + t * 64; \
        uint32_t h0, l0, h1, l1; \
        split2(pa[t].x, pa[t].y, h0, l0); \
        split2(pa[t].z, pa[t].w, h1, l1); \
        Ah_[r * BST + w0] = h0; Ah_[r * BST + w0 + 1] = h1; \
        Al_[r * BST + w0] = l0; Al_[r * BST + w0 + 1] = l1; \
        split2(pb[t].x, pb[t].y, h0, l0); \
        split2(pb[t].z, pb[t].w, h1, l1); \
        Bh_[r * BST + w0] = h0; Bh_[r * BST + w0 + 1] = h1; \
        Bl_[r * BST + w0] = l0; Bl_[r * BST + w0 + 1] = l1; \
    } } while (0)

    GB_LOAD(0);
    GB_STORE(smem);
    __syncthreads();

    for (int c = 0; c < 64; ++c) {
        uint32_t* cur = smem + (c & 1) * (4 * BTILE);
        if (c < 63) GB_LOAD((c + 1) * 16);

        uint32_t* Ah = cur;
        uint32_t* Al = cur + BTILE;
        uint32_t* Bh = cur + 2 * BTILE;
        uint32_t* Bl = cur + 3 * BTILE;

        uint32_t ah[4][4], al[4][4];
#pragma unroll
        for (int mt = 0; mt < 4; ++mt) {
            const int ra = (warp_m * 64 + mt * 16 + grp) * BST;
            ah[mt][0] = Ah[ra + tig];
            ah[mt][1] = Ah[ra + 8 * BST + tig];
            ah[mt][2] = Ah[ra + tig + 4];
            ah[mt][3] = Ah[ra + 8 * BST + tig + 4];
            al[mt][0] = Al[ra + tig];
            al[mt][1] = Al[ra + 8 * BST + tig];
            al[mt][2] = Al[ra + tig + 4];
            al[mt][3] = Al[ra + 8 * BST + tig + 4];
        }
#pragma unroll
        for (int nt = 0; nt < 4; ++nt) {
            const int rb = (warp_n * 32 + nt * 8 + grp) * BST;
            uint32_t bh0 = Bh[rb + tig];
            uint32_t bh1 = Bh[rb + tig + 4];
            uint32_t bl0 = Bl[rb + tig];
            uint32_t bl1 = Bl[rb + tig + 4];
#pragma unroll
            for (int mt = 0; mt < 4; ++mt) {
                MMA_BF16(acc[mt][nt], ah[mt][0], ah[mt][1], ah[mt][2], ah[mt][3], bh0, bh1);
                MMA_BF16(acc[mt][nt], ah[mt][0], ah[mt][1], ah[mt][2], ah[mt][3], bl0, bl1);
                MMA_BF16(acc[mt][nt], al[mt][0], al[mt][1], al[mt][2], al[mt][3], bh0, bh1);
            }
        }
        if (c < 63) GB_STORE(smem + ((c + 1) & 1) * (4 * BTILE));
        __syncthreads();
    }
#undef GB_LOAD
#undef GB_STORE
}

#define GSMEM_QK (2 * 4 * BTILE * 4)   // 49152 B

// ============================================================
// 1xTF32 GEMM (pre-converted hi in smem) — v and proj
// ============================================================
#define GST 20
#define GTILE (128 * GST)

__device__ __forceinline__ void gemm_db1(
    const float* __restrict__ A, const float* __restrict__ B,
    int bm, int bn, int aRows, float* __restrict__ smem,
    float acc[4][4][4])
{
    const int tid = threadIdx.x;
    const int wid = tid >> 5, lane = tid & 31;
    const int warp_m = wid & 1, warp_n = wid >> 1;
    const int grp = lane >> 2, tig = lane & 3;
    const int r0 = tid >> 2;
    const int f0 = (tid & 3) * 4;

    float4 pa[2], pb[2];

#define G1_LOAD(k0) do { \
    _Pragma("unroll") \
    for (int t = 0; t < 2; ++t) { \
        const int r = r0 + t * 64; \
        pa[t] = make_float4(0.f, 0.f, 0.f, 0.f); \
        if (bm + r < aRows) \
            pa[t] = *(const float4*)(A + (size_t)(bm + r) * 1024 + (k0) + f0); \
        pb[t] = *(const float4*)(B + (size_t)(bn + r) * 1024 + (k0) + f0); \
    } } while (0)

#define G1_STORE(bufp) do { \
    float* Ah_ = (bufp); \
    float* Bh_ = (bufp) + GTILE; \
    _Pragma("unroll") \
    for (int t = 0; t < 2; ++t) { \
        const int r = r0 + t * 64; \
        float4 hi; \
        hi4(pa[t], hi); *(float4*)(Ah_ + r * GST + f0) = hi; \
        hi4(pb[t], hi); *(float4*)(Bh_ + r * GST + f0) = hi; \
    } } while (0)

    G1_LOAD(0);
    G1_STORE(smem);
    __syncthreads();

    for (int c = 0; c < 64; ++c) {
        float* cur = smem + (c & 1) * (2 * GTILE);
        if (c < 63) G1_LOAD((c + 1) * 16);

        float* Ah = cur;
        float* Bh = cur + GTILE;

#pragma unroll
        for (int ks = 0; ks < 2; ++ks) {
            const int kc = ks * 8 + tig;
            uint32_t ah[4][4];
#pragma unroll
            for (int mt = 0; mt < 4; ++mt) {
                const int ra = (warp_m * 64 + mt * 16 + grp) * GST;
                ah[mt][0] = __float_as_uint(Ah[ra + kc]);
                ah[mt][1] = __float_as_uint(Ah[ra + 8 * GST + kc]);
                ah[mt][2] = __float_as_uint(Ah[ra + kc + 4]);
                ah[mt][3] = __float_as_uint(Ah[ra + 8 * GST + kc + 4]);
            }
#pragma unroll
            for (int nt = 0; nt < 4; ++nt) {
                const int rb = (warp_n * 32 + nt * 8 + grp) * GST + kc;
                uint32_t bh0 = __float_as_uint(Bh[rb]);
                uint32_t bh1 = __float_as_uint(Bh[rb + 4]);
#pragma unroll
                for (int mt = 0; mt < 4; ++mt)
                    MMA_TF32(acc[mt][nt], ah[mt][0], ah[mt][1], ah[mt][2], ah[mt][3], bh0, bh1);
            }
        }
        if (c < 63) G1_STORE(smem + ((c + 1) & 1) * (2 * GTILE));
        __syncthreads();
    }
#undef G1_LOAD
#undef G1_STORE
}

#define GSMEM_B (2 * 2 * GTILE * 4)   // 40960 B

// ---- qkv (q,k columns): bf16x3 ----
__global__ __launch_bounds__(256, 2) void gemm_qk_kern(
    const float* __restrict__ A, const float* __restrict__ B)
{
    const int bm = blockIdx.y * 128;
    const int bn = blockIdx.x * 128;
    float acc[4][4][4];
#pragma unroll
    for (int a = 0; a < 4; a++)
#pragma unroll
        for (int b = 0; b < 4; b++)
#pragma unroll
            for (int cc = 0; cc < 4; cc++) acc[a][b][cc] = 0.0f;

    gemm_db3b(A, B, bm, bn, NSEQ, (uint32_t*)dynsm, acc);

    const int tid = threadIdx.x;
    const int wid = tid >> 5, lane = tid & 31;
    const int warp_m = wid & 1, warp_n = wid >> 1;
    const int grp = lane >> 2, tig = lane & 3;

    const int s = bn >> 10;
    float* __restrict__ dst = (s == 0) ? g_q : g_k;
    const float scale = (s == 0) ? 0.125f : 1.0f;

#pragma unroll
    for (int mt = 0; mt < 4; ++mt)
#pragma unroll
        for (int half = 0; half < 2; ++half) {
            const int row = bm + warp_m * 64 + mt * 16 + grp + half * 8;
            if (row >= NSEQ) continue;
#pragma unroll
            for (int nt = 0; nt < 4; ++nt) {
                const int col = bn + warp_n * 32 + nt * 8 + tig * 2;
                const int h = (col & 1023) >> 6;
                const int d = col & 63;
                float2 v;
                v.x = acc[mt][nt][half * 2 + 0] * scale;
                v.y = acc[mt][nt][half * 2 + 1] * scale;
                *(float2*)&dst[((size_t)h * NPAD + row) * DH + d] = v;
            }
        }
}

// ---- qkv (v columns): 1xTF32 ----
__global__ __launch_bounds__(256, 2) void gemm_v_kern(
    const float* __restrict__ A, const float* __restrict__ B)
{
    const int bm = blockIdx.y * 128;
    const int bn = 2048 + blockIdx.x * 128;
    float acc[4][4][4];
#pragma unroll
    for (int a = 0; a < 4; a++)
#pragma unroll
        for (int b = 0; b < 4; b++)
#pragma unroll
            for (int cc = 0; cc < 4; cc++) acc[a][b][cc] = 0.0f;

    gemm_db1(A, B, bm, bn, NSEQ, dynsm, acc);

    const int tid = threadIdx.x;
    const int wid = tid >> 5, lane = tid & 31;
    const int warp_m = wid & 1, warp_n = wid >> 1;
    const int grp = lane >> 2, tig = lane & 3;

#pragma unroll
    for (int mt = 0; mt < 4; ++mt)
#pragma unroll
        for (int half = 0; half < 2; ++half) {
            const int row = bm + warp_m * 64 + mt * 16 + grp + half * 8;
            if (row >= NSEQ) continue;
#pragma unroll
            for (int nt = 0; nt < 4; ++nt) {
                const int col = bn + warp_n * 32 + nt * 8 + tig * 2;
                const int h = (col & 1023) >> 6;
                const int d = col & 63;
                float2 v;
                v.x = acc[mt][nt][half * 2 + 0];
                v.y = acc[mt][nt][half * 2 + 1];
                *(float2*)&g_v[((size_t)h * NPAD + row) * DH + d] = v;
            }
        }
}

// ---- proj: 1xTF32 + bias ----
__global__ __launch_bounds__(256, 2) void gemm_proj_kern(
    const float* __restrict__ B, const float* __restrict__ bias,
    float* __restrict__ C)
{
    const int bm = blockIdx.y * 128;
    const int bn = blockIdx.x * 128;
    float acc[4][4][4];
#pragma unroll
    for (int a = 0; a < 4; a++)
#pragma unroll
        for (int b = 0; b < 4; b++)
#pragma unroll
            for (int cc = 0; cc < 4; cc++) acc[a][b][cc] = 0.0f;

    gemm_db1(g_attn, B, bm, bn, NSEQ, dynsm, acc);

    const int tid = threadIdx.x;
    const int wid = tid >> 5, lane = tid & 31;
    const int warp_m = wid & 1, warp_n = wid >> 1;
    const int grp = lane >> 2, tig = lane & 3;

#pragma unroll
    for (int mt = 0; mt < 4; ++mt)
#pragma unroll
        for (int half = 0; half < 2; ++half) {
            const int row = bm + warp_m * 64 + mt * 16 + grp + half * 8;
            if (row >= NSEQ) continue;
#pragma unroll
            for (int nt = 0; nt < 4; ++nt) {
                const int col = bn + warp_n * 32 + nt * 8 + tig * 2;
                float2 v;
                v.x = acc[mt][nt][half * 2 + 0] + bias[col];
                v.y = acc[mt][nt][half * 2 + 1] + bias[col + 1];
                *(float2*)&C[(size_t)row * 1024 + col] = v;
            }
        }
}

// ============================================================
// RoPE on q and k, rows PREFIX..NSEQ-1
// ============================================================
__global__ void rope_kernel(const float* __restrict__ rope)
{
    int idx = blockIdx.x * blockDim.x + threadIdx.x;
    if (idx >= HWLEN * NH * 32) return;
    const int d = idx & 31;
    const int h = (idx >> 5) & 15;
    const int p = idx >> 9;
    const int n = PREFIX + p;

    const float s0 = rope[p * 64 + d];
    const float s1 = rope[p * 64 + d + 32];
    const float c0 = rope[HWLEN * 64 + p * 64 + d];
    const float c1 = rope[HWLEN * 64 + p * 64 + d + 32];

    const size_t base = ((size_t)h * NPAD + n) * DH;

    float q0 = g_q[base + d], q1 = g_q[base + d + 32];
    g_q[base + d]      = q0 * c0 - q1 * s0;
    g_q[base + d + 32] = q1 * c1 + q0 * s1;

    float k0 = g_k[base + d], k1 = g_k[base + d + 32];
    g_k[base + d]      = k0 * c0 - k1 * s0;
    g_k[base + d + 32] = k1 * c1 + k0 * s1;
}

// ============================================================
// Flash attention v5 (bf16x3): 128 threads, 4 warps,
// warp = 16 q-rows x 32 keys. Everything packed bf16x2 hi/lo.
// smem ~47 KB. grid (26, 16).
// ============================================================
#define AQ_H 0                       // 64*36 = 2304 words
#define AQ_L 2304
#define AK_H 4608                    // 32*36 = 1152
#define AK_L 5760
#define AV_H 6912                    // 64*20 = 1280
#define AV_L 8192
#define AP   9472                    // 4 warps * (320 h + 320 l)
#define ATTN_SMEM_BYTES (12032 * 4)  // 48128 B

__global__ __launch_bounds__(128, 3) void attn_bf16()
{
    uint32_t* usm = (uint32_t*)dynsm;
    uint32_t* Qh = usm + AQ_H;
    uint32_t* Ql = usm + AQ_L;
    uint32_t* Kh = usm + AK_H;
    uint32_t* Kl = usm + AK_L;
    uint32_t* Vh = usm + AV_H;
    uint32_t* Vl = usm + AV_L;

    const int h  = blockIdx.y;
    const int qb = blockIdx.x * 64;
    const int tid = threadIdx.x;
    const int wid = tid >> 5, lane = tid & 31;
    const int grp = lane >> 2, tig = lane & 3;
    const int row0 = wid * 16;

    uint32_t* Ph = usm + AP + wid * 640;
    uint32_t* Pl = Ph + 320;

    const float* __restrict__ Qg = g_q + (size_t)h * NPAD * DH;
    const float* __restrict__ Kg = g_k + (size_t)h * NPAD * DH;
    const float* __restrict__ Vg = g_v + (size_t)h * NPAD * DH;

    // ---- prologue: Q tile 64x64 -> packed bf16x2 hi/lo ----
#pragma unroll
    for (int t = 0; t < 8; ++t) {
        const int idx = tid + t * 128;
        const int r = idx >> 4, c4 = (idx & 15) * 4;
        float4 v = *(const float4*)(Qg + (size_t)(qb + r) * DH + c4);
        uint32_t h0, l0, h1, l1;
        split2(v.x, v.y, h0, l0);
        split2(v.z, v.w, h1, l1);
        Qh[r * 36 + c4 / 2] = h0; Qh[r * 36 + c4 / 2 + 1] = h1;
        Ql[r * 36 + c4 / 2] = l0; Ql[r * 36 + c4 / 2 + 1] = l1;
    }

    // ---- K/V tile 0 ----
    const int lr = tid >> 4;              // 0..7 (+8 per t) for K
    const int lc4 = (tid & 15) * 4;
    const int vp = tid & 15;              // V key-pair
    const int vdg = tid >> 4;             // V d-group (0..7)
    float4 pk[4];                         // K rows
    float4 ve0, ve1, vo0, vo1;            // V even/odd key rows

#define KV_FETCH(base) do { \
    _Pragma("unroll") \
    for (int t = 0; t < 4; ++t) \
        pk[t] = *(const float4*)(Kg + (size_t)((base) + lr + t * 8) * DH + lc4); \
    ve0 = *(const float4*)(Vg + (size_t)((base) + 2 * vp) * DH + vdg * 8); \
    ve1 = *(const float4*)(Vg + (size_t)((base) + 2 * vp) * DH + vdg * 8 + 4); \
    vo0 = *(const float4*)(Vg + (size_t)((base) + 2 * vp + 1) * DH + vdg * 8); \
    vo1 = *(const float4*)(Vg + (size_t)((base) + 2 * vp + 1) * DH + vdg * 8 + 4); \
} while (0)

#define KV_STORE() do { \
    _Pragma("unroll") \
    for (int t = 0; t < 4; ++t) { \
        const int r = lr + t * 8; \
        uint32_t h0, l0, h1, l1; \
        split2(pk[t].x, pk[t].y, h0, l0); \
        split2(pk[t].z, pk[t].w, h1, l1); \
        Kh[r * 36 + lc4 / 2] = h0; Kh[r * 36 + lc4 / 2 + 1] = h1; \
        Kl[r * 36 + lc4 / 2] = l0; Kl[r * 36 + lc4 / 2 + 1] = l1; \
    } \
    { \
        float ve[8] = {ve0.x, ve0.y, ve0.z, ve0.w, ve1.x, ve1.y, ve1.z, ve1.w}; \
        float vo[8] = {vo0.x, vo0.y, vo0.z, vo0.w, vo1.x, vo1.y, vo1.z, vo1.w}; \
        _Pragma("unroll") \
        for (int j = 0; j < 8; ++j) { \
            const int d = vdg * 8 + j; \
            uint32_t hh, ll; \
            split2(ve[j], vo[j], hh, ll); \
            Vh[d * 20 + vp] = hh; \
            Vl[d * 20 + vp] = ll; \
        } \
    } \
} while (0)

    KV_FETCH(0);
    KV_STORE();
    __syncthreads();

    float m0 = -1e38f, m1 = -1e38f, l0s = 0.0f, l1s = 0.0f;
    float o[8][4];
#pragma unroll
    for (int nt = 0; nt < 8; nt++)
#pragma unroll
        for (int i = 0; i < 4; i++) o[nt][i] = 0.0f;

    const int nkt = (NSEQ + 31) / 32;    // 51
    for (int kt = 0; kt < nkt; ++kt) {
        const int key0 = kt * 32;

        // ---- S = Q K^T (bf16x3) ----
        float sacc[4][4];
#pragma unroll
        for (int nt = 0; nt < 4; nt++)
#pragma unroll
            for (int i = 0; i < 4; i++) sacc[nt][i] = 0.0f;

#pragma unroll
        for (int ks = 0; ks < 4; ++ks) {
            const int kw = ks * 8;
            const int ra = (row0 + grp) * 36 + kw;
            const int rb = (row0 + grp + 8) * 36 + kw;
            uint32_t ah0 = Qh[ra + tig], ah1 = Qh[rb + tig];
            uint32_t ah2 = Qh[ra + tig + 4], ah3 = Qh[rb + tig + 4];
            uint32_t al0 = Ql[ra + tig], al1 = Ql[rb + tig];
            uint32_t al2 = Ql[ra + tig + 4], al3 = Ql[rb + tig + 4];
#pragma unroll
            for (int nt = 0; nt < 4; ++nt) {
                const int kb = (nt * 8 + grp) * 36 + kw;
                uint32_t bh0 = Kh[kb + tig], bh1 = Kh[kb + tig + 4];
                uint32_t bl0 = Kl[kb + tig], bl1 = Kl[kb + tig + 4];
                MMA_BF16(sacc[nt], ah0, ah1, ah2, ah3, bh0, bh1);
                MMA_BF16(sacc[nt], ah0, ah1, ah2, ah3, bl0, bl1);
                MMA_BF16(sacc[nt], al0, al1, al2, al3, bh0, bh1);
            }
        }

        // ---- prefetch next K/V into regs ----
        if (kt + 1 < nkt) KV_FETCH(key0 + 32);

        // ---- register softmax ----
        {
            float mx0 = -1e30f, mx1 = -1e30f;
#pragma unroll
            for (int nt = 0; nt < 4; ++nt) {
                const int c0 = key0 + nt * 8 + tig * 2;
                if (c0 >= NSEQ)     { sacc[nt][0] = -1e30f; sacc[nt][2] = -1e30f; }
                if (c0 + 1 >= NSEQ) { sacc[nt][1] = -1e30f; sacc[nt][3] = -1e30f; }
                mx0 = fmaxf(mx0, fmaxf(sacc[nt][0], sacc[nt][1]));
                mx1 = fmaxf(mx1, fmaxf(sacc[nt][2], sacc[nt][3]));
            }
            mx0 = fmaxf(mx0, __shfl_xor_sync(0xffffffffu, mx0, 1));
            mx0 = fmaxf(mx0, __shfl_xor_sync(0xffffffffu, mx0, 2));
            mx1 = fmaxf(mx1, __shfl_xor_sync(0xffffffffu, mx1, 1));
            mx1 = fmaxf(mx1, __shfl_xor_sync(0xffffffffu, mx1, 2));

            const float mn0 = fmaxf(m0, mx0);
            const float mn1 = fmaxf(m1, mx1);
            const float a0 = __expf(m0 - mn0);
            const float a1 = __expf(m1 - mn1);
            m0 = mn0; m1 = mn1;

            float s0 = 0.0f, s1 = 0.0f;
#pragma unroll
            for (int nt = 0; nt < 4; ++nt) {
                sacc[nt][0] = __expf(sacc[nt][0] - mn0); s0 += sacc[nt][0];
                sacc[nt][1] = __expf(sacc[nt][1] - mn0); s0 += sacc[nt][1];
                sacc[nt][2] = __expf(sacc[nt][2] - mn1); s1 += sacc[nt][2];
                sacc[nt][3] = __expf(sacc[nt][3] - mn1); s1 += sacc[nt][3];
            }
            s0 += __shfl_xor_sync(0xffffffffu, s0, 1);
            s0 += __shfl_xor_sync(0xffffffffu, s0, 2);
            s1 += __shfl_xor_sync(0xffffffffu, s1, 1);
            s1 += __shfl_xor_sync(0xffffffffu, s1, 2);
            l0s = l0s * a0 + s0;
            l1s = l1s * a1 + s1;

            // pack P hi/lo straight from registers
#pragma unroll
            for (int nt = 0; nt < 4; ++nt) {
                const int cw = nt * 4 + tig;
                uint32_t hh, ll;
                split2(sacc[nt][0], sacc[nt][1], hh, ll);
                Ph[grp * 20 + cw] = hh; Pl[grp * 20 + cw] = ll;
                split2(sacc[nt][2], sacc[nt][3], hh, ll);
                Ph[(grp + 8) * 20 + cw] = hh; Pl[(grp + 8) * 20 + cw] = ll;
            }
            __syncwarp();

#pragma unroll
            for (int nt = 0; nt < 8; ++nt) {
                o[nt][0] *= a0; o[nt][1] *= a0;
                o[nt][2] *= a1; o[nt][3] *= a1;
            }
        }

        // ---- O += P V (bf16x3) ----
#pragma unroll
        for (int kk = 0; kk < 2; ++kk) {
            const int kw = kk * 8;
            uint32_t ph0 = Ph[grp * 20 + kw + tig];
            uint32_t ph1 = Ph[(grp + 8) * 20 + kw + tig];
            uint32_t ph2 = Ph[grp * 20 + kw + tig + 4];
            uint32_t ph3 = Ph[(grp + 8) * 20 + kw + tig + 4];
            uint32_t pl0 = Pl[grp * 20 + kw + tig];
            uint32_t pl1 = Pl[(grp + 8) * 20 + kw + tig];
            uint32_t pl2 = Pl[grp * 20 + kw + tig + 4];
            uint32_t pl3 = Pl[(grp + 8) * 20 + kw + tig + 4];
#pragma unroll
            for (int nt = 0; nt < 8; ++nt) {
                const int d = nt * 8 + grp;
                uint32_t vh0 = Vh[d * 20 + kw + tig];
                uint32_t vh1 = Vh[d * 20 + kw + tig + 4];
                uint32_t vl0 = Vl[d * 20 + kw + tig];
                uint32_t vl1 = Vl[d * 20 + kw + tig + 4];
                MMA_BF16(o[nt], ph0, ph1, ph2, ph3, vh0, vh1);
                MMA_BF16(o[nt], ph0, ph1, ph2, ph3, vl0, vl1);
                MMA_BF16(o[nt], pl0, pl1, pl2, pl3, vh0, vh1);
            }
        }
        __syncthreads();

        // ---- store prefetched K/V tile (split once, shared) ----
        if (kt + 1 < nkt) {
            KV_STORE();
            __syncthreads();
        }
    }

    // ---- epilogue ----
    const float inv0 = 1.0f / l0s;
    const float inv1 = 1.0f / l1s;
    const int n0 = qb + row0 + grp;
    const int n1 = n0 + 8;
#pragma unroll
    for (int nt = 0; nt < 8; ++nt) {
        const int col = h * DH + nt * 8 + tig * 2;
        if (n0 < NSEQ)
            *(float2*)&g_attn[(size_t)n0 * DIMF + col] =
                make_float2(o[nt][0] * inv0, o[nt][1] * inv0);
        if (n1 < NSEQ)
            *(float2*)&g_attn[(size_t)n1 * DIMF + col] =
                make_float2(o[nt][2] * inv1, o[nt][3] * inv1);
    }
}

// ============================================================
extern "C" void kernel_launch(void* const* d_in, const int* in_sizes, int n_in,
                              void* d_out, int out_size)
{
    (void)in_sizes; (void)n_in; (void)out_size;
    const float* x     = (const float*)d_in[0];
    const float* rope  = (const float*)d_in[1];
    const float* Wqkv  = (const float*)d_in[2];
    const float* Wproj = (const float*)d_in[3];
    const float* bproj = (const float*)d_in[4];
    float* out = (float*)d_out;

    static int configured = 0;
    if (!configured) {
        cudaFuncSetAttribute(gemm_qk_kern,   cudaFuncAttributeMaxDynamicSharedMemorySize, GSMEM_QK);
        cudaFuncSetAttribute(gemm_v_kern,    cudaFuncAttributeMaxDynamicSharedMemorySize, GSMEM_B);
        cudaFuncSetAttribute(gemm_proj_kern, cudaFuncAttributeMaxDynamicSharedMemorySize, GSMEM_B);
        cudaFuncSetAttribute(attn_bf16,      cudaFuncAttributeMaxDynamicSharedMemorySize, ATTN_SMEM_BYTES);
        configured = 1;
    }

    gemm_qk_kern<<<dim3(16, 13), 256, GSMEM_QK>>>(x, Wqkv);
    gemm_v_kern<<<dim3(8, 13), 256, GSMEM_B>>>(x, Wqkv);
    rope_kernel<<<(HWLEN * NH * 32 + 255) / 256, 256>>>(rope);
    attn_bf16<<<dim3(26, NH), 128, ATTN_SMEM_BYTES>>>();
    gemm_proj_kern<<<dim3(8, 13), 256, GSMEM_B>>>(Wproj, bproj, out);
}

// round 9
// speedup vs baseline: 2.7261x; 1.1087x over previous
#include <cuda_runtime.h>
#include <cstdint>

#define NSEQ   1605
#define DIMF   1024
#define NH     16
#define DH     64
#define HWLEN  1600
#define PREFIX 5
#define NPAD   1664   // 26 * 64

// ---- scratch (device globals; zero-initialized at module load) ----
__device__ float g_q[(size_t)NH * NPAD * DH];
__device__ float g_k[(size_t)NH * NPAD * DH];
__device__ float g_v[(size_t)NH * NPAD * DH];
__device__ float g_attn[(size_t)NSEQ * DIMF];

// ============================================================
// mma / ldmatrix helpers
// ============================================================
__device__ __forceinline__ uint32_t f2tf32(float a) {
    uint32_t u; asm("cvt.rna.tf32.f32 %0, %1;" : "=r"(u) : "f"(a));
    return u;
}
__device__ __forceinline__ uint32_t cvta_s(const void* p) {
    uint32_t a;
    asm("{ .reg .u64 t; cvta.to.shared.u64 t, %1; cvt.u32.u64 %0, t; }"
        : "=r"(a) : "l"(p));
    return a;
}

#define MMA_TF32(d, a0, a1, a2, a3, b0, b1) \
    asm volatile("mma.sync.aligned.m16n8k8.row.col.f32.tf32.tf32.f32 " \
        "{%0,%1,%2,%3}, {%4,%5,%6,%7}, {%8,%9}, {%0,%1,%2,%3};" \
        : "+f"((d)[0]), "+f"((d)[1]), "+f"((d)[2]), "+f"((d)[3]) \
        : "r"(a0), "r"(a1), "r"(a2), "r"(a3), "r"(b0), "r"(b1))

#define MMA_BF16(d, a0, a1, a2, a3, b0, b1) \
    asm volatile("mma.sync.aligned.m16n8k16.row.col.f32.bf16.bf16.f32 " \
        "{%0,%1,%2,%3}, {%4,%5,%6,%7}, {%8,%9}, {%0,%1,%2,%3};" \
        : "+f"((d)[0]), "+f"((d)[1]), "+f"((d)[2]), "+f"((d)[3]) \
        : "r"(a0), "r"(a1), "r"(a2), "r"(a3), "r"(b0), "r"(b1))

#define LDSM_X4(r0, r1, r2, r3, addr) \
    asm volatile("ldmatrix.sync.aligned.m8n8.x4.shared.b16 {%0,%1,%2,%3}, [%4];" \
        : "=r"(r0), "=r"(r1), "=r"(r2), "=r"(r3) : "r"(addr))

// pack two floats to bf16x2: 'e' -> bits[0:16), 'o' -> bits[16:32)
__device__ __forceinline__ uint32_t pack_bf16x2(float lo, float hi) {
    uint32_t w;
    asm("cvt.rn.bf16x2.f32 %0, %1, %2;" : "=r"(w) : "f"(hi), "f"(lo));
    return w;
}
__device__ __forceinline__ float lo_bf16(uint32_t w) { return __uint_as_float(w << 16); }
__device__ __forceinline__ float hi_bf16(uint32_t w) { return __uint_as_float(w & 0xFFFF0000u); }

__device__ __forceinline__ void split2(float e, float o, uint32_t& h, uint32_t& l) {
    h = pack_bf16x2(e, o);
    l = pack_bf16x2(e - lo_bf16(h), o - hi_bf16(h));
}

__device__ __forceinline__ void hi4(const float4 v, float4& hi) {
    hi.x = __uint_as_float(f2tf32(v.x));
    hi.y = __uint_as_float(f2tf32(v.y));
    hi.z = __uint_as_float(f2tf32(v.z));
    hi.w = __uint_as_float(f2tf32(v.w));
}

extern __shared__ float dynsm[];

// ============================================================
// bf16x3 GEMM (qk): packed bf16x2 hi/lo smem, double-buffered,
// ldmatrix fragment loads.
// ============================================================
#define BST 12                       // words per row (8 used + 4 pad)
#define BTILE (128 * BST)            // 1536 words per tile

__device__ __forceinline__ void gemm_db3b(
    const float* __restrict__ A, const float* __restrict__ B,
    int bm, int bn, int aRows, uint32_t* __restrict__ smem,
    float acc[4][4][4])
{
    const int tid = threadIdx.x;
    const int wid = tid >> 5, lane = tid & 31;
    const int warp_m = wid & 1, warp_n = wid >> 1;
    const int r0 = tid >> 2;
    const int f0 = (tid & 3) * 4;
    const int w0 = (tid & 3) * 2;

    const uint32_t smb = cvta_s(smem);
    // ldmatrix word-index bases (within one buffer)
    const int a_lm = (warp_m * 64 + (lane & 15)) * BST + (lane >> 4) * 4;
    const int b_lm = (warp_n * 32 + (lane >> 4) * 8 + (lane & 7)) * BST
                     + ((lane >> 3) & 1) * 4;

    float4 pa[2], pb[2];

#define GB_LOAD(k0) do { \
    _Pragma("unroll") \
    for (int t = 0; t < 2; ++t) { \
        const int r = r0 + t * 64; \
        pa[t] = make_float4(0.f, 0.f, 0.f, 0.f); \
        if (bm + r < aRows) \
            pa[t] = *(const float4*)(A + (size_t)(bm + r) * 1024 + (k0) + f0); \
        pb[t] = *(const float4*)(B + (size_t)(bn + r) * 1024 + (k0) + f0); \
    } } while (0)

#define GB_STORE(bufp) do { \
    uint32_t* Ah_ = (bufp); \
    uint32_t* Al_ = (bufp) + BTILE; \
    uint32_t* Bh_ = (bufp) + 2 * BTILE; \
    uint32_t* Bl_ = (bufp) + 3 * BTILE; \
    _Pragma("unroll") \
    for (int t = 0; t < 2; ++t) { \
        const int r = r0 + t * 64; \
        uint32_t h0, l0, h1, l1; \
        split2(pa[t].x, pa[t].y, h0, l0); \
        split2(pa[t].z, pa[t].w, h1, l1); \
        Ah_[r * BST + w0] = h0; Ah_[r * BST + w0 + 1] = h1; \
        Al_[r * BST + w0] = l0; Al_[r * BST + w0 + 1] = l1; \
        split2(pb[t].x, pb[t].y, h0, l0); \
        split2(pb[t].z, pb[t].w, h1, l1); \
        Bh_[r * BST + w0] = h0; Bh_[r * BST + w0 + 1] = h1; \
        Bl_[r * BST + w0] = l0; Bl_[r * BST + w0 + 1] = l1; \
    } } while (0)

    GB_LOAD(0);
    GB_STORE(smem);
    __syncthreads();

    for (int c = 0; c < 64; ++c) {
        const int bufw = (c & 1) * (4 * BTILE);
        if (c < 63) GB_LOAD((c + 1) * 16);

        uint32_t ah[4][4], al[4][4];
#pragma unroll
        for (int mt = 0; mt < 4; ++mt) {
            LDSM_X4(ah[mt][0], ah[mt][1], ah[mt][2], ah[mt][3],
                    smb + (uint32_t)(bufw + a_lm + mt * 16 * BST) * 4u);
            LDSM_X4(al[mt][0], al[mt][1], al[mt][2], al[mt][3],
                    smb + (uint32_t)(bufw + BTILE + a_lm + mt * 16 * BST) * 4u);
        }
#pragma unroll
        for (int ntp = 0; ntp < 2; ++ntp) {
            uint32_t bh0, bh1, bh2, bh3, bl0, bl1, bl2, bl3;
            LDSM_X4(bh0, bh1, bh2, bh3,
                    smb + (uint32_t)(bufw + 2 * BTILE + b_lm + ntp * 16 * BST) * 4u);
            LDSM_X4(bl0, bl1, bl2, bl3,
                    smb + (uint32_t)(bufw + 3 * BTILE + b_lm + ntp * 16 * BST) * 4u);
#pragma unroll
            for (int mt = 0; mt < 4; ++mt) {
                MMA_BF16(acc[mt][2 * ntp], ah[mt][0], ah[mt][1], ah[mt][2], ah[mt][3], bh0, bh1);
                MMA_BF16(acc[mt][2 * ntp], ah[mt][0], ah[mt][1], ah[mt][2], ah[mt][3], bl0, bl1);
                MMA_BF16(acc[mt][2 * ntp], al[mt][0], al[mt][1], al[mt][2], al[mt][3], bh0, bh1);
                MMA_BF16(acc[mt][2 * ntp + 1], ah[mt][0], ah[mt][1], ah[mt][2], ah[mt][3], bh2, bh3);
                MMA_BF16(acc[mt][2 * ntp + 1], ah[mt][0], ah[mt][1], ah[mt][2], ah[mt][3], bl2, bl3);
                MMA_BF16(acc[mt][2 * ntp + 1], al[mt][0], al[mt][1], al[mt][2], al[mt][3], bh2, bh3);
            }
        }
        if (c < 63) GB_STORE(smem + ((c + 1) & 1) * (4 * BTILE));
        __syncthreads();
    }
#undef GB_LOAD
#undef GB_STORE
}

#define GSMEM_QK (2 * 4 * BTILE * 4)   // 49152 B

// ============================================================
// 1xTF32 GEMM (pre-converted hi in smem) — v and proj
// ============================================================
#define GST 20
#define GTILE (128 * GST)

__device__ __forceinline__ void gemm_db1(
    const float* __restrict__ A, const float* __restrict__ B,
    int bm, int bn, int aRows, float* __restrict__ smem,
    float acc[4][4][4])
{
    const int tid = threadIdx.x;
    const int wid = tid >> 5, lane = tid & 31;
    const int warp_m = wid & 1, warp_n = wid >> 1;
    const int grp = lane >> 2, tig = lane & 3;
    const int r0 = tid >> 2;
    const int f0 = (tid & 3) * 4;

    float4 pa[2], pb[2];

#define G1_LOAD(k0) do { \
    _Pragma("unroll") \
    for (int t = 0; t < 2; ++t) { \
        const int r = r0 + t * 64; \
        pa[t] = make_float4(0.f, 0.f, 0.f, 0.f); \
        if (bm + r < aRows) \
            pa[t] = *(const float4*)(A + (size_t)(bm + r) * 1024 + (k0) + f0); \
        pb[t] = *(const float4*)(B + (size_t)(bn + r) * 1024 + (k0) + f0); \
    } } while (0)

#define G1_STORE(bufp) do { \
    float* Ah_ = (bufp); \
    float* Bh_ = (bufp) + GTILE; \
    _Pragma("unroll") \
    for (int t = 0; t < 2; ++t) { \
        const int r = r0 + t * 64; \
        float4 hi; \
        hi4(pa[t], hi); *(float4*)(Ah_ + r * GST + f0) = hi; \
        hi4(pb[t], hi); *(float4*)(Bh_ + r * GST + f0) = hi; \
    } } while (0)

    G1_LOAD(0);
    G1_STORE(smem);
    __syncthreads();

    for (int c = 0; c < 64; ++c) {
        float* cur = smem + (c & 1) * (2 * GTILE);
        if (c < 63) G1_LOAD((c + 1) * 16);

        float* Ah = cur;
        float* Bh = cur + GTILE;

#pragma unroll
        for (int ks = 0; ks < 2; ++ks) {
            const int kc = ks * 8 + tig;
            uint32_t ah[4][4];
#pragma unroll
            for (int mt = 0; mt < 4; ++mt) {
                const int ra = (warp_m * 64 + mt * 16 + grp) * GST;
                ah[mt][0] = __float_as_uint(Ah[ra + kc]);
                ah[mt][1] = __float_as_uint(Ah[ra + 8 * GST + kc]);
                ah[mt][2] = __float_as_uint(Ah[ra + kc + 4]);
                ah[mt][3] = __float_as_uint(Ah[ra + 8 * GST + kc + 4]);
            }
#pragma unroll
            for (int nt = 0; nt < 4; ++nt) {
                const int rb = (warp_n * 32 + nt * 8 + grp) * GST + kc;
                uint32_t bh0 = __float_as_uint(Bh[rb]);
                uint32_t bh1 = __float_as_uint(Bh[rb + 4]);
#pragma unroll
                for (int mt = 0; mt < 4; ++mt)
                    MMA_TF32(acc[mt][nt], ah[mt][0], ah[mt][1], ah[mt][2], ah[mt][3], bh0, bh1);
            }
        }
        if (c < 63) G1_STORE(smem + ((c + 1) & 1) * (2 * GTILE));
        __syncthreads();
    }
#undef G1_LOAD
#undef G1_STORE
}

#define GSMEM_B (2 * 2 * GTILE * 4)   // 40960 B

// ---- qkv (q,k columns): bf16x3 ----
__global__ __launch_bounds__(256, 2) void gemm_qk_kern(
    const float* __restrict__ A, const float* __restrict__ B)
{
    const int bm = blockIdx.y * 128;
    const int bn = blockIdx.x * 128;
    float acc[4][4][4];
#pragma unroll
    for (int a = 0; a < 4; a++)
#pragma unroll
        for (int b = 0; b < 4; b++)
#pragma unroll
            for (int cc = 0; cc < 4; cc++) acc[a][b][cc] = 0.0f;

    gemm_db3b(A, B, bm, bn, NSEQ, (uint32_t*)dynsm, acc);

    const int tid = threadIdx.x;
    const int wid = tid >> 5, lane = tid & 31;
    const int warp_m = wid & 1, warp_n = wid >> 1;
    const int grp = lane >> 2, tig = lane & 3;

    const int s = bn >> 10;
    float* __restrict__ dst = (s == 0) ? g_q : g_k;
    const float scale = (s == 0) ? 0.125f : 1.0f;

#pragma unroll
    for (int mt = 0; mt < 4; ++mt)
#pragma unroll
        for (int half = 0; half < 2; ++half) {
            const int row = bm + warp_m * 64 + mt * 16 + grp + half * 8;
            if (row >= NSEQ) continue;
#pragma unroll
            for (int nt = 0; nt < 4; ++nt) {
                const int col = bn + warp_n * 32 + nt * 8 + tig * 2;
                const int h = (col & 1023) >> 6;
                const int d = col & 63;
                float2 v;
                v.x = acc[mt][nt][half * 2 + 0] * scale;
                v.y = acc[mt][nt][half * 2 + 1] * scale;
                *(float2*)&dst[((size_t)h * NPAD + row) * DH + d] = v;
            }
        }
}

// ---- qkv (v columns): 1xTF32 ----
__global__ __launch_bounds__(256, 2) void gemm_v_kern(
    const float* __restrict__ A, const float* __restrict__ B)
{
    const int bm = blockIdx.y * 128;
    const int bn = 2048 + blockIdx.x * 128;
    float acc[4][4][4];
#pragma unroll
    for (int a = 0; a < 4; a++)
#pragma unroll
        for (int b = 0; b < 4; b++)
#pragma unroll
            for (int cc = 0; cc < 4; cc++) acc[a][b][cc] = 0.0f;

    gemm_db1(A, B, bm, bn, NSEQ, dynsm, acc);

    const int tid = threadIdx.x;
    const int wid = tid >> 5, lane = tid & 31;
    const int warp_m = wid & 1, warp_n = wid >> 1;
    const int grp = lane >> 2, tig = lane & 3;

#pragma unroll
    for (int mt = 0; mt < 4; ++mt)
#pragma unroll
        for (int half = 0; half < 2; ++half) {
            const int row = bm + warp_m * 64 + mt * 16 + grp + half * 8;
            if (row >= NSEQ) continue;
#pragma unroll
            for (int nt = 0; nt < 4; ++nt) {
                const int col = bn + warp_n * 32 + nt * 8 + tig * 2;
                const int h = (col & 1023) >> 6;
                const int d = col & 63;
                float2 v;
                v.x = acc[mt][nt][half * 2 + 0];
                v.y = acc[mt][nt][half * 2 + 1];
                *(float2*)&g_v[((size_t)h * NPAD + row) * DH + d] = v;
            }
        }
}

// ---- proj: 1xTF32 + bias ----
__global__ __launch_bounds__(256, 2) void gemm_proj_kern(
    const float* __restrict__ B, const float* __restrict__ bias,
    float* __restrict__ C)
{
    const int bm = blockIdx.y * 128;
    const int bn = blockIdx.x * 128;
    float acc[4][4][4];
#pragma unroll
    for (int a = 0; a < 4; a++)
#pragma unroll
        for (int b = 0; b < 4; b++)
#pragma unroll
            for (int cc = 0; cc < 4; cc++) acc[a][b][cc] = 0.0f;

    gemm_db1(g_attn, B, bm, bn, NSEQ, dynsm, acc);

    const int tid = threadIdx.x;
    const int wid = tid >> 5, lane = tid & 31;
    const int warp_m = wid & 1, warp_n = wid >> 1;
    const int grp = lane >> 2, tig = lane & 3;

#pragma unroll
    for (int mt = 0; mt < 4; ++mt)
#pragma unroll
        for (int half = 0; half < 2; ++half) {
            const int row = bm + warp_m * 64 + mt * 16 + grp + half * 8;
            if (row >= NSEQ) continue;
#pragma unroll
            for (int nt = 0; nt < 4; ++nt) {
                const int col = bn + warp_n * 32 + nt * 8 + tig * 2;
                float2 v;
                v.x = acc[mt][nt][half * 2 + 0] + bias[col];
                v.y = acc[mt][nt][half * 2 + 1] + bias[col + 1];
                *(float2*)&C[(size_t)row * 1024 + col] = v;
            }
        }
}

// ============================================================
// RoPE on q and k, rows PREFIX..NSEQ-1
// ============================================================
__global__ void rope_kernel(const float* __restrict__ rope)
{
    int idx = blockIdx.x * blockDim.x + threadIdx.x;
    if (idx >= HWLEN * NH * 32) return;
    const int d = idx & 31;
    const int h = (idx >> 5) & 15;
    const int p = idx >> 9;
    const int n = PREFIX + p;

    const float s0 = rope[p * 64 + d];
    const float s1 = rope[p * 64 + d + 32];
    const float c0 = rope[HWLEN * 64 + p * 64 + d];
    const float c1 = rope[HWLEN * 64 + p * 64 + d + 32];

    const size_t base = ((size_t)h * NPAD + n) * DH;

    float q0 = g_q[base + d], q1 = g_q[base + d + 32];
    g_q[base + d]      = q0 * c0 - q1 * s0;
    g_q[base + d + 32] = q1 * c1 + q0 * s1;

    float k0 = g_k[base + d], k1 = g_k[base + d + 32];
    g_k[base + d]      = k0 * c0 - k1 * s0;
    g_k[base + d + 32] = k1 * c1 + k0 * s1;
}

// ============================================================
// Flash attention v6 (bf16x3 + ldmatrix): 128 threads, 4 warps,
// warp = 16 q-rows x 32 keys. grid (26, 16). smem ~47 KB.
// ============================================================
#define AQ_H 0                       // 64*36 = 2304 words
#define AQ_L 2304
#define AK_H 4608                    // 32*36 = 1152
#define AK_L 5760
#define AV_H 6912                    // 64*20 = 1280
#define AV_L 8192
#define AP   9472                    // 4 warps * (320 h + 320 l)
#define ATTN_SMEM_BYTES (12032 * 4)  // 48128 B

__global__ __launch_bounds__(128, 3) void attn_bf16()
{
    uint32_t* usm = (uint32_t*)dynsm;
    uint32_t* Kh = usm + AK_H;
    uint32_t* Kl = usm + AK_L;
    uint32_t* Vh = usm + AV_H;
    uint32_t* Vl = usm + AV_L;

    const int h  = blockIdx.y;
    const int qb = blockIdx.x * 64;
    const int tid = threadIdx.x;
    const int wid = tid >> 5, lane = tid & 31;
    const int grp = lane >> 2, tig = lane & 3;
    const int row0 = wid * 16;

    uint32_t* Qh = usm + AQ_H;
    uint32_t* Ql = usm + AQ_L;
    uint32_t* Ph = usm + AP + wid * 640;
    uint32_t* Pl = Ph + 320;

    const uint32_t smb = cvta_s(usm);
    // ldmatrix word-index bases
    const int q_lm  = AQ_H + (row0 + (lane & 15)) * 36 + (lane >> 4) * 4;
    const int q_lml = q_lm + (AQ_L - AQ_H);
    const int k_lm  = AK_H + ((lane >> 4) * 8 + (lane & 7)) * 36 + ((lane >> 3) & 1) * 4;
    const int k_lml = k_lm + (AK_L - AK_H);
    const int v_lm  = AV_H + ((lane >> 4) * 8 + (lane & 7)) * 20 + ((lane >> 3) & 1) * 4;
    const int v_lml = v_lm + (AV_L - AV_H);
    const int p_lm  = AP + wid * 640 + (lane & 15) * 20 + (lane >> 4) * 4;
    const int p_lml = p_lm + 320;

    const float* __restrict__ Qg = g_q + (size_t)h * NPAD * DH;
    const float* __restrict__ Kg = g_k + (size_t)h * NPAD * DH;
    const float* __restrict__ Vg = g_v + (size_t)h * NPAD * DH;

    // ---- prologue: Q tile 64x64 -> packed bf16x2 hi/lo ----
#pragma unroll
    for (int t = 0; t < 8; ++t) {
        const int idx = tid + t * 128;
        const int r = idx >> 4, c4 = (idx & 15) * 4;
        float4 v = *(const float4*)(Qg + (size_t)(qb + r) * DH + c4);
        uint32_t h0, l0, h1, l1;
        split2(v.x, v.y, h0, l0);
        split2(v.z, v.w, h1, l1);
        Qh[r * 36 + c4 / 2] = h0; Qh[r * 36 + c4 / 2 + 1] = h1;
        Ql[r * 36 + c4 / 2] = l0; Ql[r * 36 + c4 / 2 + 1] = l1;
    }

    // ---- K/V tile 0 ----
    const int lr = tid >> 4;              // 0..7 (+8 per t) for K
    const int lc4 = (tid & 15) * 4;
    const int vp = tid & 15;              // V key-pair
    const int vdg = tid >> 4;             // V d-group (0..7)
    float4 pk[4];
    float4 ve0, ve1, vo0, vo1;

#define KV_FETCH(base) do { \
    _Pragma("unroll") \
    for (int t = 0; t < 4; ++t) \
        pk[t] = *(const float4*)(Kg + (size_t)((base) + lr + t * 8) * DH + lc4); \
    ve0 = *(const float4*)(Vg + (size_t)((base) + 2 * vp) * DH + vdg * 8); \
    ve1 = *(const float4*)(Vg + (size_t)((base) + 2 * vp) * DH + vdg * 8 + 4); \
    vo0 = *(const float4*)(Vg + (size_t)((base) + 2 * vp + 1) * DH + vdg * 8); \
    vo1 = *(const float4*)(Vg + (size_t)((base) + 2 * vp + 1) * DH + vdg * 8 + 4); \
} while (0)

#define KV_STORE() do { \
    _Pragma("unroll") \
    for (int t = 0; t < 4; ++t) { \
        const int r = lr + t * 8; \
        uint32_t h0, l0, h1, l1; \
        split2(pk[t].x, pk[t].y, h0, l0); \
        split2(pk[t].z, pk[t].w, h1, l1); \
        Kh[r * 36 + lc4 / 2] = h0; Kh[r * 36 + lc4 / 2 + 1] = h1; \
        Kl[r * 36 + lc4 / 2] = l0; Kl[r * 36 + lc4 / 2 + 1] = l1; \
    } \
    { \
        float ve[8] = {ve0.x, ve0.y, ve0.z, ve0.w, ve1.x, ve1.y, ve1.z, ve1.w}; \
        float vo[8] = {vo0.x, vo0.y, vo0.z, vo0.w, vo1.x, vo1.y, vo1.z, vo1.w}; \
        _Pragma("unroll") \
        for (int j = 0; j < 8; ++j) { \
            const int d = vdg * 8 + j; \
            uint32_t hh, ll; \
            split2(ve[j], vo[j], hh, ll); \
            Vh[d * 20 + vp] = hh; \
            Vl[d * 20 + vp] = ll; \
        } \
    } \
} while (0)

    KV_FETCH(0);
    KV_STORE();
    __syncthreads();

    float m0 = -1e38f, m1 = -1e38f, l0s = 0.0f, l1s = 0.0f;
    float o[8][4];
#pragma unroll
    for (int nt = 0; nt < 8; nt++)
#pragma unroll
        for (int i = 0; i < 4; i++) o[nt][i] = 0.0f;

    const int nkt = (NSEQ + 31) / 32;    // 51
    for (int kt = 0; kt < nkt; ++kt) {
        const int key0 = kt * 32;

        // ---- S = Q K^T (bf16x3, ldmatrix fragments) ----
        float sacc[4][4];
#pragma unroll
        for (int nt = 0; nt < 4; nt++)
#pragma unroll
            for (int i = 0; i < 4; i++) sacc[nt][i] = 0.0f;

#pragma unroll
        for (int ks = 0; ks < 4; ++ks) {
            const int kw = ks * 8;
            uint32_t ah0, ah1, ah2, ah3, al0, al1, al2, al3;
            LDSM_X4(ah0, ah1, ah2, ah3, smb + (uint32_t)(q_lm + kw) * 4u);
            LDSM_X4(al0, al1, al2, al3, smb + (uint32_t)(q_lml + kw) * 4u);
#pragma unroll
            for (int ntp = 0; ntp < 2; ++ntp) {
                uint32_t bh0, bh1, bh2, bh3, bl0, bl1, bl2, bl3;
                LDSM_X4(bh0, bh1, bh2, bh3,
                        smb + (uint32_t)(k_lm + ntp * 16 * 36 + kw) * 4u);
                LDSM_X4(bl0, bl1, bl2, bl3,
                        smb + (uint32_t)(k_lml + ntp * 16 * 36 + kw) * 4u);
                MMA_BF16(sacc[2 * ntp], ah0, ah1, ah2, ah3, bh0, bh1);
                MMA_BF16(sacc[2 * ntp], ah0, ah1, ah2, ah3, bl0, bl1);
                MMA_BF16(sacc[2 * ntp], al0, al1, al2, al3, bh0, bh1);
                MMA_BF16(sacc[2 * ntp + 1], ah0, ah1, ah2, ah3, bh2, bh3);
                MMA_BF16(sacc[2 * ntp + 1], ah0, ah1, ah2, ah3, bl2, bl3);
                MMA_BF16(sacc[2 * ntp + 1], al0, al1, al2, al3, bh2, bh3);
            }
        }

        // ---- prefetch next K/V into regs ----
        if (kt + 1 < nkt) KV_FETCH(key0 + 32);

        // ---- register softmax ----
        {
            float mx0 = -1e30f, mx1 = -1e30f;
#pragma unroll
            for (int nt = 0; nt < 4; ++nt) {
                const int c0 = key0 + nt * 8 + tig * 2;
                if (c0 >= NSEQ)     { sacc[nt][0] = -1e30f; sacc[nt][2] = -1e30f; }
                if (c0 + 1 >= NSEQ) { sacc[nt][1] = -1e30f; sacc[nt][3] = -1e30f; }
                mx0 = fmaxf(mx0, fmaxf(sacc[nt][0], sacc[nt][1]));
                mx1 = fmaxf(mx1, fmaxf(sacc[nt][2], sacc[nt][3]));
            }
            mx0 = fmaxf(mx0, __shfl_xor_sync(0xffffffffu, mx0, 1));
            mx0 = fmaxf(mx0, __shfl_xor_sync(0xffffffffu, mx0, 2));
            mx1 = fmaxf(mx1, __shfl_xor_sync(0xffffffffu, mx1, 1));
            mx1 = fmaxf(mx1, __shfl_xor_sync(0xffffffffu, mx1, 2));

            const float mn0 = fmaxf(m0, mx0);
            const float mn1 = fmaxf(m1, mx1);
            const float a0 = __expf(m0 - mn0);
            const float a1 = __expf(m1 - mn1);
            m0 = mn0; m1 = mn1;

            float s0 = 0.0f, s1 = 0.0f;
#pragma unroll
            for (int nt = 0; nt < 4; ++nt) {
                sacc[nt][0] = __expf(sacc[nt][0] - mn0); s0 += sacc[nt][0];
                sacc[nt][1] = __expf(sacc[nt][1] - mn0); s0 += sacc[nt][1];
                sacc[nt][2] = __expf(sacc[nt][2] - mn1); s1 += sacc[nt][2];
                sacc[nt][3] = __expf(sacc[nt][3] - mn1); s1 += sacc[nt][3];
            }
            s0 += __shfl_xor_sync(0xffffffffu, s0, 1);
            s0 += __shfl_xor_sync(0xffffffffu, s0, 2);
            s1 += __shfl_xor_sync(0xffffffffu, s1, 1);
            s1 += __shfl_xor_sync(0xffffffffu, s1, 2);
            l0s = l0s * a0 + s0;
            l1s = l1s * a1 + s1;

            // pack P hi/lo straight from registers
#pragma unroll
            for (int nt = 0; nt < 4; ++nt) {
                const int cw = nt * 4 + tig;
                uint32_t hh, ll;
                split2(sacc[nt][0], sacc[nt][1], hh, ll);
                Ph[grp * 20 + cw] = hh; Pl[grp * 20 + cw] = ll;
                split2(sacc[nt][2], sacc[nt][3], hh, ll);
                Ph[(grp + 8) * 20 + cw] = hh; Pl[(grp + 8) * 20 + cw] = ll;
            }
            __syncwarp();

#pragma unroll
            for (int nt = 0; nt < 8; ++nt) {
                o[nt][0] *= a0; o[nt][1] *= a0;
                o[nt][2] *= a1; o[nt][3] *= a1;
            }
        }

        // ---- O += P V (bf16x3, ldmatrix fragments) ----
#pragma unroll
        for (int kk = 0; kk < 2; ++kk) {
            const int kw = kk * 8;
            uint32_t ph0, ph1, ph2, ph3, pl0, pl1, pl2, pl3;
            LDSM_X4(ph0, ph1, ph2, ph3, smb + (uint32_t)(p_lm + kw) * 4u);
            LDSM_X4(pl0, pl1, pl2, pl3, smb + (uint32_t)(p_lml + kw) * 4u);
#pragma unroll
            for (int ntp = 0; ntp < 4; ++ntp) {
                uint32_t vh0, vh1, vh2, vh3, vl0, vl1, vl2, vl3;
                LDSM_X4(vh0, vh1, vh2, vh3,
                        smb + (uint32_t)(v_lm + ntp * 16 * 20 + kw) * 4u);
                LDSM_X4(vl0, vl1, vl2, vl3,
                        smb + (uint32_t)(v_lml + ntp * 16 * 20 + kw) * 4u);
                MMA_BF16(o[2 * ntp], ph0, ph1, ph2, ph3, vh0, vh1);
                MMA_BF16(o[2 * ntp], ph0, ph1, ph2, ph3, vl0, vl1);
                MMA_BF16(o[2 * ntp], pl0, pl1, pl2, pl3, vh0, vh1);
                MMA_BF16(o[2 * ntp + 1], ph0, ph1, ph2, ph3, vh2, vh3);
                MMA_BF16(o[2 * ntp + 1], ph0, ph1, ph2, ph3, vl2, vl3);
                MMA_BF16(o[2 * ntp + 1], pl0, pl1, pl2, pl3, vh2, vh3);
            }
        }
        __syncthreads();

        // ---- store prefetched K/V tile ----
        if (kt + 1 < nkt) {
            KV_STORE();
            __syncthreads();
        }
    }

    // ---- epilogue ----
    const float inv0 = 1.0f / l0s;
    const float inv1 = 1.0f / l1s;
    const int n0 = qb + row0 + grp;
    const int n1 = n0 + 8;
#pragma unroll
    for (int nt = 0; nt < 8; ++nt) {
        const int col = h * DH + nt * 8 + tig * 2;
        if (n0 < NSEQ)
            *(float2*)&g_attn[(size_t)n0 * DIMF + col] =
                make_float2(o[nt][0] * inv0, o[nt][1] * inv0);
        if (n1 < NSEQ)
            *(float2*)&g_attn[(size_t)n1 * DIMF + col] =
                make_float2(o[nt][2] * inv1, o[nt][3] * inv1);
    }
}

// ============================================================
extern "C" void kernel_launch(void* const* d_in, const int* in_sizes, int n_in,
                              void* d_out, int out_size)
{
    (void)in_sizes; (void)n_in; (void)out_size;
    const float* x     = (const float*)d_in[0];
    const float* rope  = (const float*)d_in[1];
    const float* Wqkv  = (const float*)d_in[2];
    const float* Wproj = (const float*)d_in[3];
    const float* bproj = (const float*)d_in[4];
    float* out = (float*)d_out;

    static int configured = 0;
    if (!configured) {
        cudaFuncSetAttribute(gemm_qk_kern,   cudaFuncAttributeMaxDynamicSharedMemorySize, GSMEM_QK);
        cudaFuncSetAttribute(gemm_v_kern,    cudaFuncAttributeMaxDynamicSharedMemorySize, GSMEM_B);
        cudaFuncSetAttribute(gemm_proj_kern, cudaFuncAttributeMaxDynamicSharedMemorySize, GSMEM_B);
        cudaFuncSetAttribute(attn_bf16,      cudaFuncAttributeMaxDynamicSharedMemorySize, ATTN_SMEM_BYTES);
        configured = 1;
    }

    gemm_qk_kern<<<dim3(16, 13), 256, GSMEM_QK>>>(x, Wqkv);
    gemm_v_kern<<<dim3(8, 13), 256, GSMEM_B>>>(x, Wqkv);
    rope_kernel<<<(HWLEN * NH * 32 + 255) / 256, 256>>>(rope);
    attn_bf16<<<dim3(26, NH), 128, ATTN_SMEM_BYTES>>>();
    gemm_proj_kern<<<dim3(8, 13), 256, GSMEM_B>>>(Wproj, bproj, out);
}

// round 10
// speedup vs baseline: 2.7502x; 1.0088x over previous
#include <cuda_runtime.h>
#include <cstdint>

#define NSEQ   1605
#define DIMF   1024
#define NH     16
#define DH     64
#define HWLEN  1600
#define PREFIX 5
#define NPAD   1664   // 26 * 64

// ---- scratch (device globals; zero-initialized at module load) ----
__device__ float g_q[(size_t)NH * NPAD * DH];
__device__ float g_k[(size_t)NH * NPAD * DH];
__device__ float g_v[(size_t)NH * NPAD * DH];
__device__ float g_attn[(size_t)NSEQ * DIMF];

// ============================================================
// mma / ldmatrix helpers
// ============================================================
__device__ __forceinline__ uint32_t f2tf32(float a) {
    uint32_t u; asm("cvt.rna.tf32.f32 %0, %1;" : "=r"(u) : "f"(a));
    return u;
}
__device__ __forceinline__ uint32_t cvta_s(const void* p) {
    uint32_t a;
    asm("{ .reg .u64 t; cvta.to.shared.u64 t, %1; cvt.u32.u64 %0, t; }"
        : "=r"(a) : "l"(p));
    return a;
}

#define MMA_TF32(d, a0, a1, a2, a3, b0, b1) \
    asm volatile("mma.sync.aligned.m16n8k8.row.col.f32.tf32.tf32.f32 " \
        "{%0,%1,%2,%3}, {%4,%5,%6,%7}, {%8,%9}, {%0,%1,%2,%3};" \
        : "+f"((d)[0]), "+f"((d)[1]), "+f"((d)[2]), "+f"((d)[3]) \
        : "r"(a0), "r"(a1), "r"(a2), "r"(a3), "r"(b0), "r"(b1))

#define MMA_BF16(d, a0, a1, a2, a3, b0, b1) \
    asm volatile("mma.sync.aligned.m16n8k16.row.col.f32.bf16.bf16.f32 " \
        "{%0,%1,%2,%3}, {%4,%5,%6,%7}, {%8,%9}, {%0,%1,%2,%3};" \
        : "+f"((d)[0]), "+f"((d)[1]), "+f"((d)[2]), "+f"((d)[3]) \
        : "r"(a0), "r"(a1), "r"(a2), "r"(a3), "r"(b0), "r"(b1))

#define LDSM_X4(r0, r1, r2, r3, addr) \
    asm volatile("ldmatrix.sync.aligned.m8n8.x4.shared.b16 {%0,%1,%2,%3}, [%4];" \
        : "=r"(r0), "=r"(r1), "=r"(r2), "=r"(r3) : "r"(addr))

__device__ __forceinline__ uint32_t pack_bf16x2(float lo, float hi) {
    uint32_t w;
    asm("cvt.rn.bf16x2.f32 %0, %1, %2;" : "=r"(w) : "f"(hi), "f"(lo));
    return w;
}
__device__ __forceinline__ float lo_bf16(uint32_t w) { return __uint_as_float(w << 16); }
__device__ __forceinline__ float hi_bf16(uint32_t w) { return __uint_as_float(w & 0xFFFF0000u); }

__device__ __forceinline__ void split2(float e, float o, uint32_t& h, uint32_t& l) {
    h = pack_bf16x2(e, o);
    l = pack_bf16x2(e - lo_bf16(h), o - hi_bf16(h));
}

__device__ __forceinline__ void hi4(const float4 v, float4& hi) {
    hi.x = __uint_as_float(f2tf32(v.x));
    hi.y = __uint_as_float(f2tf32(v.y));
    hi.z = __uint_as_float(f2tf32(v.z));
    hi.w = __uint_as_float(f2tf32(v.w));
}

extern __shared__ float dynsm[];

// ============================================================
// bf16x3 GEMM (qk): packed bf16x2 hi/lo smem, double-buffered,
// ldmatrix fragment loads.  (unchanged from round 9)
// ============================================================
#define BST 12
#define BTILE (128 * BST)

__device__ __forceinline__ void gemm_db3b(
    const float* __restrict__ A, const float* __restrict__ B,
    int bm, int bn, int aRows, uint32_t* __restrict__ smem,
    float acc[4][4][4])
{
    const int tid = threadIdx.x;
    const int wid = tid >> 5, lane = tid & 31;
    const int warp_m = wid & 1, warp_n = wid >> 1;
    const int r0 = tid >> 2;
    const int f0 = (tid & 3) * 4;
    const int w0 = (tid & 3) * 2;

    const uint32_t smb = cvta_s(smem);
    const int a_lm = (warp_m * 64 + (lane & 15)) * BST + (lane >> 4) * 4;
    const int b_lm = (warp_n * 32 + (lane >> 4) * 8 + (lane & 7)) * BST
                     + ((lane >> 3) & 1) * 4;

    float4 pa[2], pb[2];

#define GB_LOAD(k0) do { \
    _Pragma("unroll") \
    for (int t = 0; t < 2; ++t) { \
        const int r = r0 + t * 64; \
        pa[t] = make_float4(0.f, 0.f, 0.f, 0.f); \
        if (bm + r < aRows) \
            pa[t] = *(const float4*)(A + (size_t)(bm + r) * 1024 + (k0) + f0); \
        pb[t] = *(const float4*)(B + (size_t)(bn + r) * 1024 + (k0) + f0); \
    } } while (0)

#define GB_STORE(bufp) do { \
    uint32_t* Ah_ = (bufp); \
    uint32_t* Al_ = (bufp) + BTILE; \
    uint32_t* Bh_ = (bufp) + 2 * BTILE; \
    uint32_t* Bl_ = (bufp) + 3 * BTILE; \
    _Pragma("unroll") \
    for (int t = 0; t < 2; ++t) { \
        const int r = r0 + t * 64; \
        uint32_t h0, l0, h1, l1; \
        split2(pa[t].x, pa[t].y, h0, l0); \
        split2(pa[t].z, pa[t].w, h1, l1); \
        Ah_[r * BST + w0] = h0; Ah_[r * BST + w0 + 1] = h1; \
        Al_[r * BST + w0] = l0; Al_[r * BST + w0 + 1] = l1; \
        split2(pb[t].x, pb[t].y, h0, l0); \
        split2(pb[t].z, pb[t].w, h1, l1); \
        Bh_[r * BST + w0] = h0; Bh_[r * BST + w0 + 1] = h1; \
        Bl_[r * BST + w0] = l0; Bl_[r * BST + w0 + 1] = l1; \
    } } while (0)

    GB_LOAD(0);
    GB_STORE(smem);
    __syncthreads();

    for (int c = 0; c < 64; ++c) {
        const int bufw = (c & 1) * (4 * BTILE);
        if (c < 63) GB_LOAD((c + 1) * 16);

        uint32_t ah[4][4], al[4][4];
#pragma unroll
        for (int mt = 0; mt < 4; ++mt) {
            LDSM_X4(ah[mt][0], ah[mt][1], ah[mt][2], ah[mt][3],
                    smb + (uint32_t)(bufw + a_lm + mt * 16 * BST) * 4u);
            LDSM_X4(al[mt][0], al[mt][1], al[mt][2], al[mt][3],
                    smb + (uint32_t)(bufw + BTILE + a_lm + mt * 16 * BST) * 4u);
        }
#pragma unroll
        for (int ntp = 0; ntp < 2; ++ntp) {
            uint32_t bh0, bh1, bh2, bh3, bl0, bl1, bl2, bl3;
            LDSM_X4(bh0, bh1, bh2, bh3,
                    smb + (uint32_t)(bufw + 2 * BTILE + b_lm + ntp * 16 * BST) * 4u);
            LDSM_X4(bl0, bl1, bl2, bl3,
                    smb + (uint32_t)(bufw + 3 * BTILE + b_lm + ntp * 16 * BST) * 4u);
#pragma unroll
            for (int mt = 0; mt < 4; ++mt) {
                MMA_BF16(acc[mt][2 * ntp], ah[mt][0], ah[mt][1], ah[mt][2], ah[mt][3], bh0, bh1);
                MMA_BF16(acc[mt][2 * ntp], ah[mt][0], ah[mt][1], ah[mt][2], ah[mt][3], bl0, bl1);
                MMA_BF16(acc[mt][2 * ntp], al[mt][0], al[mt][1], al[mt][2], al[mt][3], bh0, bh1);
                MMA_BF16(acc[mt][2 * ntp + 1], ah[mt][0], ah[mt][1], ah[mt][2], ah[mt][3], bh2, bh3);
                MMA_BF16(acc[mt][2 * ntp + 1], ah[mt][0], ah[mt][1], ah[mt][2], ah[mt][3], bl2, bl3);
                MMA_BF16(acc[mt][2 * ntp + 1], al[mt][0], al[mt][1], al[mt][2], al[mt][3], bh2, bh3);
            }
        }
        if (c < 63) GB_STORE(smem + ((c + 1) & 1) * (4 * BTILE));
        __syncthreads();
    }
#undef GB_LOAD
#undef GB_STORE
}

#define GSMEM_QK (2 * 4 * BTILE * 4)

// ============================================================
// 1xTF32 GEMM (pre-converted hi in smem) — v and proj
// ============================================================
#define GST 20
#define GTILE (128 * GST)

__device__ __forceinline__ void gemm_db1(
    const float* __restrict__ A, const float* __restrict__ B,
    int bm, int bn, int aRows, float* __restrict__ smem,
    float acc[4][4][4])
{
    const int tid = threadIdx.x;
    const int wid = tid >> 5, lane = tid & 31;
    const int warp_m = wid & 1, warp_n = wid >> 1;
    const int grp = lane >> 2, tig = lane & 3;
    const int r0 = tid >> 2;
    const int f0 = (tid & 3) * 4;

    float4 pa[2], pb[2];

#define G1_LOAD(k0) do { \
    _Pragma("unroll") \
    for (int t = 0; t < 2; ++t) { \
        const int r = r0 + t * 64; \
        pa[t] = make_float4(0.f, 0.f, 0.f, 0.f); \
        if (bm + r < aRows) \
            pa[t] = *(const float4*)(A + (size_t)(bm + r) * 1024 + (k0) + f0); \
        pb[t] = *(const float4*)(B + (size_t)(bn + r) * 1024 + (k0) + f0); \
    } } while (0)

#define G1_STORE(bufp) do { \
    float* Ah_ = (bufp); \
    float* Bh_ = (bufp) + GTILE; \
    _Pragma("unroll") \
    for (int t = 0; t < 2; ++t) { \
        const int r = r0 + t * 64; \
        float4 hi; \
        hi4(pa[t], hi); *(float4*)(Ah_ + r * GST + f0) = hi; \
        hi4(pb[t], hi); *(float4*)(Bh_ + r * GST + f0) = hi; \
    } } while (0)

    G1_LOAD(0);
    G1_STORE(smem);
    __syncthreads();

    for (int c = 0; c < 64; ++c) {
        float* cur = smem + (c & 1) * (2 * GTILE);
        if (c < 63) G1_LOAD((c + 1) * 16);

        float* Ah = cur;
        float* Bh = cur + GTILE;

#pragma unroll
        for (int ks = 0; ks < 2; ++ks) {
            const int kc = ks * 8 + tig;
            uint32_t ah[4][4];
#pragma unroll
            for (int mt = 0; mt < 4; ++mt) {
                const int ra = (warp_m * 64 + mt * 16 + grp) * GST;
                ah[mt][0] = __float_as_uint(Ah[ra + kc]);
                ah[mt][1] = __float_as_uint(Ah[ra + 8 * GST + kc]);
                ah[mt][2] = __float_as_uint(Ah[ra + kc + 4]);
                ah[mt][3] = __float_as_uint(Ah[ra + 8 * GST + kc + 4]);
            }
#pragma unroll
            for (int nt = 0; nt < 4; ++nt) {
                const int rb = (warp_n * 32 + nt * 8 + grp) * GST + kc;
                uint32_t bh0 = __float_as_uint(Bh[rb]);
                uint32_t bh1 = __float_as_uint(Bh[rb + 4]);
#pragma unroll
                for (int mt = 0; mt < 4; ++mt)
                    MMA_TF32(acc[mt][nt], ah[mt][0], ah[mt][1], ah[mt][2], ah[mt][3], bh0, bh1);
            }
        }
        if (c < 63) G1_STORE(smem + ((c + 1) & 1) * (2 * GTILE));
        __syncthreads();
    }
#undef G1_LOAD
#undef G1_STORE
}

#define GSMEM_B (2 * 2 * GTILE * 4)

// ---- qkv (q,k columns): bf16x3 ----
__global__ __launch_bounds__(256, 2) void gemm_qk_kern(
    const float* __restrict__ A, const float* __restrict__ B)
{
    const int bm = blockIdx.y * 128;
    const int bn = blockIdx.x * 128;
    float acc[4][4][4];
#pragma unroll
    for (int a = 0; a < 4; a++)
#pragma unroll
        for (int b = 0; b < 4; b++)
#pragma unroll
            for (int cc = 0; cc < 4; cc++) acc[a][b][cc] = 0.0f;

    gemm_db3b(A, B, bm, bn, NSEQ, (uint32_t*)dynsm, acc);

    const int tid = threadIdx.x;
    const int wid = tid >> 5, lane = tid & 31;
    const int warp_m = wid & 1, warp_n = wid >> 1;
    const int grp = lane >> 2, tig = lane & 3;

    const int s = bn >> 10;
    float* __restrict__ dst = (s == 0) ? g_q : g_k;
    const float scale = (s == 0) ? 0.125f : 1.0f;

#pragma unroll
    for (int mt = 0; mt < 4; ++mt)
#pragma unroll
        for (int half = 0; half < 2; ++half) {
            const int row = bm + warp_m * 64 + mt * 16 + grp + half * 8;
            if (row >= NSEQ) continue;
#pragma unroll
            for (int nt = 0; nt < 4; ++nt) {
                const int col = bn + warp_n * 32 + nt * 8 + tig * 2;
                const int h = (col & 1023) >> 6;
                const int d = col & 63;
                float2 v;
                v.x = acc[mt][nt][half * 2 + 0] * scale;
                v.y = acc[mt][nt][half * 2 + 1] * scale;
                *(float2*)&dst[((size_t)h * NPAD + row) * DH + d] = v;
            }
        }
}

// ---- qkv (v columns): 1xTF32 ----
__global__ __launch_bounds__(256, 2) void gemm_v_kern(
    const float* __restrict__ A, const float* __restrict__ B)
{
    const int bm = blockIdx.y * 128;
    const int bn = 2048 + blockIdx.x * 128;
    float acc[4][4][4];
#pragma unroll
    for (int a = 0; a < 4; a++)
#pragma unroll
        for (int b = 0; b < 4; b++)
#pragma unroll
            for (int cc = 0; cc < 4; cc++) acc[a][b][cc] = 0.0f;

    gemm_db1(A, B, bm, bn, NSEQ, dynsm, acc);

    const int tid = threadIdx.x;
    const int wid = tid >> 5, lane = tid & 31;
    const int warp_m = wid & 1, warp_n = wid >> 1;
    const int grp = lane >> 2, tig = lane & 3;

#pragma unroll
    for (int mt = 0; mt < 4; ++mt)
#pragma unroll
        for (int half = 0; half < 2; ++half) {
            const int row = bm + warp_m * 64 + mt * 16 + grp + half * 8;
            if (row >= NSEQ) continue;
#pragma unroll
            for (int nt = 0; nt < 4; ++nt) {
                const int col = bn + warp_n * 32 + nt * 8 + tig * 2;
                const int h = (col & 1023) >> 6;
                const int d = col & 63;
                float2 v;
                v.x = acc[mt][nt][half * 2 + 0];
                v.y = acc[mt][nt][half * 2 + 1];
                *(float2*)&g_v[((size_t)h * NPAD + row) * DH + d] = v;
            }
        }
}

// ---- proj: 1xTF32 + bias ----
__global__ __launch_bounds__(256, 2) void gemm_proj_kern(
    const float* __restrict__ B, const float* __restrict__ bias,
    float* __restrict__ C)
{
    const int bm = blockIdx.y * 128;
    const int bn = blockIdx.x * 128;
    float acc[4][4][4];
#pragma unroll
    for (int a = 0; a < 4; a++)
#pragma unroll
        for (int b = 0; b < 4; b++)
#pragma unroll
            for (int cc = 0; cc < 4; cc++) acc[a][b][cc] = 0.0f;

    gemm_db1(g_attn, B, bm, bn, NSEQ, dynsm, acc);

    const int tid = threadIdx.x;
    const int wid = tid >> 5, lane = tid & 31;
    const int warp_m = wid & 1, warp_n = wid >> 1;
    const int grp = lane >> 2, tig = lane & 3;

#pragma unroll
    for (int mt = 0; mt < 4; ++mt)
#pragma unroll
        for (int half = 0; half < 2; ++half) {
            const int row = bm + warp_m * 64 + mt * 16 + grp + half * 8;
            if (row >= NSEQ) continue;
#pragma unroll
            for (int nt = 0; nt < 4; ++nt) {
                const int col = bn + warp_n * 32 + nt * 8 + tig * 2;
                float2 v;
                v.x = acc[mt][nt][half * 2 + 0] + bias[col];
                v.y = acc[mt][nt][half * 2 + 1] + bias[col + 1];
                *(float2*)&C[(size_t)row * 1024 + col] = v;
            }
        }
}

// ============================================================
// RoPE on q and k, rows PREFIX..NSEQ-1
// ============================================================
__global__ void rope_kernel(const float* __restrict__ rope)
{
    int idx = blockIdx.x * blockDim.x + threadIdx.x;
    if (idx >= HWLEN * NH * 32) return;
    const int d = idx & 31;
    const int h = (idx >> 5) & 15;
    const int p = idx >> 9;
    const int n = PREFIX + p;

    const float s0 = rope[p * 64 + d];
    const float s1 = rope[p * 64 + d + 32];
    const float c0 = rope[HWLEN * 64 + p * 64 + d];
    const float c1 = rope[HWLEN * 64 + p * 64 + d + 32];

    const size_t base = ((size_t)h * NPAD + n) * DH;

    float q0 = g_q[base + d], q1 = g_q[base + d + 32];
    g_q[base + d]      = q0 * c0 - q1 * s0;
    g_q[base + d + 32] = q1 * c1 + q0 * s1;

    float k0 = g_k[base + d], k1 = g_k[base + d + 32];
    g_k[base + d]      = k0 * c0 - k1 * s0;
    g_k[base + d + 32] = k1 * c1 + k0 * s1;
}

// ============================================================
// Flash attention v7: warp = 32 q-rows (2 m-tiles) x 32 keys.
// 4 warps -> q-tile 128. K/V/P fragments amortized over 2 m-tiles.
// grid (13, 16), 128 threads, smem 76.8 KB, 2 CTAs/SM.
// ============================================================
#define AQ_H 0                       // Q hi: 128*36 = 4608 words
#define AQ_L 4608
#define AK_H 9216                    // K hi: 32*36 = 1152
#define AK_L 10368
#define AV_H 11520                   // V hi: 64*20 = 1280
#define AV_L 12800
#define AP   14080                   // 4 warps * 1280 (hi 640 + lo 640)
#define ATTN_SMEM_BYTES (19200 * 4)  // 76800 B

__global__ __launch_bounds__(128, 2) void attn_bf16()
{
    uint32_t* usm = (uint32_t*)dynsm;
    uint32_t* Qh = usm + AQ_H;
    uint32_t* Ql = usm + AQ_L;
    uint32_t* Kh = usm + AK_H;
    uint32_t* Kl = usm + AK_L;
    uint32_t* Vh = usm + AV_H;
    uint32_t* Vl = usm + AV_L;

    const int h  = blockIdx.y;
    const int qb = blockIdx.x * 128;
    const int tid = threadIdx.x;
    const int wid = tid >> 5, lane = tid & 31;
    const int grp = lane >> 2, tig = lane & 3;
    const int row0 = wid * 32;

    uint32_t* Ph = usm + AP + wid * 1280;
    uint32_t* Pl = Ph + 640;

    const uint32_t smb = cvta_s(usm);
    const int q_lm  = AQ_H + (row0 + (lane & 15)) * 36 + (lane >> 4) * 4;
    const int q_lml = q_lm + 4608;
    const int k_lm  = AK_H + ((lane >> 4) * 8 + (lane & 7)) * 36 + ((lane >> 3) & 1) * 4;
    const int k_lml = k_lm + 1152;
    const int v_lm  = AV_H + ((lane >> 4) * 8 + (lane & 7)) * 20 + ((lane >> 3) & 1) * 4;
    const int v_lml = v_lm + 1280;
    const int p_lm  = AP + wid * 1280 + (lane & 15) * 20 + (lane >> 4) * 4;
    const int p_lml = p_lm + 640;

    const float* __restrict__ Qg = g_q + (size_t)h * NPAD * DH;
    const float* __restrict__ Kg = g_k + (size_t)h * NPAD * DH;
    const float* __restrict__ Vg = g_v + (size_t)h * NPAD * DH;

    // ---- prologue: Q tile 128x64 -> packed bf16x2 hi/lo ----
#pragma unroll
    for (int t = 0; t < 16; ++t) {
        const int idx = tid + t * 128;
        const int r = idx >> 4, c4 = (idx & 15) * 4;
        float4 v = *(const float4*)(Qg + (size_t)(qb + r) * DH + c4);
        uint32_t h0, l0, h1, l1;
        split2(v.x, v.y, h0, l0);
        split2(v.z, v.w, h1, l1);
        Qh[r * 36 + c4 / 2] = h0; Qh[r * 36 + c4 / 2 + 1] = h1;
        Ql[r * 36 + c4 / 2] = l0; Ql[r * 36 + c4 / 2 + 1] = l1;
    }

    // ---- K/V tile 0 ----
    const int lr = tid >> 4;
    const int lc4 = (tid & 15) * 4;
    const int vp = tid & 15;
    const int vdg = tid >> 4;
    float4 pk[4];
    float4 ve0, ve1, vo0, vo1;

#define KV_FETCH(base) do { \
    _Pragma("unroll") \
    for (int t = 0; t < 4; ++t) \
        pk[t] = *(const float4*)(Kg + (size_t)((base) + lr + t * 8) * DH + lc4); \
    ve0 = *(const float4*)(Vg + (size_t)((base) + 2 * vp) * DH + vdg * 8); \
    ve1 = *(const float4*)(Vg + (size_t)((base) + 2 * vp) * DH + vdg * 8 + 4); \
    vo0 = *(const float4*)(Vg + (size_t)((base) + 2 * vp + 1) * DH + vdg * 8); \
    vo1 = *(const float4*)(Vg + (size_t)((base) + 2 * vp + 1) * DH + vdg * 8 + 4); \
} while (0)

#define KV_STORE() do { \
    _Pragma("unroll") \
    for (int t = 0; t < 4; ++t) { \
        const int r = lr + t * 8; \
        uint32_t h0, l0, h1, l1; \
        split2(pk[t].x, pk[t].y, h0, l0); \
        split2(pk[t].z, pk[t].w, h1, l1); \
        Kh[r * 36 + lc4 / 2] = h0; Kh[r * 36 + lc4 / 2 + 1] = h1; \
        Kl[r * 36 + lc4 / 2] = l0; Kl[r * 36 + lc4 / 2 + 1] = l1; \
    } \
    { \
        float ve[8] = {ve0.x, ve0.y, ve0.z, ve0.w, ve1.x, ve1.y, ve1.z, ve1.w}; \
        float vo[8] = {vo0.x, vo0.y, vo0.z, vo0.w, vo1.x, vo1.y, vo1.z, vo1.w}; \
        _Pragma("unroll") \
        for (int j = 0; j < 8; ++j) { \
            const int d = vdg * 8 + j; \
            uint32_t hh, ll; \
            split2(ve[j], vo[j], hh, ll); \
            Vh[d * 20 + vp] = hh; \
            Vl[d * 20 + vp] = ll; \
        } \
    } \
} while (0)

    KV_FETCH(0);
    KV_STORE();
    __syncthreads();

    float mreg[2][2], lreg[2][2];
#pragma unroll
    for (int mt = 0; mt < 2; ++mt) {
        mreg[mt][0] = -1e38f; mreg[mt][1] = -1e38f;
        lreg[mt][0] = 0.0f;   lreg[mt][1] = 0.0f;
    }
    float o[2][8][4];
#pragma unroll
    for (int mt = 0; mt < 2; mt++)
#pragma unroll
        for (int nt = 0; nt < 8; nt++)
#pragma unroll
            for (int i = 0; i < 4; i++) o[mt][nt][i] = 0.0f;

    const int nkt = (NSEQ + 31) / 32;    // 51
    for (int kt = 0; kt < nkt; ++kt) {
        const int key0 = kt * 32;

        // ---- S = Q K^T (bf16x3): 2 m-tiles share K fragments ----
        float sacc[2][4][4];
#pragma unroll
        for (int mt = 0; mt < 2; mt++)
#pragma unroll
            for (int nt = 0; nt < 4; nt++)
#pragma unroll
                for (int i = 0; i < 4; i++) sacc[mt][nt][i] = 0.0f;

#pragma unroll
        for (int ks = 0; ks < 4; ++ks) {
            const int kw = ks * 8;
            uint32_t ah[2][4], al[2][4];
#pragma unroll
            for (int mt = 0; mt < 2; ++mt) {
                LDSM_X4(ah[mt][0], ah[mt][1], ah[mt][2], ah[mt][3],
                        smb + (uint32_t)(q_lm + mt * 576 + kw) * 4u);
                LDSM_X4(al[mt][0], al[mt][1], al[mt][2], al[mt][3],
                        smb + (uint32_t)(q_lml + mt * 576 + kw) * 4u);
            }
#pragma unroll
            for (int ntp = 0; ntp < 2; ++ntp) {
                uint32_t bh0, bh1, bh2, bh3, bl0, bl1, bl2, bl3;
                LDSM_X4(bh0, bh1, bh2, bh3,
                        smb + (uint32_t)(k_lm + ntp * 16 * 36 + kw) * 4u);
                LDSM_X4(bl0, bl1, bl2, bl3,
                        smb + (uint32_t)(k_lml + ntp * 16 * 36 + kw) * 4u);
#pragma unroll
                for (int mt = 0; mt < 2; ++mt) {
                    MMA_BF16(sacc[mt][2 * ntp], ah[mt][0], ah[mt][1], ah[mt][2], ah[mt][3], bh0, bh1);
                    MMA_BF16(sacc[mt][2 * ntp], ah[mt][0], ah[mt][1], ah[mt][2], ah[mt][3], bl0, bl1);
                    MMA_BF16(sacc[mt][2 * ntp], al[mt][0], al[mt][1], al[mt][2], al[mt][3], bh0, bh1);
                    MMA_BF16(sacc[mt][2 * ntp + 1], ah[mt][0], ah[mt][1], ah[mt][2], ah[mt][3], bh2, bh3);
                    MMA_BF16(sacc[mt][2 * ntp + 1], ah[mt][0], ah[mt][1], ah[mt][2], ah[mt][3], bl2, bl3);
                    MMA_BF16(sacc[mt][2 * ntp + 1], al[mt][0], al[mt][1], al[mt][2], al[mt][3], bh2, bh3);
                }
            }
        }

        // ---- prefetch next K/V into regs ----
        if (kt + 1 < nkt) KV_FETCH(key0 + 32);

        // ---- register softmax, per m-tile ----
#pragma unroll
        for (int mt = 0; mt < 2; ++mt) {
            float mx0 = -1e30f, mx1 = -1e30f;
#pragma unroll
            for (int nt = 0; nt < 4; ++nt) {
                const int c0 = key0 + nt * 8 + tig * 2;
                if (c0 >= NSEQ)     { sacc[mt][nt][0] = -1e30f; sacc[mt][nt][2] = -1e30f; }
                if (c0 + 1 >= NSEQ) { sacc[mt][nt][1] = -1e30f; sacc[mt][nt][3] = -1e30f; }
                mx0 = fmaxf(mx0, fmaxf(sacc[mt][nt][0], sacc[mt][nt][1]));
                mx1 = fmaxf(mx1, fmaxf(sacc[mt][nt][2], sacc[mt][nt][3]));
            }
            mx0 = fmaxf(mx0, __shfl_xor_sync(0xffffffffu, mx0, 1));
            mx0 = fmaxf(mx0, __shfl_xor_sync(0xffffffffu, mx0, 2));
            mx1 = fmaxf(mx1, __shfl_xor_sync(0xffffffffu, mx1, 1));
            mx1 = fmaxf(mx1, __shfl_xor_sync(0xffffffffu, mx1, 2));

            const float mn0 = fmaxf(mreg[mt][0], mx0);
            const float mn1 = fmaxf(mreg[mt][1], mx1);
            const float a0 = __expf(mreg[mt][0] - mn0);
            const float a1 = __expf(mreg[mt][1] - mn1);
            mreg[mt][0] = mn0; mreg[mt][1] = mn1;

            float s0 = 0.0f, s1 = 0.0f;
#pragma unroll
            for (int nt = 0; nt < 4; ++nt) {
                sacc[mt][nt][0] = __expf(sacc[mt][nt][0] - mn0); s0 += sacc[mt][nt][0];
                sacc[mt][nt][1] = __expf(sacc[mt][nt][1] - mn0); s0 += sacc[mt][nt][1];
                sacc[mt][nt][2] = __expf(sacc[mt][nt][2] - mn1); s1 += sacc[mt][nt][2];
                sacc[mt][nt][3] = __expf(sacc[mt][nt][3] - mn1); s1 += sacc[mt][nt][3];
            }
            s0 += __shfl_xor_sync(0xffffffffu, s0, 1);
            s0 += __shfl_xor_sync(0xffffffffu, s0, 2);
            s1 += __shfl_xor_sync(0xffffffffu, s1, 1);
            s1 += __shfl_xor_sync(0xffffffffu, s1, 2);
            lreg[mt][0] = lreg[mt][0] * a0 + s0;
            lreg[mt][1] = lreg[mt][1] * a1 + s1;

            // pack P hi/lo straight from registers
#pragma unroll
            for (int nt = 0; nt < 4; ++nt) {
                const int cw = nt * 4 + tig;
                const int rb = mt * 16;
                uint32_t hh, ll;
                split2(sacc[mt][nt][0], sacc[mt][nt][1], hh, ll);
                Ph[(rb + grp) * 20 + cw] = hh; Pl[(rb + grp) * 20 + cw] = ll;
                split2(sacc[mt][nt][2], sacc[mt][nt][3], hh, ll);
                Ph[(rb + grp + 8) * 20 + cw] = hh; Pl[(rb + grp + 8) * 20 + cw] = ll;
            }

            // rescale O for this m-tile
#pragma unroll
            for (int nt = 0; nt < 8; ++nt) {
                o[mt][nt][0] *= a0; o[mt][nt][1] *= a0;
                o[mt][nt][2] *= a1; o[mt][nt][3] *= a1;
            }
        }
        __syncwarp();

        // ---- O += P V (bf16x3): 2 m-tiles share V fragments ----
#pragma unroll
        for (int kk = 0; kk < 2; ++kk) {
            const int kw = kk * 8;
            uint32_t ph[2][4], pl[2][4];
#pragma unroll
            for (int mt = 0; mt < 2; ++mt) {
                LDSM_X4(ph[mt][0], ph[mt][1], ph[mt][2], ph[mt][3],
                        smb + (uint32_t)(p_lm + mt * 320 + kw) * 4u);
                LDSM_X4(pl[mt][0], pl[mt][1], pl[mt][2], pl[mt][3],
                        smb + (uint32_t)(p_lml + mt * 320 + kw) * 4u);
            }
#pragma unroll
            for (int ntp = 0; ntp < 4; ++ntp) {
                uint32_t vh0, vh1, vh2, vh3, vl0, vl1, vl2, vl3;
                LDSM_X4(vh0, vh1, vh2, vh3,
                        smb + (uint32_t)(v_lm + ntp * 16 * 20 + kw) * 4u);
                LDSM_X4(vl0, vl1, vl2, vl3,
                        smb + (uint32_t)(v_lml + ntp * 16 * 20 + kw) * 4u);
#pragma unroll
                for (int mt = 0; mt < 2; ++mt) {
                    MMA_BF16(o[mt][2 * ntp], ph[mt][0], ph[mt][1], ph[mt][2], ph[mt][3], vh0, vh1);
                    MMA_BF16(o[mt][2 * ntp], ph[mt][0], ph[mt][1], ph[mt][2], ph[mt][3], vl0, vl1);
                    MMA_BF16(o[mt][2 * ntp], pl[mt][0], pl[mt][1], pl[mt][2], pl[mt][3], vh0, vh1);
                    MMA_BF16(o[mt][2 * ntp + 1], ph[mt][0], ph[mt][1], ph[mt][2], ph[mt][3], vh2, vh3);
                    MMA_BF16(o[mt][2 * ntp + 1], ph[mt][0], ph[mt][1], ph[mt][2], ph[mt][3], vl2, vl3);
                    MMA_BF16(o[mt][2 * ntp + 1], pl[mt][0], pl[mt][1], pl[mt][2], pl[mt][3], vh2, vh3);
                }
            }
        }
        __syncthreads();

        // ---- store prefetched K/V tile ----
        if (kt + 1 < nkt) {
            KV_STORE();
            __syncthreads();
        }
    }

    // ---- epilogue ----
#pragma unroll
    for (int mt = 0; mt < 2; ++mt) {
        const float inv0 = 1.0f / lreg[mt][0];
        const float inv1 = 1.0f / lreg[mt][1];
        const int n0 = qb + row0 + mt * 16 + grp;
        const int n1 = n0 + 8;
#pragma unroll
        for (int nt = 0; nt < 8; ++nt) {
            const int col = h * DH + nt * 8 + tig * 2;
            if (n0 < NSEQ)
                *(float2*)&g_attn[(size_t)n0 * DIMF + col] =
                    make_float2(o[mt][nt][0] * inv0, o[mt][nt][1] * inv0);
            if (n1 < NSEQ)
                *(float2*)&g_attn[(size_t)n1 * DIMF + col] =
                    make_float2(o[mt][nt][2] * inv1, o[mt][nt][3] * inv1);
        }
    }
}

// ============================================================
extern "C" void kernel_launch(void* const* d_in, const int* in_sizes, int n_in,
                              void* d_out, int out_size)
{
    (void)in_sizes; (void)n_in; (void)out_size;
    const float* x     = (const float*)d_in[0];
    const float* rope  = (const float*)d_in[1];
    const float* Wqkv  = (const float*)d_in[2];
    const float* Wproj = (const float*)d_in[3];
    const float* bproj = (const float*)d_in[4];
    float* out = (float*)d_out;

    static int configured = 0;
    if (!configured) {
        cudaFuncSetAttribute(gemm_qk_kern,   cudaFuncAttributeMaxDynamicSharedMemorySize, GSMEM_QK);
        cudaFuncSetAttribute(gemm_v_kern,    cudaFuncAttributeMaxDynamicSharedMemorySize, GSMEM_B);
        cudaFuncSetAttribute(gemm_proj_kern, cudaFuncAttributeMaxDynamicSharedMemorySize, GSMEM_B);
        cudaFuncSetAttribute(attn_bf16,      cudaFuncAttributeMaxDynamicSharedMemorySize, ATTN_SMEM_BYTES);
        configured = 1;
    }

    gemm_qk_kern<<<dim3(16, 13), 256, GSMEM_QK>>>(x, Wqkv);
    gemm_v_kern<<<dim3(8, 13), 256, GSMEM_B>>>(x, Wqkv);
    rope_kernel<<<(HWLEN * NH * 32 + 255) / 256, 256>>>(rope);
    attn_bf16<<<dim3(13, NH), 128, ATTN_SMEM_BYTES>>>();
    gemm_proj_kern<<<dim3(8, 13), 256, GSMEM_B>>>(Wproj, bproj, out);
}

// round 11
// speedup vs baseline: 2.8364x; 1.0314x over previous
#include <cuda_runtime.h>
#include <cstdint>

#define NSEQ   1605
#define DIMF   1024
#define NH     16
#define DH     64
#define HWLEN  1600
#define PREFIX 5
#define NPAD   1664   // 26 * 64
#define NSPLIT 2
#define NKT_TOT 51
#define NKT0   26

// ---- scratch (device globals; zero-initialized at module load) ----
__device__ float g_q[(size_t)NH * NPAD * DH];
__device__ float g_k[(size_t)NH * NPAD * DH];
__device__ float g_v[(size_t)NH * NPAD * DH];
__device__ float g_attn[(size_t)NSEQ * DIMF];
__device__ float  g_part[(size_t)NSPLIT * NH * NPAD * DH];
__device__ float2 g_ml[(size_t)NSPLIT * NH * NPAD];

// ============================================================
// mma / ldmatrix helpers
// ============================================================
__device__ __forceinline__ uint32_t f2tf32(float a) {
    uint32_t u; asm("cvt.rna.tf32.f32 %0, %1;" : "=r"(u) : "f"(a));
    return u;
}
__device__ __forceinline__ uint32_t cvta_s(const void* p) {
    uint32_t a;
    asm("{ .reg .u64 t; cvta.to.shared.u64 t, %1; cvt.u32.u64 %0, t; }"
        : "=r"(a) : "l"(p));
    return a;
}

#define MMA_TF32(d, a0, a1, a2, a3, b0, b1) \
    asm volatile("mma.sync.aligned.m16n8k8.row.col.f32.tf32.tf32.f32 " \
        "{%0,%1,%2,%3}, {%4,%5,%6,%7}, {%8,%9}, {%0,%1,%2,%3};" \
        : "+f"((d)[0]), "+f"((d)[1]), "+f"((d)[2]), "+f"((d)[3]) \
        : "r"(a0), "r"(a1), "r"(a2), "r"(a3), "r"(b0), "r"(b1))

#define MMA_BF16(d, a0, a1, a2, a3, b0, b1) \
    asm volatile("mma.sync.aligned.m16n8k16.row.col.f32.bf16.bf16.f32 " \
        "{%0,%1,%2,%3}, {%4,%5,%6,%7}, {%8,%9}, {%0,%1,%2,%3};" \
        : "+f"((d)[0]), "+f"((d)[1]), "+f"((d)[2]), "+f"((d)[3]) \
        : "r"(a0), "r"(a1), "r"(a2), "r"(a3), "r"(b0), "r"(b1))

#define LDSM_X4(r0, r1, r2, r3, addr) \
    asm volatile("ldmatrix.sync.aligned.m8n8.x4.shared.b16 {%0,%1,%2,%3}, [%4];" \
        : "=r"(r0), "=r"(r1), "=r"(r2), "=r"(r3) : "r"(addr))

__device__ __forceinline__ uint32_t pack_bf16x2(float lo, float hi) {
    uint32_t w;
    asm("cvt.rn.bf16x2.f32 %0, %1, %2;" : "=r"(w) : "f"(hi), "f"(lo));
    return w;
}
__device__ __forceinline__ float lo_bf16(uint32_t w) { return __uint_as_float(w << 16); }
__device__ __forceinline__ float hi_bf16(uint32_t w) { return __uint_as_float(w & 0xFFFF0000u); }

__device__ __forceinline__ void split2(float e, float o, uint32_t& h, uint32_t& l) {
    h = pack_bf16x2(e, o);
    l = pack_bf16x2(e - lo_bf16(h), o - hi_bf16(h));
}

__device__ __forceinline__ void hi4(const float4 v, float4& hi) {
    hi.x = __uint_as_float(f2tf32(v.x));
    hi.y = __uint_as_float(f2tf32(v.y));
    hi.z = __uint_as_float(f2tf32(v.z));
    hi.w = __uint_as_float(f2tf32(v.w));
}

extern __shared__ float dynsm[];

// ============================================================
// bf16x3 GEMM (qk): unchanged from round 10
// ============================================================
#define BST 12
#define BTILE (128 * BST)

__device__ __forceinline__ void gemm_db3b(
    const float* __restrict__ A, const float* __restrict__ B,
    int bm, int bn, int aRows, uint32_t* __restrict__ smem,
    float acc[4][4][4])
{
    const int tid = threadIdx.x;
    const int wid = tid >> 5, lane = tid & 31;
    const int warp_m = wid & 1, warp_n = wid >> 1;
    const int r0 = tid >> 2;
    const int f0 = (tid & 3) * 4;
    const int w0 = (tid & 3) * 2;

    const uint32_t smb = cvta_s(smem);
    const int a_lm = (warp_m * 64 + (lane & 15)) * BST + (lane >> 4) * 4;
    const int b_lm = (warp_n * 32 + (lane >> 4) * 8 + (lane & 7)) * BST
                     + ((lane >> 3) & 1) * 4;

    float4 pa[2], pb[2];

#define GB_LOAD(k0) do { \
    _Pragma("unroll") \
    for (int t = 0; t < 2; ++t) { \
        const int r = r0 + t * 64; \
        pa[t] = make_float4(0.f, 0.f, 0.f, 0.f); \
        if (bm + r < aRows) \
            pa[t] = *(const float4*)(A + (size_t)(bm + r) * 1024 + (k0) + f0); \
        pb[t] = *(const float4*)(B + (size_t)(bn + r) * 1024 + (k0) + f0); \
    } } while (0)

#define GB_STORE(bufp) do { \
    uint32_t* Ah_ = (bufp); \
    uint32_t* Al_ = (bufp) + BTILE; \
    uint32_t* Bh_ = (bufp) + 2 * BTILE; \
    uint32_t* Bl_ = (bufp) + 3 * BTILE; \
    _Pragma("unroll") \
    for (int t = 0; t < 2; ++t) { \
        const int r = r0 + t * 64; \
        uint32_t h0, l0, h1, l1; \
        split2(pa[t].x, pa[t].y, h0, l0); \
        split2(pa[t].z, pa[t].w, h1, l1); \
        Ah_[r * BST + w0] = h0; Ah_[r * BST + w0 + 1] = h1; \
        Al_[r * BST + w0] = l0; Al_[r * BST + w0 + 1] = l1; \
        split2(pb[t].x, pb[t].y, h0, l0); \
        split2(pb[t].z, pb[t].w, h1, l1); \
        Bh_[r * BST + w0] = h0; Bh_[r * BST + w0 + 1] = h1; \
        Bl_[r * BST + w0] = l0; Bl_[r * BST + w0 + 1] = l1; \
    } } while (0)

    GB_LOAD(0);
    GB_STORE(smem);
    __syncthreads();

    for (int c = 0; c < 64; ++c) {
        const int bufw = (c & 1) * (4 * BTILE);
        if (c < 63) GB_LOAD((c + 1) * 16);

        uint32_t ah[4][4], al[4][4];
#pragma unroll
        for (int mt = 0; mt < 4; ++mt) {
            LDSM_X4(ah[mt][0], ah[mt][1], ah[mt][2], ah[mt][3],
                    smb + (uint32_t)(bufw + a_lm + mt * 16 * BST) * 4u);
            LDSM_X4(al[mt][0], al[mt][1], al[mt][2], al[mt][3],
                    smb + (uint32_t)(bufw + BTILE + a_lm + mt * 16 * BST) * 4u);
        }
#pragma unroll
        for (int ntp = 0; ntp < 2; ++ntp) {
            uint32_t bh0, bh1, bh2, bh3, bl0, bl1, bl2, bl3;
            LDSM_X4(bh0, bh1, bh2, bh3,
                    smb + (uint32_t)(bufw + 2 * BTILE + b_lm + ntp * 16 * BST) * 4u);
            LDSM_X4(bl0, bl1, bl2, bl3,
                    smb + (uint32_t)(bufw + 3 * BTILE + b_lm + ntp * 16 * BST) * 4u);
#pragma unroll
            for (int mt = 0; mt < 4; ++mt) {
                MMA_BF16(acc[mt][2 * ntp], ah[mt][0], ah[mt][1], ah[mt][2], ah[mt][3], bh0, bh1);
                MMA_BF16(acc[mt][2 * ntp], ah[mt][0], ah[mt][1], ah[mt][2], ah[mt][3], bl0, bl1);
                MMA_BF16(acc[mt][2 * ntp], al[mt][0], al[mt][1], al[mt][2], al[mt][3], bh0, bh1);
                MMA_BF16(acc[mt][2 * ntp + 1], ah[mt][0], ah[mt][1], ah[mt][2], ah[mt][3], bh2, bh3);
                MMA_BF16(acc[mt][2 * ntp + 1], ah[mt][0], ah[mt][1], ah[mt][2], ah[mt][3], bl2, bl3);
                MMA_BF16(acc[mt][2 * ntp + 1], al[mt][0], al[mt][1], al[mt][2], al[mt][3], bh2, bh3);
            }
        }
        if (c < 63) GB_STORE(smem + ((c + 1) & 1) * (4 * BTILE));
        __syncthreads();
    }
#undef GB_LOAD
#undef GB_STORE
}

#define GSMEM_QK (2 * 4 * BTILE * 4)

// ============================================================
// 1xTF32 GEMM (pre-converted hi in smem) — v and proj
// ============================================================
#define GST 20
#define GTILE (128 * GST)

__device__ __forceinline__ void gemm_db1(
    const float* __restrict__ A, const float* __restrict__ B,
    int bm, int bn, int aRows, float* __restrict__ smem,
    float acc[4][4][4])
{
    const int tid = threadIdx.x;
    const int wid = tid >> 5, lane = tid & 31;
    const int warp_m = wid & 1, warp_n = wid >> 1;
    const int grp = lane >> 2, tig = lane & 3;
    const int r0 = tid >> 2;
    const int f0 = (tid & 3) * 4;

    float4 pa[2], pb[2];

#define G1_LOAD(k0) do { \
    _Pragma("unroll") \
    for (int t = 0; t < 2; ++t) { \
        const int r = r0 + t * 64; \
        pa[t] = make_float4(0.f, 0.f, 0.f, 0.f); \
        if (bm + r < aRows) \
            pa[t] = *(const float4*)(A + (size_t)(bm + r) * 1024 + (k0) + f0); \
        pb[t] = *(const float4*)(B + (size_t)(bn + r) * 1024 + (k0) + f0); \
    } } while (0)

#define G1_STORE(bufp) do { \
    float* Ah_ = (bufp); \
    float* Bh_ = (bufp) + GTILE; \
    _Pragma("unroll") \
    for (int t = 0; t < 2; ++t) { \
        const int r = r0 + t * 64; \
        float4 hi; \
        hi4(pa[t], hi); *(float4*)(Ah_ + r * GST + f0) = hi; \
        hi4(pb[t], hi); *(float4*)(Bh_ + r * GST + f0) = hi; \
    } } while (0)

    G1_LOAD(0);
    G1_STORE(smem);
    __syncthreads();

    for (int c = 0; c < 64; ++c) {
        float* cur = smem + (c & 1) * (2 * GTILE);
        if (c < 63) G1_LOAD((c + 1) * 16);

        float* Ah = cur;
        float* Bh = cur + GTILE;

#pragma unroll
        for (int ks = 0; ks < 2; ++ks) {
            const int kc = ks * 8 + tig;
            uint32_t ah[4][4];
#pragma unroll
            for (int mt = 0; mt < 4; ++mt) {
                const int ra = (warp_m * 64 + mt * 16 + grp) * GST;
                ah[mt][0] = __float_as_uint(Ah[ra + kc]);
                ah[mt][1] = __float_as_uint(Ah[ra + 8 * GST + kc]);
                ah[mt][2] = __float_as_uint(Ah[ra + kc + 4]);
                ah[mt][3] = __float_as_uint(Ah[ra + 8 * GST + kc + 4]);
            }
#pragma unroll
            for (int nt = 0; nt < 4; ++nt) {
                const int rb = (warp_n * 32 + nt * 8 + grp) * GST + kc;
                uint32_t bh0 = __float_as_uint(Bh[rb]);
                uint32_t bh1 = __float_as_uint(Bh[rb + 4]);
#pragma unroll
                for (int mt = 0; mt < 4; ++mt)
                    MMA_TF32(acc[mt][nt], ah[mt][0], ah[mt][1], ah[mt][2], ah[mt][3], bh0, bh1);
            }
        }
        if (c < 63) G1_STORE(smem + ((c + 1) & 1) * (2 * GTILE));
        __syncthreads();
    }
#undef G1_LOAD
#undef G1_STORE
}

#define GSMEM_B (2 * 2 * GTILE * 4)

// ---- qkv (q,k columns): bf16x3 ----
__global__ __launch_bounds__(256, 2) void gemm_qk_kern(
    const float* __restrict__ A, const float* __restrict__ B)
{
    const int bm = blockIdx.y * 128;
    const int bn = blockIdx.x * 128;
    float acc[4][4][4];
#pragma unroll
    for (int a = 0; a < 4; a++)
#pragma unroll
        for (int b = 0; b < 4; b++)
#pragma unroll
            for (int cc = 0; cc < 4; cc++) acc[a][b][cc] = 0.0f;

    gemm_db3b(A, B, bm, bn, NSEQ, (uint32_t*)dynsm, acc);

    const int tid = threadIdx.x;
    const int wid = tid >> 5, lane = tid & 31;
    const int warp_m = wid & 1, warp_n = wid >> 1;
    const int grp = lane >> 2, tig = lane & 3;

    const int s = bn >> 10;
    float* __restrict__ dst = (s == 0) ? g_q : g_k;
    const float scale = (s == 0) ? 0.125f : 1.0f;

#pragma unroll
    for (int mt = 0; mt < 4; ++mt)
#pragma unroll
        for (int half = 0; half < 2; ++half) {
            const int row = bm + warp_m * 64 + mt * 16 + grp + half * 8;
            if (row >= NSEQ) continue;
#pragma unroll
            for (int nt = 0; nt < 4; ++nt) {
                const int col = bn + warp_n * 32 + nt * 8 + tig * 2;
                const int h = (col & 1023) >> 6;
                const int d = col & 63;
                float2 v;
                v.x = acc[mt][nt][half * 2 + 0] * scale;
                v.y = acc[mt][nt][half * 2 + 1] * scale;
                *(float2*)&dst[((size_t)h * NPAD + row) * DH + d] = v;
            }
        }
}

// ---- qkv (v columns): 1xTF32 ----
__global__ __launch_bounds__(256, 2) void gemm_v_kern(
    const float* __restrict__ A, const float* __restrict__ B)
{
    const int bm = blockIdx.y * 128;
    const int bn = 2048 + blockIdx.x * 128;
    float acc[4][4][4];
#pragma unroll
    for (int a = 0; a < 4; a++)
#pragma unroll
        for (int b = 0; b < 4; b++)
#pragma unroll
            for (int cc = 0; cc < 4; cc++) acc[a][b][cc] = 0.0f;

    gemm_db1(A, B, bm, bn, NSEQ, dynsm, acc);

    const int tid = threadIdx.x;
    const int wid = tid >> 5, lane = tid & 31;
    const int warp_m = wid & 1, warp_n = wid >> 1;
    const int grp = lane >> 2, tig = lane & 3;

#pragma unroll
    for (int mt = 0; mt < 4; ++mt)
#pragma unroll
        for (int half = 0; half < 2; ++half) {
            const int row = bm + warp_m * 64 + mt * 16 + grp + half * 8;
            if (row >= NSEQ) continue;
#pragma unroll
            for (int nt = 0; nt < 4; ++nt) {
                const int col = bn + warp_n * 32 + nt * 8 + tig * 2;
                const int h = (col & 1023) >> 6;
                const int d = col & 63;
                float2 v;
                v.x = acc[mt][nt][half * 2 + 0];
                v.y = acc[mt][nt][half * 2 + 1];
                *(float2*)&g_v[((size_t)h * NPAD + row) * DH + d] = v;
            }
        }
}

// ---- proj: 1xTF32 + bias ----
__global__ __launch_bounds__(256, 2) void gemm_proj_kern(
    const float* __restrict__ B, const float* __restrict__ bias,
    float* __restrict__ C)
{
    const int bm = blockIdx.y * 128;
    const int bn = blockIdx.x * 128;
    float acc[4][4][4];
#pragma unroll
    for (int a = 0; a < 4; a++)
#pragma unroll
        for (int b = 0; b < 4; b++)
#pragma unroll
            for (int cc = 0; cc < 4; cc++) acc[a][b][cc] = 0.0f;

    gemm_db1(g_attn, B, bm, bn, NSEQ, dynsm, acc);

    const int tid = threadIdx.x;
    const int wid = tid >> 5, lane = tid & 31;
    const int warp_m = wid & 1, warp_n = wid >> 1;
    const int grp = lane >> 2, tig = lane & 3;

#pragma unroll
    for (int mt = 0; mt < 4; ++mt)
#pragma unroll
        for (int half = 0; half < 2; ++half) {
            const int row = bm + warp_m * 64 + mt * 16 + grp + half * 8;
            if (row >= NSEQ) continue;
#pragma unroll
            for (int nt = 0; nt < 4; ++nt) {
                const int col = bn + warp_n * 32 + nt * 8 + tig * 2;
                float2 v;
                v.x = acc[mt][nt][half * 2 + 0] + bias[col];
                v.y = acc[mt][nt][half * 2 + 1] + bias[col + 1];
                *(float2*)&C[(size_t)row * 1024 + col] = v;
            }
        }
}

// ============================================================
// RoPE on q and k, rows PREFIX..NSEQ-1
// ============================================================
__global__ void rope_kernel(const float* __restrict__ rope)
{
    int idx = blockIdx.x * blockDim.x + threadIdx.x;
    if (idx >= HWLEN * NH * 32) return;
    const int d = idx & 31;
    const int h = (idx >> 5) & 15;
    const int p = idx >> 9;
    const int n = PREFIX + p;

    const float s0 = rope[p * 64 + d];
    const float s1 = rope[p * 64 + d + 32];
    const float c0 = rope[HWLEN * 64 + p * 64 + d];
    const float c1 = rope[HWLEN * 64 + p * 64 + d + 32];

    const size_t base = ((size_t)h * NPAD + n) * DH;

    float q0 = g_q[base + d], q1 = g_q[base + d + 32];
    g_q[base + d]      = q0 * c0 - q1 * s0;
    g_q[base + d + 32] = q1 * c1 + q0 * s1;

    float k0 = g_k[base + d], k1 = g_k[base + d + 32];
    g_k[base + d]      = k0 * c0 - k1 * s0;
    g_k[base + d + 32] = k1 * c1 + k0 * s1;
}

// ============================================================
// Flash attention v8: split-K (2 splits), warp = 32 q-rows x 32 keys.
// grid (13, 16, 2), 128 threads, launch_bounds(128,3) -> 1 wave.
// Partials (normalized O, m, l) to g_part/g_ml; combine kernel merges.
// ============================================================
#define AQ_H 0
#define AQ_L 4608
#define AK_H 9216
#define AK_L 10368
#define AV_H 11520
#define AV_L 12800
#define AP   14080
#define ATTN_SMEM_BYTES (19200 * 4)  // 76800 B

__global__ __launch_bounds__(128, 3) void attn_bf16()
{
    uint32_t* usm = (uint32_t*)dynsm;
    uint32_t* Qh = usm + AQ_H;
    uint32_t* Ql = usm + AQ_L;
    uint32_t* Kh = usm + AK_H;
    uint32_t* Kl = usm + AK_L;
    uint32_t* Vh = usm + AV_H;
    uint32_t* Vl = usm + AV_L;

    const int h  = blockIdx.y;
    const int z  = blockIdx.z;
    const int qb = blockIdx.x * 128;
    const int tid = threadIdx.x;
    const int wid = tid >> 5, lane = tid & 31;
    const int grp = lane >> 2, tig = lane & 3;
    const int row0 = wid * 32;

    const int ktb = z * NKT0;
    const int kte = (z == 0) ? NKT0 : NKT_TOT;

    uint32_t* Ph = usm + AP + wid * 1280;
    uint32_t* Pl = Ph + 640;

    const uint32_t smb = cvta_s(usm);
    const int q_lm  = AQ_H + (row0 + (lane & 15)) * 36 + (lane >> 4) * 4;
    const int q_lml = q_lm + 4608;
    const int k_lm  = AK_H + ((lane >> 4) * 8 + (lane & 7)) * 36 + ((lane >> 3) & 1) * 4;
    const int k_lml = k_lm + 1152;
    const int v_lm  = AV_H + ((lane >> 4) * 8 + (lane & 7)) * 20 + ((lane >> 3) & 1) * 4;
    const int v_lml = v_lm + 1280;
    const int p_lm  = AP + wid * 1280 + (lane & 15) * 20 + (lane >> 4) * 4;
    const int p_lml = p_lm + 640;

    const float* __restrict__ Qg = g_q + (size_t)h * NPAD * DH;
    const float* __restrict__ Kg = g_k + (size_t)h * NPAD * DH;
    const float* __restrict__ Vg = g_v + (size_t)h * NPAD * DH;

    // ---- prologue: Q tile 128x64 -> packed bf16x2 hi/lo ----
#pragma unroll
    for (int t = 0; t < 16; ++t) {
        const int idx = tid + t * 128;
        const int r = idx >> 4, c4 = (idx & 15) * 4;
        float4 v = *(const float4*)(Qg + (size_t)(qb + r) * DH + c4);
        uint32_t h0, l0, h1, l1;
        split2(v.x, v.y, h0, l0);
        split2(v.z, v.w, h1, l1);
        Qh[r * 36 + c4 / 2] = h0; Qh[r * 36 + c4 / 2 + 1] = h1;
        Ql[r * 36 + c4 / 2] = l0; Ql[r * 36 + c4 / 2 + 1] = l1;
    }

    // ---- K/V tile ----
    const int lr = tid >> 4;
    const int lc4 = (tid & 15) * 4;
    const int vp = tid & 15;
    const int vdg = tid >> 4;
    float4 pk[4];
    float4 ve0, ve1, vo0, vo1;

#define KV_FETCH(base) do { \
    _Pragma("unroll") \
    for (int t = 0; t < 4; ++t) \
        pk[t] = *(const float4*)(Kg + (size_t)((base) + lr + t * 8) * DH + lc4); \
    ve0 = *(const float4*)(Vg + (size_t)((base) + 2 * vp) * DH + vdg * 8); \
    ve1 = *(const float4*)(Vg + (size_t)((base) + 2 * vp) * DH + vdg * 8 + 4); \
    vo0 = *(const float4*)(Vg + (size_t)((base) + 2 * vp + 1) * DH + vdg * 8); \
    vo1 = *(const float4*)(Vg + (size_t)((base) + 2 * vp + 1) * DH + vdg * 8 + 4); \
} while (0)

#define KV_STORE() do { \
    _Pragma("unroll") \
    for (int t = 0; t < 4; ++t) { \
        const int r = lr + t * 8; \
        uint32_t h0, l0, h1, l1; \
        split2(pk[t].x, pk[t].y, h0, l0); \
        split2(pk[t].z, pk[t].w, h1, l1); \
        Kh[r * 36 + lc4 / 2] = h0; Kh[r * 36 + lc4 / 2 + 1] = h1; \
        Kl[r * 36 + lc4 / 2] = l0; Kl[r * 36 + lc4 / 2 + 1] = l1; \
    } \
    { \
        float ve[8] = {ve0.x, ve0.y, ve0.z, ve0.w, ve1.x, ve1.y, ve1.z, ve1.w}; \
        float vo[8] = {vo0.x, vo0.y, vo0.z, vo0.w, vo1.x, vo1.y, vo1.z, vo1.w}; \
        _Pragma("unroll") \
        for (int j = 0; j < 8; ++j) { \
            const int d = vdg * 8 + j; \
            uint32_t hh, ll; \
            split2(ve[j], vo[j], hh, ll); \
            Vh[d * 20 + vp] = hh; \
            Vl[d * 20 + vp] = ll; \
        } \
    } \
} while (0)

    KV_FETCH(ktb * 32);
    KV_STORE();
    __syncthreads();

    float mreg[2][2], lreg[2][2];
#pragma unroll
    for (int mt = 0; mt < 2; ++mt) {
        mreg[mt][0] = -1e38f; mreg[mt][1] = -1e38f;
        lreg[mt][0] = 0.0f;   lreg[mt][1] = 0.0f;
    }
    float o[2][8][4];
#pragma unroll
    for (int mt = 0; mt < 2; mt++)
#pragma unroll
        for (int nt = 0; nt < 8; nt++)
#pragma unroll
            for (int i = 0; i < 4; i++) o[mt][nt][i] = 0.0f;

    for (int kt = ktb; kt < kte; ++kt) {
        const int key0 = kt * 32;

        // ---- S = Q K^T (bf16x3) ----
        float sacc[2][4][4];
#pragma unroll
        for (int mt = 0; mt < 2; mt++)
#pragma unroll
            for (int nt = 0; nt < 4; nt++)
#pragma unroll
                for (int i = 0; i < 4; i++) sacc[mt][nt][i] = 0.0f;

#pragma unroll
        for (int ks = 0; ks < 4; ++ks) {
            const int kw = ks * 8;
            uint32_t ah[2][4], al[2][4];
#pragma unroll
            for (int mt = 0; mt < 2; ++mt) {
                LDSM_X4(ah[mt][0], ah[mt][1], ah[mt][2], ah[mt][3],
                        smb + (uint32_t)(q_lm + mt * 576 + kw) * 4u);
                LDSM_X4(al[mt][0], al[mt][1], al[mt][2], al[mt][3],
                        smb + (uint32_t)(q_lml + mt * 576 + kw) * 4u);
            }
#pragma unroll
            for (int ntp = 0; ntp < 2; ++ntp) {
                uint32_t bh0, bh1, bh2, bh3, bl0, bl1, bl2, bl3;
                LDSM_X4(bh0, bh1, bh2, bh3,
                        smb + (uint32_t)(k_lm + ntp * 16 * 36 + kw) * 4u);
                LDSM_X4(bl0, bl1, bl2, bl3,
                        smb + (uint32_t)(k_lml + ntp * 16 * 36 + kw) * 4u);
#pragma unroll
                for (int mt = 0; mt < 2; ++mt) {
                    MMA_BF16(sacc[mt][2 * ntp], ah[mt][0], ah[mt][1], ah[mt][2], ah[mt][3], bh0, bh1);
                    MMA_BF16(sacc[mt][2 * ntp], ah[mt][0], ah[mt][1], ah[mt][2], ah[mt][3], bl0, bl1);
                    MMA_BF16(sacc[mt][2 * ntp], al[mt][0], al[mt][1], al[mt][2], al[mt][3], bh0, bh1);
                    MMA_BF16(sacc[mt][2 * ntp + 1], ah[mt][0], ah[mt][1], ah[mt][2], ah[mt][3], bh2, bh3);
                    MMA_BF16(sacc[mt][2 * ntp + 1], ah[mt][0], ah[mt][1], ah[mt][2], ah[mt][3], bl2, bl3);
                    MMA_BF16(sacc[mt][2 * ntp + 1], al[mt][0], al[mt][1], al[mt][2], al[mt][3], bh2, bh3);
                }
            }
        }

        // ---- prefetch next K/V into regs ----
        if (kt + 1 < kte) KV_FETCH((kt + 1) * 32);

        // ---- register softmax, per m-tile ----
#pragma unroll
        for (int mt = 0; mt < 2; ++mt) {
            float mx0 = -1e30f, mx1 = -1e30f;
#pragma unroll
            for (int nt = 0; nt < 4; ++nt) {
                const int c0 = key0 + nt * 8 + tig * 2;
                if (c0 >= NSEQ)     { sacc[mt][nt][0] = -1e30f; sacc[mt][nt][2] = -1e30f; }
                if (c0 + 1 >= NSEQ) { sacc[mt][nt][1] = -1e30f; sacc[mt][nt][3] = -1e30f; }
                mx0 = fmaxf(mx0, fmaxf(sacc[mt][nt][0], sacc[mt][nt][1]));
                mx1 = fmaxf(mx1, fmaxf(sacc[mt][nt][2], sacc[mt][nt][3]));
            }
            mx0 = fmaxf(mx0, __shfl_xor_sync(0xffffffffu, mx0, 1));
            mx0 = fmaxf(mx0, __shfl_xor_sync(0xffffffffu, mx0, 2));
            mx1 = fmaxf(mx1, __shfl_xor_sync(0xffffffffu, mx1, 1));
            mx1 = fmaxf(mx1, __shfl_xor_sync(0xffffffffu, mx1, 2));

            const float mn0 = fmaxf(mreg[mt][0], mx0);
            const float mn1 = fmaxf(mreg[mt][1], mx1);
            const float a0 = __expf(mreg[mt][0] - mn0);
            const float a1 = __expf(mreg[mt][1] - mn1);
            mreg[mt][0] = mn0; mreg[mt][1] = mn1;

            float s0 = 0.0f, s1 = 0.0f;
#pragma unroll
            for (int nt = 0; nt < 4; ++nt) {
                sacc[mt][nt][0] = __expf(sacc[mt][nt][0] - mn0); s0 += sacc[mt][nt][0];
                sacc[mt][nt][1] = __expf(sacc[mt][nt][1] - mn0); s0 += sacc[mt][nt][1];
                sacc[mt][nt][2] = __expf(sacc[mt][nt][2] - mn1); s1 += sacc[mt][nt][2];
                sacc[mt][nt][3] = __expf(sacc[mt][nt][3] - mn1); s1 += sacc[mt][nt][3];
            }
            s0 += __shfl_xor_sync(0xffffffffu, s0, 1);
            s0 += __shfl_xor_sync(0xffffffffu, s0, 2);
            s1 += __shfl_xor_sync(0xffffffffu, s1, 1);
            s1 += __shfl_xor_sync(0xffffffffu, s1, 2);
            lreg[mt][0] = lreg[mt][0] * a0 + s0;
            lreg[mt][1] = lreg[mt][1] * a1 + s1;

#pragma unroll
            for (int nt = 0; nt < 4; ++nt) {
                const int cw = nt * 4 + tig;
                const int rb = mt * 16;
                uint32_t hh, ll;
                split2(sacc[mt][nt][0], sacc[mt][nt][1], hh, ll);
                Ph[(rb + grp) * 20 + cw] = hh; Pl[(rb + grp) * 20 + cw] = ll;
                split2(sacc[mt][nt][2], sacc[mt][nt][3], hh, ll);
                Ph[(rb + grp + 8) * 20 + cw] = hh; Pl[(rb + grp + 8) * 20 + cw] = ll;
            }

#pragma unroll
            for (int nt = 0; nt < 8; ++nt) {
                o[mt][nt][0] *= a0; o[mt][nt][1] *= a0;
                o[mt][nt][2] *= a1; o[mt][nt][3] *= a1;
            }
        }
        __syncwarp();

        // ---- O += P V (bf16x3) ----
#pragma unroll
        for (int kk = 0; kk < 2; ++kk) {
            const int kw = kk * 8;
            uint32_t ph[2][4], pl[2][4];
#pragma unroll
            for (int mt = 0; mt < 2; ++mt) {
                LDSM_X4(ph[mt][0], ph[mt][1], ph[mt][2], ph[mt][3],
                        smb + (uint32_t)(p_lm + mt * 320 + kw) * 4u);
                LDSM_X4(pl[mt][0], pl[mt][1], pl[mt][2], pl[mt][3],
                        smb + (uint32_t)(p_lml + mt * 320 + kw) * 4u);
            }
#pragma unroll
            for (int ntp = 0; ntp < 4; ++ntp) {
                uint32_t vh0, vh1, vh2, vh3, vl0, vl1, vl2, vl3;
                LDSM_X4(vh0, vh1, vh2, vh3,
                        smb + (uint32_t)(v_lm + ntp * 16 * 20 + kw) * 4u);
                LDSM_X4(vl0, vl1, vl2, vl3,
                        smb + (uint32_t)(v_lml + ntp * 16 * 20 + kw) * 4u);
#pragma unroll
                for (int mt = 0; mt < 2; ++mt) {
                    MMA_BF16(o[mt][2 * ntp], ph[mt][0], ph[mt][1], ph[mt][2], ph[mt][3], vh0, vh1);
                    MMA_BF16(o[mt][2 * ntp], ph[mt][0], ph[mt][1], ph[mt][2], ph[mt][3], vl0, vl1);
                    MMA_BF16(o[mt][2 * ntp], pl[mt][0], pl[mt][1], pl[mt][2], pl[mt][3], vh0, vh1);
                    MMA_BF16(o[mt][2 * ntp + 1], ph[mt][0], ph[mt][1], ph[mt][2], ph[mt][3], vh2, vh3);
                    MMA_BF16(o[mt][2 * ntp + 1], ph[mt][0], ph[mt][1], ph[mt][2], ph[mt][3], vl2, vl3);
                    MMA_BF16(o[mt][2 * ntp + 1], pl[mt][0], pl[mt][1], pl[mt][2], pl[mt][3], vh2, vh3);
                }
            }
        }
        __syncthreads();

        // ---- store prefetched K/V tile ----
        if (kt + 1 < kte) {
            KV_STORE();
            __syncthreads();
        }
    }

    // ---- epilogue: write normalized partial O + (m,l) ----
    float* __restrict__ part = g_part + (size_t)(z * NH + h) * NPAD * DH;
    float2* __restrict__ mlp = g_ml + (size_t)(z * NH + h) * NPAD;
#pragma unroll
    for (int mt = 0; mt < 2; ++mt) {
        const float inv0 = 1.0f / lreg[mt][0];
        const float inv1 = 1.0f / lreg[mt][1];
        const int n0 = qb + row0 + mt * 16 + grp;
        const int n1 = n0 + 8;
        if (tig == 0) {
            if (n0 < NSEQ) mlp[n0] = make_float2(mreg[mt][0], lreg[mt][0]);
            if (n1 < NSEQ) mlp[n1] = make_float2(mreg[mt][1], lreg[mt][1]);
        }
#pragma unroll
        for (int nt = 0; nt < 8; ++nt) {
            const int col = nt * 8 + tig * 2;
            if (n0 < NSEQ)
                *(float2*)&part[(size_t)n0 * DH + col] =
                    make_float2(o[mt][nt][0] * inv0, o[mt][nt][1] * inv0);
            if (n1 < NSEQ)
                *(float2*)&part[(size_t)n1 * DH + col] =
                    make_float2(o[mt][nt][2] * inv1, o[mt][nt][3] * inv1);
        }
    }
}

// ============================================================
// Combine split-K partials -> g_attn
// ============================================================
__global__ void attn_combine()
{
    const int t = blockIdx.x * blockDim.x + threadIdx.x;
    if (t >= NH * NSEQ * 16) return;
    const int d4 = (t & 15) * 4;
    const int n = (t >> 4) % NSEQ;
    const int h = t / (16 * NSEQ);

    const float2 ml0 = g_ml[(size_t)(0 * NH + h) * NPAD + n];
    const float2 ml1 = g_ml[(size_t)(1 * NH + h) * NPAD + n];
    const float m = fmaxf(ml0.x, ml1.x);
    float w0 = ml0.y * __expf(ml0.x - m);
    float w1 = ml1.y * __expf(ml1.x - m);
    const float inv = 1.0f / (w0 + w1);
    w0 *= inv; w1 *= inv;

    const float4 o0 = *(const float4*)&g_part[((size_t)(0 * NH + h) * NPAD + n) * DH + d4];
    const float4 o1 = *(const float4*)&g_part[((size_t)(1 * NH + h) * NPAD + n) * DH + d4];
    float4 r;
    r.x = w0 * o0.x + w1 * o1.x;
    r.y = w0 * o0.y + w1 * o1.y;
    r.z = w0 * o0.z + w1 * o1.z;
    r.w = w0 * o0.w + w1 * o1.w;
    *(float4*)&g_attn[(size_t)n * DIMF + h * DH + d4] = r;
}

// ============================================================
extern "C" void kernel_launch(void* const* d_in, const int* in_sizes, int n_in,
                              void* d_out, int out_size)
{
    (void)in_sizes; (void)n_in; (void)out_size;
    const float* x     = (const float*)d_in[0];
    const float* rope  = (const float*)d_in[1];
    const float* Wqkv  = (const float*)d_in[2];
    const float* Wproj = (const float*)d_in[3];
    const float* bproj = (const float*)d_in[4];
    float* out = (float*)d_out;

    static int configured = 0;
    if (!configured) {
        cudaFuncSetAttribute(gemm_qk_kern,   cudaFuncAttributeMaxDynamicSharedMemorySize, GSMEM_QK);
        cudaFuncSetAttribute(gemm_v_kern,    cudaFuncAttributeMaxDynamicSharedMemorySize, GSMEM_B);
        cudaFuncSetAttribute(gemm_proj_kern, cudaFuncAttributeMaxDynamicSharedMemorySize, GSMEM_B);
        cudaFuncSetAttribute(attn_bf16,      cudaFuncAttributeMaxDynamicSharedMemorySize, ATTN_SMEM_BYTES);
        configured = 1;
    }

    gemm_qk_kern<<<dim3(16, 13), 256, GSMEM_QK>>>(x, Wqkv);
    gemm_v_kern<<<dim3(8, 13), 256, GSMEM_B>>>(x, Wqkv);
    rope_kernel<<<(HWLEN * NH * 32 + 255) / 256, 256>>>(rope);
    attn_bf16<<<dim3(13, NH, NSPLIT), 128, ATTN_SMEM_BYTES>>>();
    attn_combine<<<(NH * NSEQ * 16 + 255) / 256, 256>>>();
    gemm_proj_kern<<<dim3(8, 13), 256, GSMEM_B>>>(Wproj, bproj, out);
}

// round 12
// speedup vs baseline: 2.9080x; 1.0252x over previous
#include <cuda_runtime.h>
#include <cstdint>

#define NSEQ   1605
#define DIMF   1024
#define NH     16
#define DH     64
#define HWLEN  1600
#define PREFIX 5
#define NPAD   1664   // 26 * 64
#define NSPLIT 2
#define NKT_TOT 51
#define NKT0   26

// ---- scratch (device globals; zero-initialized at module load) ----
__device__ float g_q[(size_t)NH * NPAD * DH];
__device__ float g_k[(size_t)NH * NPAD * DH];
__device__ float g_v[(size_t)NH * NPAD * DH];
__device__ float g_attn[(size_t)NSEQ * DIMF];
__device__ float  g_part[(size_t)NSPLIT * NH * NPAD * DH];
__device__ float2 g_ml[(size_t)NSPLIT * NH * NPAD];

// ============================================================
// mma / ldmatrix helpers
// ============================================================
__device__ __forceinline__ uint32_t f2tf32(float a) {
    uint32_t u; asm("cvt.rna.tf32.f32 %0, %1;" : "=r"(u) : "f"(a));
    return u;
}
__device__ __forceinline__ uint32_t cvta_s(const void* p) {
    uint32_t a;
    asm("{ .reg .u64 t; cvta.to.shared.u64 t, %1; cvt.u32.u64 %0, t; }"
        : "=r"(a) : "l"(p));
    return a;
}

#define MMA_TF32(d, a0, a1, a2, a3, b0, b1) \
    asm volatile("mma.sync.aligned.m16n8k8.row.col.f32.tf32.tf32.f32 " \
        "{%0,%1,%2,%3}, {%4,%5,%6,%7}, {%8,%9}, {%0,%1,%2,%3};" \
        : "+f"((d)[0]), "+f"((d)[1]), "+f"((d)[2]), "+f"((d)[3]) \
        : "r"(a0), "r"(a1), "r"(a2), "r"(a3), "r"(b0), "r"(b1))

#define MMA_BF16(d, a0, a1, a2, a3, b0, b1) \
    asm volatile("mma.sync.aligned.m16n8k16.row.col.f32.bf16.bf16.f32 " \
        "{%0,%1,%2,%3}, {%4,%5,%6,%7}, {%8,%9}, {%0,%1,%2,%3};" \
        : "+f"((d)[0]), "+f"((d)[1]), "+f"((d)[2]), "+f"((d)[3]) \
        : "r"(a0), "r"(a1), "r"(a2), "r"(a3), "r"(b0), "r"(b1))

#define LDSM_X4(r0, r1, r2, r3, addr) \
    asm volatile("ldmatrix.sync.aligned.m8n8.x4.shared.b16 {%0,%1,%2,%3}, [%4];" \
        : "=r"(r0), "=r"(r1), "=r"(r2), "=r"(r3) : "r"(addr))

__device__ __forceinline__ uint32_t pack_bf16x2(float lo, float hi) {
    uint32_t w;
    asm("cvt.rn.bf16x2.f32 %0, %1, %2;" : "=r"(w) : "f"(hi), "f"(lo));
    return w;
}
__device__ __forceinline__ float lo_bf16(uint32_t w) { return __uint_as_float(w << 16); }
__device__ __forceinline__ float hi_bf16(uint32_t w) { return __uint_as_float(w & 0xFFFF0000u); }

__device__ __forceinline__ void split2(float e, float o, uint32_t& h, uint32_t& l) {
    h = pack_bf16x2(e, o);
    l = pack_bf16x2(e - lo_bf16(h), o - hi_bf16(h));
}

__device__ __forceinline__ void hi4(const float4 v, float4& hi) {
    hi.x = __uint_as_float(f2tf32(v.x));
    hi.y = __uint_as_float(f2tf32(v.y));
    hi.z = __uint_as_float(f2tf32(v.z));
    hi.w = __uint_as_float(f2tf32(v.w));
}

extern __shared__ float dynsm[];

// ============================================================
// bf16x3 GEMM mainloop (qk)
// ============================================================
#define BST 12
#define BTILE (128 * BST)

__device__ __forceinline__ void gemm_db3b(
    const float* __restrict__ A, const float* __restrict__ B,
    int bm, int bn, int aRows, uint32_t* __restrict__ smem,
    float acc[4][4][4])
{
    const int tid = threadIdx.x;
    const int wid = tid >> 5, lane = tid & 31;
    const int warp_m = wid & 1, warp_n = wid >> 1;
    const int r0 = tid >> 2;
    const int f0 = (tid & 3) * 4;
    const int w0 = (tid & 3) * 2;

    const uint32_t smb = cvta_s(smem);
    const int a_lm = (warp_m * 64 + (lane & 15)) * BST + (lane >> 4) * 4;
    const int b_lm = (warp_n * 32 + (lane >> 4) * 8 + (lane & 7)) * BST
                     + ((lane >> 3) & 1) * 4;

    float4 pa[2], pb[2];

#define GB_LOAD(k0) do { \
    _Pragma("unroll") \
    for (int t = 0; t < 2; ++t) { \
        const int r = r0 + t * 64; \
        pa[t] = make_float4(0.f, 0.f, 0.f, 0.f); \
        if (bm + r < aRows) \
            pa[t] = *(const float4*)(A + (size_t)(bm + r) * 1024 + (k0) + f0); \
        pb[t] = *(const float4*)(B + (size_t)(bn + r) * 1024 + (k0) + f0); \
    } } while (0)

#define GB_STORE(bufp) do { \
    uint32_t* Ah_ = (bufp); \
    uint32_t* Al_ = (bufp) + BTILE; \
    uint32_t* Bh_ = (bufp) + 2 * BTILE; \
    uint32_t* Bl_ = (bufp) + 3 * BTILE; \
    _Pragma("unroll") \
    for (int t = 0; t < 2; ++t) { \
        const int r = r0 + t * 64; \
        uint32_t h0, l0, h1, l1; \
        split2(pa[t].x, pa[t].y, h0, l0); \
        split2(pa[t].z, pa[t].w, h1, l1); \
        Ah_[r * BST + w0] = h0; Ah_[r * BST + w0 + 1] = h1; \
        Al_[r * BST + w0] = l0; Al_[r * BST + w0 + 1] = l1; \
        split2(pb[t].x, pb[t].y, h0, l0); \
        split2(pb[t].z, pb[t].w, h1, l1); \
        Bh_[r * BST + w0] = h0; Bh_[r * BST + w0 + 1] = h1; \
        Bl_[r * BST + w0] = l0; Bl_[r * BST + w0 + 1] = l1; \
    } } while (0)

    GB_LOAD(0);
    GB_STORE(smem);
    __syncthreads();

    for (int c = 0; c < 64; ++c) {
        const int bufw = (c & 1) * (4 * BTILE);
        if (c < 63) GB_LOAD((c + 1) * 16);

        uint32_t ah[4][4], al[4][4];
#pragma unroll
        for (int mt = 0; mt < 4; ++mt) {
            LDSM_X4(ah[mt][0], ah[mt][1], ah[mt][2], ah[mt][3],
                    smb + (uint32_t)(bufw + a_lm + mt * 16 * BST) * 4u);
            LDSM_X4(al[mt][0], al[mt][1], al[mt][2], al[mt][3],
                    smb + (uint32_t)(bufw + BTILE + a_lm + mt * 16 * BST) * 4u);
        }
#pragma unroll
        for (int ntp = 0; ntp < 2; ++ntp) {
            uint32_t bh0, bh1, bh2, bh3, bl0, bl1, bl2, bl3;
            LDSM_X4(bh0, bh1, bh2, bh3,
                    smb + (uint32_t)(bufw + 2 * BTILE + b_lm + ntp * 16 * BST) * 4u);
            LDSM_X4(bl0, bl1, bl2, bl3,
                    smb + (uint32_t)(bufw + 3 * BTILE + b_lm + ntp * 16 * BST) * 4u);
#pragma unroll
            for (int mt = 0; mt < 4; ++mt) {
                MMA_BF16(acc[mt][2 * ntp], ah[mt][0], ah[mt][1], ah[mt][2], ah[mt][3], bh0, bh1);
                MMA_BF16(acc[mt][2 * ntp], ah[mt][0], ah[mt][1], ah[mt][2], ah[mt][3], bl0, bl1);
                MMA_BF16(acc[mt][2 * ntp], al[mt][0], al[mt][1], al[mt][2], al[mt][3], bh0, bh1);
                MMA_BF16(acc[mt][2 * ntp + 1], ah[mt][0], ah[mt][1], ah[mt][2], ah[mt][3], bh2, bh3);
                MMA_BF16(acc[mt][2 * ntp + 1], ah[mt][0], ah[mt][1], ah[mt][2], ah[mt][3], bl2, bl3);
                MMA_BF16(acc[mt][2 * ntp + 1], al[mt][0], al[mt][1], al[mt][2], al[mt][3], bh2, bh3);
            }
        }
        if (c < 63) GB_STORE(smem + ((c + 1) & 1) * (4 * BTILE));
        __syncthreads();
    }
#undef GB_LOAD
#undef GB_STORE
}

#define GSMEM_QK (2 * 4 * BTILE * 4)   // 49152 B

// ============================================================
// 1xTF32 GEMM mainloop — v and proj
// ============================================================
#define GST 20
#define GTILE (128 * GST)

__device__ __forceinline__ void gemm_db1(
    const float* __restrict__ A, const float* __restrict__ B,
    int bm, int bn, int aRows, float* __restrict__ smem,
    float acc[4][4][4])
{
    const int tid = threadIdx.x;
    const int wid = tid >> 5, lane = tid & 31;
    const int warp_m = wid & 1, warp_n = wid >> 1;
    const int grp = lane >> 2, tig = lane & 3;
    const int r0 = tid >> 2;
    const int f0 = (tid & 3) * 4;

    float4 pa[2], pb[2];

#define G1_LOAD(k0) do { \
    _Pragma("unroll") \
    for (int t = 0; t < 2; ++t) { \
        const int r = r0 + t * 64; \
        pa[t] = make_float4(0.f, 0.f, 0.f, 0.f); \
        if (bm + r < aRows) \
            pa[t] = *(const float4*)(A + (size_t)(bm + r) * 1024 + (k0) + f0); \
        pb[t] = *(const float4*)(B + (size_t)(bn + r) * 1024 + (k0) + f0); \
    } } while (0)

#define G1_STORE(bufp) do { \
    float* Ah_ = (bufp); \
    float* Bh_ = (bufp) + GTILE; \
    _Pragma("unroll") \
    for (int t = 0; t < 2; ++t) { \
        const int r = r0 + t * 64; \
        float4 hi; \
        hi4(pa[t], hi); *(float4*)(Ah_ + r * GST + f0) = hi; \
        hi4(pb[t], hi); *(float4*)(Bh_ + r * GST + f0) = hi; \
    } } while (0)

    G1_LOAD(0);
    G1_STORE(smem);
    __syncthreads();

    for (int c = 0; c < 64; ++c) {
        float* cur = smem + (c & 1) * (2 * GTILE);
        if (c < 63) G1_LOAD((c + 1) * 16);

        float* Ah = cur;
        float* Bh = cur + GTILE;

#pragma unroll
        for (int ks = 0; ks < 2; ++ks) {
            const int kc = ks * 8 + tig;
            uint32_t ah[4][4];
#pragma unroll
            for (int mt = 0; mt < 4; ++mt) {
                const int ra = (warp_m * 64 + mt * 16 + grp) * GST;
                ah[mt][0] = __float_as_uint(Ah[ra + kc]);
                ah[mt][1] = __float_as_uint(Ah[ra + 8 * GST + kc]);
                ah[mt][2] = __float_as_uint(Ah[ra + kc + 4]);
                ah[mt][3] = __float_as_uint(Ah[ra + 8 * GST + kc + 4]);
            }
#pragma unroll
            for (int nt = 0; nt < 4; ++nt) {
                const int rb = (warp_n * 32 + nt * 8 + grp) * GST + kc;
                uint32_t bh0 = __float_as_uint(Bh[rb]);
                uint32_t bh1 = __float_as_uint(Bh[rb + 4]);
#pragma unroll
                for (int mt = 0; mt < 4; ++mt)
                    MMA_TF32(acc[mt][nt], ah[mt][0], ah[mt][1], ah[mt][2], ah[mt][3], bh0, bh1);
            }
        }
        if (c < 63) G1_STORE(smem + ((c + 1) & 1) * (2 * GTILE));
        __syncthreads();
    }
#undef G1_LOAD
#undef G1_STORE
}

#define GSMEM_B (2 * 2 * GTILE * 4)

// ============================================================
// MERGED qkv GEMM: bx<16 -> q,k (bf16x3); bx>=16 -> v (1xTF32)
// grid (24, 13), dynamic smem = GSMEM_QK
// ============================================================
__global__ __launch_bounds__(256, 2) void gemm_qkv_kern(
    const float* __restrict__ A, const float* __restrict__ B)
{
    const int bm = blockIdx.y * 128;
    const int tid = threadIdx.x;
    const int wid = tid >> 5, lane = tid & 31;
    const int warp_m = wid & 1, warp_n = wid >> 1;
    const int grp = lane >> 2, tig = lane & 3;

    float acc[4][4][4];
#pragma unroll
    for (int a = 0; a < 4; a++)
#pragma unroll
        for (int b = 0; b < 4; b++)
#pragma unroll
            for (int cc = 0; cc < 4; cc++) acc[a][b][cc] = 0.0f;

    if (blockIdx.x < 16) {
        const int bn = blockIdx.x * 128;
        gemm_db3b(A, B, bm, bn, NSEQ, (uint32_t*)dynsm, acc);

        const int s = bn >> 10;
        float* __restrict__ dst = (s == 0) ? g_q : g_k;
        const float scale = (s == 0) ? 0.125f : 1.0f;

#pragma unroll
        for (int mt = 0; mt < 4; ++mt)
#pragma unroll
            for (int half = 0; half < 2; ++half) {
                const int row = bm + warp_m * 64 + mt * 16 + grp + half * 8;
                if (row >= NSEQ) continue;
#pragma unroll
                for (int nt = 0; nt < 4; ++nt) {
                    const int col = bn + warp_n * 32 + nt * 8 + tig * 2;
                    const int h = (col & 1023) >> 6;
                    const int d = col & 63;
                    float2 v;
                    v.x = acc[mt][nt][half * 2 + 0] * scale;
                    v.y = acc[mt][nt][half * 2 + 1] * scale;
                    *(float2*)&dst[((size_t)h * NPAD + row) * DH + d] = v;
                }
            }
    } else {
        const int bn = 2048 + (blockIdx.x - 16) * 128;
        gemm_db1(A, B, bm, bn, NSEQ, dynsm, acc);

#pragma unroll
        for (int mt = 0; mt < 4; ++mt)
#pragma unroll
            for (int half = 0; half < 2; ++half) {
                const int row = bm + warp_m * 64 + mt * 16 + grp + half * 8;
                if (row >= NSEQ) continue;
#pragma unroll
                for (int nt = 0; nt < 4; ++nt) {
                    const int col = bn + warp_n * 32 + nt * 8 + tig * 2;
                    const int h = (col & 1023) >> 6;
                    const int d = col & 63;
                    float2 v;
                    v.x = acc[mt][nt][half * 2 + 0];
                    v.y = acc[mt][nt][half * 2 + 1];
                    *(float2*)&g_v[((size_t)h * NPAD + row) * DH + d] = v;
                }
            }
    }
}

// ---- proj: 1xTF32 + bias ----
__global__ __launch_bounds__(256, 2) void gemm_proj_kern(
    const float* __restrict__ B, const float* __restrict__ bias,
    float* __restrict__ C)
{
    const int bm = blockIdx.y * 128;
    const int bn = blockIdx.x * 128;
    float acc[4][4][4];
#pragma unroll
    for (int a = 0; a < 4; a++)
#pragma unroll
        for (int b = 0; b < 4; b++)
#pragma unroll
            for (int cc = 0; cc < 4; cc++) acc[a][b][cc] = 0.0f;

    gemm_db1(g_attn, B, bm, bn, NSEQ, dynsm, acc);

    const int tid = threadIdx.x;
    const int wid = tid >> 5, lane = tid & 31;
    const int warp_m = wid & 1, warp_n = wid >> 1;
    const int grp = lane >> 2, tig = lane & 3;

#pragma unroll
    for (int mt = 0; mt < 4; ++mt)
#pragma unroll
        for (int half = 0; half < 2; ++half) {
            const int row = bm + warp_m * 64 + mt * 16 + grp + half * 8;
            if (row >= NSEQ) continue;
#pragma unroll
            for (int nt = 0; nt < 4; ++nt) {
                const int col = bn + warp_n * 32 + nt * 8 + tig * 2;
                float2 v;
                v.x = acc[mt][nt][half * 2 + 0] + bias[col];
                v.y = acc[mt][nt][half * 2 + 1] + bias[col + 1];
                *(float2*)&C[(size_t)row * 1024 + col] = v;
            }
        }
}

// ============================================================
// RoPE on q and k, rows PREFIX..NSEQ-1
// ============================================================
__global__ void rope_kernel(const float* __restrict__ rope)
{
    int idx = blockIdx.x * blockDim.x + threadIdx.x;
    if (idx >= HWLEN * NH * 32) return;
    const int d = idx & 31;
    const int h = (idx >> 5) & 15;
    const int p = idx >> 9;
    const int n = PREFIX + p;

    const float s0 = rope[p * 64 + d];
    const float s1 = rope[p * 64 + d + 32];
    const float c0 = rope[HWLEN * 64 + p * 64 + d];
    const float c1 = rope[HWLEN * 64 + p * 64 + d + 32];

    const size_t base = ((size_t)h * NPAD + n) * DH;

    float q0 = g_q[base + d], q1 = g_q[base + d + 32];
    g_q[base + d]      = q0 * c0 - q1 * s0;
    g_q[base + d + 32] = q1 * c1 + q0 * s1;

    float k0 = g_k[base + d], k1 = g_k[base + d + 32];
    g_k[base + d]      = k0 * c0 - k1 * s0;
    g_k[base + d + 32] = k1 * c1 + k0 * s1;
}

// ============================================================
// Flash attention v9: split-K, warp = 32 q-rows x 32 keys,
// half-size P (per-m-tile reuse) -> smem 66.56 KB -> 3 CTAs/SM,
// all 416 CTAs in ONE wave.
// ============================================================
#define AQ_H 0
#define AQ_L 4608
#define AK_H 9216
#define AK_L 10368
#define AV_H 11520
#define AV_L 12800
#define AP   14080                   // 4 warps * 640 (hi 320 + lo 320)
#define ATTN_SMEM_BYTES (16640 * 4)  // 66560 B

__global__ __launch_bounds__(128, 3) void attn_bf16()
{
    uint32_t* usm = (uint32_t*)dynsm;
    uint32_t* Qh = usm + AQ_H;
    uint32_t* Ql = usm + AQ_L;
    uint32_t* Kh = usm + AK_H;
    uint32_t* Kl = usm + AK_L;
    uint32_t* Vh = usm + AV_H;
    uint32_t* Vl = usm + AV_L;

    const int h  = blockIdx.y;
    const int z  = blockIdx.z;
    const int qb = blockIdx.x * 128;
    const int tid = threadIdx.x;
    const int wid = tid >> 5, lane = tid & 31;
    const int grp = lane >> 2, tig = lane & 3;
    const int row0 = wid * 32;

    const int ktb = z * NKT0;
    const int kte = (z == 0) ? NKT0 : NKT_TOT;

    uint32_t* Ph = usm + AP + wid * 640;
    uint32_t* Pl = Ph + 320;

    const uint32_t smb = cvta_s(usm);
    const int q_lm  = AQ_H + (row0 + (lane & 15)) * 36 + (lane >> 4) * 4;
    const int q_lml = q_lm + 4608;
    const int k_lm  = AK_H + ((lane >> 4) * 8 + (lane & 7)) * 36 + ((lane >> 3) & 1) * 4;
    const int k_lml = k_lm + 1152;
    const int v_lm  = AV_H + ((lane >> 4) * 8 + (lane & 7)) * 20 + ((lane >> 3) & 1) * 4;
    const int v_lml = v_lm + 1280;
    const int p_lm  = AP + wid * 640 + (lane & 15) * 20 + (lane >> 4) * 4;
    const int p_lml = p_lm + 320;

    const float* __restrict__ Qg = g_q + (size_t)h * NPAD * DH;
    const float* __restrict__ Kg = g_k + (size_t)h * NPAD * DH;
    const float* __restrict__ Vg = g_v + (size_t)h * NPAD * DH;

    // ---- prologue: Q tile 128x64 -> packed bf16x2 hi/lo ----
#pragma unroll
    for (int t = 0; t < 16; ++t) {
        const int idx = tid + t * 128;
        const int r = idx >> 4, c4 = (idx & 15) * 4;
        float4 v = *(const float4*)(Qg + (size_t)(qb + r) * DH + c4);
        uint32_t h0, l0, h1, l1;
        split2(v.x, v.y, h0, l0);
        split2(v.z, v.w, h1, l1);
        Qh[r * 36 + c4 / 2] = h0; Qh[r * 36 + c4 / 2 + 1] = h1;
        Ql[r * 36 + c4 / 2] = l0; Ql[r * 36 + c4 / 2 + 1] = l1;
    }

    // ---- K/V tile ----
    const int lr = tid >> 4;
    const int lc4 = (tid & 15) * 4;
    const int vp = tid & 15;
    const int vdg = tid >> 4;
    float4 pk[4];
    float4 ve0, ve1, vo0, vo1;

#define KV_FETCH(base) do { \
    _Pragma("unroll") \
    for (int t = 0; t < 4; ++t) \
        pk[t] = *(const float4*)(Kg + (size_t)((base) + lr + t * 8) * DH + lc4); \
    ve0 = *(const float4*)(Vg + (size_t)((base) + 2 * vp) * DH + vdg * 8); \
    ve1 = *(const float4*)(Vg + (size_t)((base) + 2 * vp) * DH + vdg * 8 + 4); \
    vo0 = *(const float4*)(Vg + (size_t)((base) + 2 * vp + 1) * DH + vdg * 8); \
    vo1 = *(const float4*)(Vg + (size_t)((base) + 2 * vp + 1) * DH + vdg * 8 + 4); \
} while (0)

#define KV_STORE() do { \
    _Pragma("unroll") \
    for (int t = 0; t < 4; ++t) { \
        const int r = lr + t * 8; \
        uint32_t h0, l0, h1, l1; \
        split2(pk[t].x, pk[t].y, h0, l0); \
        split2(pk[t].z, pk[t].w, h1, l1); \
        Kh[r * 36 + lc4 / 2] = h0; Kh[r * 36 + lc4 / 2 + 1] = h1; \
        Kl[r * 36 + lc4 / 2] = l0; Kl[r * 36 + lc4 / 2 + 1] = l1; \
    } \
    { \
        float ve[8] = {ve0.x, ve0.y, ve0.z, ve0.w, ve1.x, ve1.y, ve1.z, ve1.w}; \
        float vo[8] = {vo0.x, vo0.y, vo0.z, vo0.w, vo1.x, vo1.y, vo1.z, vo1.w}; \
        _Pragma("unroll") \
        for (int j = 0; j < 8; ++j) { \
            const int d = vdg * 8 + j; \
            uint32_t hh, ll; \
            split2(ve[j], vo[j], hh, ll); \
            Vh[d * 20 + vp] = hh; \
            Vl[d * 20 + vp] = ll; \
        } \
    } \
} while (0)

    KV_FETCH(ktb * 32);
    KV_STORE();
    __syncthreads();

    float mreg[2][2], lreg[2][2];
#pragma unroll
    for (int mt = 0; mt < 2; ++mt) {
        mreg[mt][0] = -1e38f; mreg[mt][1] = -1e38f;
        lreg[mt][0] = 0.0f;   lreg[mt][1] = 0.0f;
    }
    float o[2][8][4];
#pragma unroll
    for (int mt = 0; mt < 2; mt++)
#pragma unroll
        for (int nt = 0; nt < 8; nt++)
#pragma unroll
            for (int i = 0; i < 4; i++) o[mt][nt][i] = 0.0f;

    for (int kt = ktb; kt < kte; ++kt) {
        const int key0 = kt * 32;

        // ---- S = Q K^T (bf16x3) ----
        float sacc[2][4][4];
#pragma unroll
        for (int mt = 0; mt < 2; mt++)
#pragma unroll
            for (int nt = 0; nt < 4; nt++)
#pragma unroll
                for (int i = 0; i < 4; i++) sacc[mt][nt][i] = 0.0f;

#pragma unroll
        for (int ks = 0; ks < 4; ++ks) {
            const int kw = ks * 8;
            uint32_t ah[2][4], al[2][4];
#pragma unroll
            for (int mt = 0; mt < 2; ++mt) {
                LDSM_X4(ah[mt][0], ah[mt][1], ah[mt][2], ah[mt][3],
                        smb + (uint32_t)(q_lm + mt * 576 + kw) * 4u);
                LDSM_X4(al[mt][0], al[mt][1], al[mt][2], al[mt][3],
                        smb + (uint32_t)(q_lml + mt * 576 + kw) * 4u);
            }
#pragma unroll
            for (int ntp = 0; ntp < 2; ++ntp) {
                uint32_t bh0, bh1, bh2, bh3, bl0, bl1, bl2, bl3;
                LDSM_X4(bh0, bh1, bh2, bh3,
                        smb + (uint32_t)(k_lm + ntp * 16 * 36 + kw) * 4u);
                LDSM_X4(bl0, bl1, bl2, bl3,
                        smb + (uint32_t)(k_lml + ntp * 16 * 36 + kw) * 4u);
#pragma unroll
                for (int mt = 0; mt < 2; ++mt) {
                    MMA_BF16(sacc[mt][2 * ntp], ah[mt][0], ah[mt][1], ah[mt][2], ah[mt][3], bh0, bh1);
                    MMA_BF16(sacc[mt][2 * ntp], ah[mt][0], ah[mt][1], ah[mt][2], ah[mt][3], bl0, bl1);
                    MMA_BF16(sacc[mt][2 * ntp], al[mt][0], al[mt][1], al[mt][2], al[mt][3], bh0, bh1);
                    MMA_BF16(sacc[mt][2 * ntp + 1], ah[mt][0], ah[mt][1], ah[mt][2], ah[mt][3], bh2, bh3);
                    MMA_BF16(sacc[mt][2 * ntp + 1], ah[mt][0], ah[mt][1], ah[mt][2], ah[mt][3], bl2, bl3);
                    MMA_BF16(sacc[mt][2 * ntp + 1], al[mt][0], al[mt][1], al[mt][2], al[mt][3], bh2, bh3);
                }
            }
        }

        // ---- prefetch next K/V into regs ----
        if (kt + 1 < kte) KV_FETCH((kt + 1) * 32);

        // ---- per m-tile: softmax -> P buffer -> PV (shared buffer) ----
#pragma unroll
        for (int mt = 0; mt < 2; ++mt) {
            float mx0 = -1e30f, mx1 = -1e30f;
#pragma unroll
            for (int nt = 0; nt < 4; ++nt) {
                const int c0 = key0 + nt * 8 + tig * 2;
                if (c0 >= NSEQ)     { sacc[mt][nt][0] = -1e30f; sacc[mt][nt][2] = -1e30f; }
                if (c0 + 1 >= NSEQ) { sacc[mt][nt][1] = -1e30f; sacc[mt][nt][3] = -1e30f; }
                mx0 = fmaxf(mx0, fmaxf(sacc[mt][nt][0], sacc[mt][nt][1]));
                mx1 = fmaxf(mx1, fmaxf(sacc[mt][nt][2], sacc[mt][nt][3]));
            }
            mx0 = fmaxf(mx0, __shfl_xor_sync(0xffffffffu, mx0, 1));
            mx0 = fmaxf(mx0, __shfl_xor_sync(0xffffffffu, mx0, 2));
            mx1 = fmaxf(mx1, __shfl_xor_sync(0xffffffffu, mx1, 1));
            mx1 = fmaxf(mx1, __shfl_xor_sync(0xffffffffu, mx1, 2));

            const float mn0 = fmaxf(mreg[mt][0], mx0);
            const float mn1 = fmaxf(mreg[mt][1], mx1);
            const float a0 = __expf(mreg[mt][0] - mn0);
            const float a1 = __expf(mreg[mt][1] - mn1);
            mreg[mt][0] = mn0; mreg[mt][1] = mn1;

            float s0 = 0.0f, s1 = 0.0f;
#pragma unroll
            for (int nt = 0; nt < 4; ++nt) {
                sacc[mt][nt][0] = __expf(sacc[mt][nt][0] - mn0); s0 += sacc[mt][nt][0];
                sacc[mt][nt][1] = __expf(sacc[mt][nt][1] - mn0); s0 += sacc[mt][nt][1];
                sacc[mt][nt][2] = __expf(sacc[mt][nt][2] - mn1); s1 += sacc[mt][nt][2];
                sacc[mt][nt][3] = __expf(sacc[mt][nt][3] - mn1); s1 += sacc[mt][nt][3];
            }
            s0 += __shfl_xor_sync(0xffffffffu, s0, 1);
            s0 += __shfl_xor_sync(0xffffffffu, s0, 2);
            s1 += __shfl_xor_sync(0xffffffffu, s1, 1);
            s1 += __shfl_xor_sync(0xffffffffu, s1, 2);
            lreg[mt][0] = lreg[mt][0] * a0 + s0;
            lreg[mt][1] = lreg[mt][1] * a1 + s1;

            // pack P (this m-tile only) into the shared warp buffer
#pragma unroll
            for (int nt = 0; nt < 4; ++nt) {
                const int cw = nt * 4 + tig;
                uint32_t hh, ll;
                split2(sacc[mt][nt][0], sacc[mt][nt][1], hh, ll);
                Ph[grp * 20 + cw] = hh; Pl[grp * 20 + cw] = ll;
                split2(sacc[mt][nt][2], sacc[mt][nt][3], hh, ll);
                Ph[(grp + 8) * 20 + cw] = hh; Pl[(grp + 8) * 20 + cw] = ll;
            }

            // rescale O for this m-tile
#pragma unroll
            for (int nt = 0; nt < 8; ++nt) {
                o[mt][nt][0] *= a0; o[mt][nt][1] *= a0;
                o[mt][nt][2] *= a1; o[mt][nt][3] *= a1;
            }
            __syncwarp();

            // PV for this m-tile
#pragma unroll
            for (int kk = 0; kk < 2; ++kk) {
                const int kw = kk * 8;
                uint32_t ph0, ph1, ph2, ph3, pl0, pl1, pl2, pl3;
                LDSM_X4(ph0, ph1, ph2, ph3, smb + (uint32_t)(p_lm + kw) * 4u);
                LDSM_X4(pl0, pl1, pl2, pl3, smb + (uint32_t)(p_lml + kw) * 4u);
#pragma unroll
                for (int ntp = 0; ntp < 4; ++ntp) {
                    uint32_t vh0, vh1, vh2, vh3, vl0, vl1, vl2, vl3;
                    LDSM_X4(vh0, vh1, vh2, vh3,
                            smb + (uint32_t)(v_lm + ntp * 16 * 20 + kw) * 4u);
                    LDSM_X4(vl0, vl1, vl2, vl3,
                            smb + (uint32_t)(v_lml + ntp * 16 * 20 + kw) * 4u);
                    MMA_BF16(o[mt][2 * ntp], ph0, ph1, ph2, ph3, vh0, vh1);
                    MMA_BF16(o[mt][2 * ntp], ph0, ph1, ph2, ph3, vl0, vl1);
                    MMA_BF16(o[mt][2 * ntp], pl0, pl1, pl2, pl3, vh0, vh1);
                    MMA_BF16(o[mt][2 * ntp + 1], ph0, ph1, ph2, ph3, vh2, vh3);
                    MMA_BF16(o[mt][2 * ntp + 1], ph0, ph1, ph2, ph3, vl2, vl3);
                    MMA_BF16(o[mt][2 * ntp + 1], pl0, pl1, pl2, pl3, vh2, vh3);
                }
            }
            if (mt == 0) __syncwarp();   // protect P before overwrite
        }
        __syncthreads();

        // ---- store prefetched K/V tile ----
        if (kt + 1 < kte) {
            KV_STORE();
            __syncthreads();
        }
    }

    // ---- epilogue: write normalized partial O + (m,l) ----
    float* __restrict__ part = g_part + (size_t)(z * NH + h) * NPAD * DH;
    float2* __restrict__ mlp = g_ml + (size_t)(z * NH + h) * NPAD;
#pragma unroll
    for (int mt = 0; mt < 2; ++mt) {
        const float inv0 = 1.0f / lreg[mt][0];
        const float inv1 = 1.0f / lreg[mt][1];
        const int n0 = qb + row0 + mt * 16 + grp;
        const int n1 = n0 + 8;
        if (tig == 0) {
            if (n0 < NSEQ) mlp[n0] = make_float2(mreg[mt][0], lreg[mt][0]);
            if (n1 < NSEQ) mlp[n1] = make_float2(mreg[mt][1], lreg[mt][1]);
        }
#pragma unroll
        for (int nt = 0; nt < 8; ++nt) {
            const int col = nt * 8 + tig * 2;
            if (n0 < NSEQ)
                *(float2*)&part[(size_t)n0 * DH + col] =
                    make_float2(o[mt][nt][0] * inv0, o[mt][nt][1] * inv0);
            if (n1 < NSEQ)
                *(float2*)&part[(size_t)n1 * DH + col] =
                    make_float2(o[mt][nt][2] * inv1, o[mt][nt][3] * inv1);
        }
    }
}

// ============================================================
// Combine split-K partials -> g_attn
// ============================================================
__global__ void attn_combine()
{
    const int t = blockIdx.x * blockDim.x + threadIdx.x;
    if (t >= NH * NSEQ * 16) return;
    const int d4 = (t & 15) * 4;
    const int n = (t >> 4) % NSEQ;
    const int h = t / (16 * NSEQ);

    const float2 ml0 = g_ml[(size_t)(0 * NH + h) * NPAD + n];
    const float2 ml1 = g_ml[(size_t)(1 * NH + h) * NPAD + n];
    const float m = fmaxf(ml0.x, ml1.x);
    float w0 = ml0.y * __expf(ml0.x - m);
    float w1 = ml1.y * __expf(ml1.x - m);
    const float inv = 1.0f / (w0 + w1);
    w0 *= inv; w1 *= inv;

    const float4 o0 = *(const float4*)&g_part[((size_t)(0 * NH + h) * NPAD + n) * DH + d4];
    const float4 o1 = *(const float4*)&g_part[((size_t)(1 * NH + h) * NPAD + n) * DH + d4];
    float4 r;
    r.x = w0 * o0.x + w1 * o1.x;
    r.y = w0 * o0.y + w1 * o1.y;
    r.z = w0 * o0.z + w1 * o1.z;
    r.w = w0 * o0.w + w1 * o1.w;
    *(float4*)&g_attn[(size_t)n * DIMF + h * DH + d4] = r;
}

// ============================================================
extern "C" void kernel_launch(void* const* d_in, const int* in_sizes, int n_in,
                              void* d_out, int out_size)
{
    (void)in_sizes; (void)n_in; (void)out_size;
    const float* x     = (const float*)d_in[0];
    const float* rope  = (const float*)d_in[1];
    const float* Wqkv  = (const float*)d_in[2];
    const float* Wproj = (const float*)d_in[3];
    const float* bproj = (const float*)d_in[4];
    float* out = (float*)d_out;

    static int configured = 0;
    if (!configured) {
        cudaFuncSetAttribute(gemm_qkv_kern,  cudaFuncAttributeMaxDynamicSharedMemorySize, GSMEM_QK);
        cudaFuncSetAttribute(gemm_proj_kern, cudaFuncAttributeMaxDynamicSharedMemorySize, GSMEM_B);
        cudaFuncSetAttribute(attn_bf16,      cudaFuncAttributeMaxDynamicSharedMemorySize, ATTN_SMEM_BYTES);
        configured = 1;
    }

    gemm_qkv_kern<<<dim3(24, 13), 256, GSMEM_QK>>>(x, Wqkv);
    rope_kernel<<<(HWLEN * NH * 32 + 255) / 256, 256>>>(rope);
    attn_bf16<<<dim3(13, NH, NSPLIT), 128, ATTN_SMEM_BYTES>>>();
    attn_combine<<<(NH * NSEQ * 16 + 255) / 256, 256>>>();
    gemm_proj_kern<<<dim3(8, 13), 256, GSMEM_B>>>(Wproj, bproj, out);
}